// round 8
// baseline (speedup 1.0000x reference)
#include <cuda_runtime.h>
#include <math.h>
#include <stdint.h>

#define BB  2
#define SS  2048
#define DM  1024
#define NH  16
#define DKK 64

// Scratch (allocation-free rule: __device__ globals)
__device__ float g_Qh[BB*NH*SS*DKK];   // [b][h][s][dk]  (tf32 bits)
__device__ float g_Kh[BB*NH*SS*DKK];   // (tf32 bits)
__device__ float g_Vh[BB*NH*SS*DKK];   // (tf32 bits)
__device__ float g_Oh[BB*SS*DM];       // [b][s][h*64+dk] (tf32 bits)
__device__ float g_qtf[BB*SS*DM];      // pre-converted q (tf32 bits)
__device__ float g_ktf[BB*SS*DM];      // pre-converted k (tf32 bits)
__device__ float g_Wtf[4*DM*DM];       // pre-converted Wq,Wk,Wv,Wo (tf32 bits)

// ---------------------------------------------------------------------------
// tf32 / cp.async helpers
// ---------------------------------------------------------------------------
__device__ __forceinline__ uint32_t f2tf(float x) {
    uint32_t u;
    asm("cvt.rna.tf32.f32 %0, %1;" : "=r"(u) : "f"(x));
    return u;
}

__device__ __forceinline__ void mma_tf32(float c[4], const uint32_t a[4], const uint32_t b[2]) {
    asm volatile(
        "mma.sync.aligned.m16n8k8.row.col.f32.tf32.tf32.f32 "
        "{%0,%1,%2,%3}, {%4,%5,%6,%7}, {%8,%9}, {%0,%1,%2,%3};\n"
        : "+f"(c[0]), "+f"(c[1]), "+f"(c[2]), "+f"(c[3])
        : "r"(a[0]), "r"(a[1]), "r"(a[2]), "r"(a[3]), "r"(b[0]), "r"(b[1]));
}

__device__ __forceinline__ void cp16(float* dst, const float* src) {
    uint32_t d = (uint32_t)__cvta_generic_to_shared(dst);
    asm volatile("cp.async.cg.shared.global [%0], [%1], 16;" :: "r"(d), "l"(src));
}
__device__ __forceinline__ void cp_commit() {
    asm volatile("cp.async.commit_group;");
}
__device__ __forceinline__ void cp_wait1() {
    asm volatile("cp.async.wait_group 1;");
}

// ---------------------------------------------------------------------------
// Single fused fp32 -> tf32(RNA) pre-pass over q, k, Wq, Wk, Wv, Wo.
// ---------------------------------------------------------------------------
#define NQ4 (BB*SS*DM/4)   // 1048576 float4
#define NW4 (DM*DM/4)      // 262144 float4
#define NCVT4 (2*NQ4 + 4*NW4)

__global__ void cvt_all(const float* __restrict__ q, const float* __restrict__ k,
                        const float* __restrict__ Wq, const float* __restrict__ Wk,
                        const float* __restrict__ Wv, const float* __restrict__ Wo,
                        float* __restrict__ qtf, float* __restrict__ ktf,
                        float* __restrict__ Wtf)
{
    int i = blockIdx.x * blockDim.x + threadIdx.x;
    if (i >= NCVT4) return;
    const float4* src; float4* dst; int off;
    if (i < NQ4)            { src = (const float4*)q;  dst = (float4*)qtf; off = i; }
    else if (i < 2 * NQ4)   { src = (const float4*)k;  dst = (float4*)ktf; off = i - NQ4; }
    else {
        int j = i - 2 * NQ4;
        int w = j / NW4; off = j - w * NW4;
        src = (const float4*)(w == 0 ? Wq : w == 1 ? Wk : w == 2 ? Wv : Wo);
        dst = (float4*)(Wtf) + (size_t)w * NW4;
    }
    float4 d = src[off];
    float4 e;
    e.x = __uint_as_float(f2tf(d.x)); e.y = __uint_as_float(f2tf(d.y));
    e.z = __uint_as_float(f2tf(d.z)); e.w = __uint_as_float(f2tf(d.w));
    dst[off] = e;
}

// ---------------------------------------------------------------------------
// tf32 tensor-core GEMM, cp.async double-buffered, cvt-free mainloop,
// 128 threads (4 warps 2x2), warp tile 64x64 (LDS/mma = 1.0).
// Y[m][n] = sum_k X[m][k]*W[n][k] + bias[n]
// head_split=1: write tf32-rounded bits to [b][h][s][dk]; else fp32 row-major.
// ---------------------------------------------------------------------------
#define AS_OFF(buf) ((buf) * 4608)            // 128*36 floats
#define BS_OFF(buf) (9216 + (buf) * 4608)
#define GEMM_SMEM_BYTES (18432 * sizeof(float))   // 73728

__global__ __launch_bounds__(128, 2)
void gemm_tf32(const float* __restrict__ X, const float* __restrict__ W,
               const float* __restrict__ bias, float* __restrict__ Y,
               int head_split)
{
    extern __shared__ float sm[];

    const int bm = blockIdx.y * 128;
    const int bn = blockIdx.x * 128;
    const int tid = threadIdx.x;
    const int lane = tid & 31, wid = tid >> 5;
    const int wm = wid >> 1;        // 0..1  (m offset wm*64)
    const int wn = wid & 1;         // 0..1  (n offset wn*64)
    const int grp = lane >> 2;      // 0..7
    const int tig = lane & 3;       // 0..3

    const int ldrow = tid >> 3;     // 0..15
    const int ldc4  = tid & 7;      // 0..7

    float c[4][8][4];
    #pragma unroll
    for (int t = 0; t < 4; t++)
        #pragma unroll
        for (int u = 0; u < 8; u++)
            #pragma unroll
            for (int r = 0; r < 4; r++) c[t][u][r] = 0.f;

    // prologue: issue tile 0 (A and B 128x32 each = 1024 float4, 8 per thread)
    #pragma unroll
    for (int i = 0; i < 8; i++) {
        int row = ldrow + i * 16;
        cp16(&sm[AS_OFF(0) + row * 36 + ldc4 * 4], X + (size_t)(bm + row) * DM + ldc4 * 4);
        cp16(&sm[BS_OFF(0) + row * 36 + ldc4 * 4], W + (size_t)(bn + row) * DM + ldc4 * 4);
    }
    cp_commit();

    const int NT = DM / 32;   // 32
    for (int kt = 0; kt < NT; kt++) {
        if (kt + 1 < NT) {
            int k0n = (kt + 1) * 32;
            int bufn = (kt + 1) & 1;
            #pragma unroll
            for (int i = 0; i < 8; i++) {
                int row = ldrow + i * 16;
                cp16(&sm[AS_OFF(bufn) + row * 36 + ldc4 * 4], X + (size_t)(bm + row) * DM + k0n + ldc4 * 4);
                cp16(&sm[BS_OFF(bufn) + row * 36 + ldc4 * 4], W + (size_t)(bn + row) * DM + k0n + ldc4 * 4);
            }
        }
        cp_commit();
        cp_wait1();
        __syncthreads();

        const float* As = &sm[AS_OFF(kt & 1)];
        const float* Bs = &sm[BS_OFF(kt & 1)];

        #pragma unroll
        for (int s = 0; s < 4; s++) {
            uint32_t a[4][4];
            uint32_t b[8][2];
            const int cc = s * 8 + tig;
            #pragma unroll
            for (int t = 0; t < 4; t++) {
                int r = wm * 64 + t * 16 + grp;
                a[t][0] = __float_as_uint(As[r * 36 + cc]);
                a[t][1] = __float_as_uint(As[(r + 8) * 36 + cc]);
                a[t][2] = __float_as_uint(As[r * 36 + cc + 4]);
                a[t][3] = __float_as_uint(As[(r + 8) * 36 + cc + 4]);
            }
            #pragma unroll
            for (int u = 0; u < 8; u++) {
                int n = wn * 64 + u * 8 + grp;
                b[u][0] = __float_as_uint(Bs[n * 36 + cc]);
                b[u][1] = __float_as_uint(Bs[n * 36 + cc + 4]);
            }
            #pragma unroll
            for (int t = 0; t < 4; t++)
                #pragma unroll
                for (int u = 0; u < 8; u++)
                    mma_tf32(c[t][u], a[t], b[u]);
        }
        __syncthreads();   // before next iter's cp.async overwrites the other buffer
    }

    // epilogue
    #pragma unroll
    for (int t = 0; t < 4; t++) {
        #pragma unroll
        for (int u = 0; u < 8; u++) {
            int r0  = bm + wm * 64 + t * 16 + grp;
            int col = bn + wn * 64 + u * 8 + 2 * tig;
            float b0 = bias[col], b1 = bias[col + 1];
            #pragma unroll
            for (int half = 0; half < 2; half++) {
                int m = r0 + half * 8;
                float vx = c[t][u][half * 2 + 0] + b0;
                float vy = c[t][u][half * 2 + 1] + b1;
                if (head_split) {
                    float2 o;
                    o.x = __uint_as_float(f2tf(vx));
                    o.y = __uint_as_float(f2tf(vy));
                    int b_ = m >> 11, s_ = m & 2047;
                    int h_ = col >> 6, dk = col & 63;
                    *(float2*)(Y + (((size_t)b_ * NH + h_) * SS + s_) * DKK + dk) = o;
                } else {
                    float2 o = make_float2(vx, vy);
                    *(float2*)(Y + (size_t)m * DM + col) = o;
                }
            }
        }
    }
}

// ---------------------------------------------------------------------------
// Flash attention, tf32 mma, register-resident online softmax.
// Tile Sq=128 x Sk=64, d_k=64. 256 threads (8 warps 4x2: wm 0..3, wn 0..1).
// Per-warp code identical to proven Sq=64 version; only row ranges widen.
// Dynamic smem: Ps[128][68], KV[64][68], redm/reds[128][2], kmask[64].
// grid = (S/128, NH, B), longest-first.
// ---------------------------------------------------------------------------
#define FL_SMEM_FLOATS (128*68 + 64*68 + 128*2 + 128*2 + 64)
#define FL_SMEM_BYTES  (FL_SMEM_FLOATS * sizeof(float))   // 54528

__global__ __launch_bounds__(256, 1)
void flash_attn_tc(const int* __restrict__ q_mask, const int* __restrict__ k_mask,
                   const int* __restrict__ causal_flag, int causal_default)
{
    extern __shared__ float fsm[];
    float (*Ps)[68]   = (float(*)[68])fsm;
    float (*KV)[68]   = (float(*)[68])(fsm + 128 * 68);
    float (*redm)[2]  = (float(*)[2])(fsm + 128 * 68 + 64 * 68);
    float (*reds)[2]  = redm + 128;
    int*  kmask_s     = (int*)(fsm + 128 * 68 + 64 * 68 + 2 * 128 + 2 * 128);

    const int b  = blockIdx.z, h = blockIdx.y;
    const int q0 = ((int)gridDim.x - 1 - (int)blockIdx.x) * 128;  // longest-first
    const int tid = threadIdx.x;
    const int lane = tid & 31, wid = tid >> 5;
    const int wm = wid >> 1;      // 0..3 : q rows [wm*32, +32)
    const int wn = wid & 1;       // 0..1 : k cols / d cols [wn*32, +32)
    const int grp = lane >> 2;    // 0..7
    const int tig = lane & 3;     // 0..3
    const int causal = causal_flag ? causal_flag[0] : causal_default;

    const float* Qb = g_Qh + (((size_t)b * NH + h) * SS) * DKK;
    const float* Kb = g_Kh + (((size_t)b * NH + h) * SS) * DKK;
    const float* Vb = g_Vh + (((size_t)b * NH + h) * SS) * DKK;

    // ---- stage Q (tf32 bits, 128x64 = 2048 float4) into Ps ----
    #pragma unroll
    for (int i = 0; i < 8; i++) {
        int v = tid + i * 256;
        int row = v >> 4, c4 = v & 15;
        float4 d = *(const float4*)(Qb + (size_t)(q0 + row) * DKK + c4 * 4);
        *(float4*)&Ps[row][c4 * 4] = d;
    }
    __syncthreads();

    // ---- extract Q fragments (already tf32) ----
    uint32_t qf[8][2][4];
    #pragma unroll
    for (int s8 = 0; s8 < 8; s8++) {
        #pragma unroll
        for (int t = 0; t < 2; t++) {
            int r = wm * 32 + t * 16 + grp;
            int cc = s8 * 8 + tig;
            qf[s8][t][0] = __float_as_uint(Ps[r    ][cc]);
            qf[s8][t][1] = __float_as_uint(Ps[r + 8][cc]);
            qf[s8][t][2] = __float_as_uint(Ps[r    ][cc + 4]);
            qf[s8][t][3] = __float_as_uint(Ps[r + 8][cc + 4]);
        }
    }

    float o[2][4][4];
    #pragma unroll
    for (int t = 0; t < 2; t++)
        #pragma unroll
        for (int u = 0; u < 4; u++)
            #pragma unroll
            for (int r = 0; r < 4; r++) o[t][u][r] = 0.f;

    float m_r[2][2], l_r[2][2];
    #pragma unroll
    for (int t = 0; t < 2; t++)
        #pragma unroll
        for (int hf = 0; hf < 2; hf++) { m_r[t][hf] = -INFINITY; l_r[t][hf] = 0.f; }

    const int nkt = causal ? (q0 >> 6) + 2 : (SS / 64);

    for (int kt = 0; kt < nkt; kt++) {
        const int k0 = kt * 64;
        __syncthreads();   // S1: KV (prev V) + Ps (prev P / Q frags) free

        // ---- K tile (64x64 = 1024 float4, tf32 bits) -> KV ; kmask ----
        #pragma unroll
        for (int i = 0; i < 4; i++) {
            int v = tid + i * 256;
            int row = v >> 4, c4 = v & 15;
            float4 d = *(const float4*)(Kb + (size_t)(k0 + row) * DKK + c4 * 4);
            *(float4*)&KV[row][c4 * 4] = d;
        }
        if (tid < 64) kmask_s[tid] = k_mask[(size_t)b * SS + k0 + tid];
        __syncthreads();   // S2: K ready

        // ---- S = Q K^T via mma ----
        float sacc[2][4][4];
        #pragma unroll
        for (int t = 0; t < 2; t++)
            #pragma unroll
            for (int u = 0; u < 4; u++)
                #pragma unroll
                for (int r = 0; r < 4; r++) sacc[t][u][r] = 0.f;

        #pragma unroll
        for (int s8 = 0; s8 < 8; s8++) {
            uint32_t kb[4][2];
            const int cc = s8 * 8 + tig;
            #pragma unroll
            for (int u = 0; u < 4; u++) {
                int n = wn * 32 + u * 8 + grp;
                kb[u][0] = __float_as_uint(KV[n][cc]);
                kb[u][1] = __float_as_uint(KV[n][cc + 4]);
            }
            #pragma unroll
            for (int t = 0; t < 2; t++)
                #pragma unroll
                for (int u = 0; u < 4; u++)
                    mma_tf32(sacc[t][u], qf[s8][t], kb[u]);
        }

        // ---- scale + masks (registers) ----
        #pragma unroll
        for (int t = 0; t < 2; t++) {
            int rl0 = wm * 32 + t * 16 + grp;
            int qg0 = q0 + rl0, qg1 = qg0 + 8;
            #pragma unroll
            for (int u = 0; u < 4; u++) {
                int cl = wn * 32 + u * 8 + 2 * tig;
                int kg = k0 + cl;
                int km0 = kmask_s[cl], km1 = kmask_s[cl + 1];
                float x0 = sacc[t][u][0] * 0.125f;
                float x1 = sacc[t][u][1] * 0.125f;
                float x2 = sacc[t][u][2] * 0.125f;
                float x3 = sacc[t][u][3] * 0.125f;
                if ((causal && kg     > qg0) || km0 == 0) x0 = -INFINITY;
                if ((causal && kg + 1 > qg0) || km1 == 0) x1 = -INFINITY;
                if ((causal && kg     > qg1) || km0 == 0) x2 = -INFINITY;
                if ((causal && kg + 1 > qg1) || km1 == 0) x3 = -INFINITY;
                sacc[t][u][0] = x0; sacc[t][u][1] = x1;
                sacc[t][u][2] = x2; sacc[t][u][3] = x3;
            }
        }

        // ---- row max: per-thread partial + quad shuffle + cross-warp via smem ----
        #pragma unroll
        for (int t = 0; t < 2; t++) {
            #pragma unroll
            for (int hf = 0; hf < 2; hf++) {
                float mx = -INFINITY;
                #pragma unroll
                for (int u = 0; u < 4; u++)
                    mx = fmaxf(mx, fmaxf(sacc[t][u][2*hf], sacc[t][u][2*hf + 1]));
                mx = fmaxf(mx, __shfl_xor_sync(0xffffffffu, mx, 1));
                mx = fmaxf(mx, __shfl_xor_sync(0xffffffffu, mx, 2));
                if (tig == 0) redm[wm * 32 + t * 16 + grp + 8 * hf][wn] = mx;
            }
        }
        __syncthreads();   // S3: redm ready, all K reads done

        // ---- V tile (tf32 bits) -> KV (overlaps exp phase) ----
        #pragma unroll
        for (int i = 0; i < 4; i++) {
            int v = tid + i * 256;
            int row = v >> 4, c4 = v & 15;
            float4 d = *(const float4*)(Vb + (size_t)(k0 + row) * DKK + c4 * 4);
            *(float4*)&KV[row][c4 * 4] = d;
        }

        // ---- m_new, exp, row sums ----
        float mnew[2][2];
        #pragma unroll
        for (int t = 0; t < 2; t++) {
            #pragma unroll
            for (int hf = 0; hf < 2; hf++) {
                int rl = wm * 32 + t * 16 + grp + 8 * hf;
                float2 mm = *(float2*)&redm[rl][0];
                mnew[t][hf] = fmaxf(m_r[t][hf], fmaxf(mm.x, mm.y));
            }
        }
        float psum[2][2] = {{0.f, 0.f}, {0.f, 0.f}};
        #pragma unroll
        for (int t = 0; t < 2; t++) {
            #pragma unroll
            for (int u = 0; u < 4; u++) {
                float p0 = __expf(sacc[t][u][0] - mnew[t][0]);
                float p1 = __expf(sacc[t][u][1] - mnew[t][0]);
                float p2 = __expf(sacc[t][u][2] - mnew[t][1]);
                float p3 = __expf(sacc[t][u][3] - mnew[t][1]);
                sacc[t][u][0] = p0; sacc[t][u][1] = p1;
                sacc[t][u][2] = p2; sacc[t][u][3] = p3;
                psum[t][0] += p0 + p1;
                psum[t][1] += p2 + p3;
            }
        }
        #pragma unroll
        for (int t = 0; t < 2; t++) {
            #pragma unroll
            for (int hf = 0; hf < 2; hf++) {
                float s = psum[t][hf];
                s += __shfl_xor_sync(0xffffffffu, s, 1);
                s += __shfl_xor_sync(0xffffffffu, s, 2);
                if (tig == 0) reds[wm * 32 + t * 16 + grp + 8 * hf][wn] = s;
            }
        }

        // ---- write P (tf32) to Ps ----
        #pragma unroll
        for (int t = 0; t < 2; t++) {
            int rl0 = wm * 32 + t * 16 + grp;
            #pragma unroll
            for (int u = 0; u < 4; u++) {
                int cl = wn * 32 + u * 8 + 2 * tig;
                float2 lo, hi;
                lo.x = __uint_as_float(f2tf(sacc[t][u][0]));
                lo.y = __uint_as_float(f2tf(sacc[t][u][1]));
                hi.x = __uint_as_float(f2tf(sacc[t][u][2]));
                hi.y = __uint_as_float(f2tf(sacc[t][u][3]));
                *(float2*)&Ps[rl0    ][cl] = lo;
                *(float2*)&Ps[rl0 + 8][cl] = hi;
            }
        }
        __syncthreads();   // S4: V, reds, Ps all visible

        // ---- l/alpha update + rescale O (registers) ----
        float alpha_v[2][2];
        #pragma unroll
        for (int t = 0; t < 2; t++) {
            #pragma unroll
            for (int hf = 0; hf < 2; hf++) {
                int rl = wm * 32 + t * 16 + grp + 8 * hf;
                float2 ss = *(float2*)&reds[rl][0];
                float al = __expf(m_r[t][hf] - mnew[t][hf]);  // NaN iff both -inf (matches ref)
                l_r[t][hf] = l_r[t][hf] * al + ss.x + ss.y;
                m_r[t][hf] = mnew[t][hf];
                alpha_v[t][hf] = al;
            }
        }
        #pragma unroll
        for (int t = 0; t < 2; t++) {
            #pragma unroll
            for (int u = 0; u < 4; u++) {
                o[t][u][0] *= alpha_v[t][0]; o[t][u][1] *= alpha_v[t][0];
                o[t][u][2] *= alpha_v[t][1]; o[t][u][3] *= alpha_v[t][1];
            }
        }

        // ---- O += P @ V via mma ----
        #pragma unroll
        for (int s8 = 0; s8 < 8; s8++) {
            uint32_t pf[2][4];
            uint32_t vb[4][2];
            const int cc = s8 * 8 + tig;
            #pragma unroll
            for (int t = 0; t < 2; t++) {
                int r = wm * 32 + t * 16 + grp;
                pf[t][0] = __float_as_uint(Ps[r    ][cc]);
                pf[t][1] = __float_as_uint(Ps[r + 8][cc]);
                pf[t][2] = __float_as_uint(Ps[r    ][cc + 4]);
                pf[t][3] = __float_as_uint(Ps[r + 8][cc + 4]);
            }
            #pragma unroll
            for (int u = 0; u < 4; u++) {
                int dcol = wn * 32 + u * 8 + grp;
                int kr = s8 * 8 + tig;
                vb[u][0] = __float_as_uint(KV[kr    ][dcol]);
                vb[u][1] = __float_as_uint(KV[kr + 4][dcol]);
            }
            #pragma unroll
            for (int t = 0; t < 2; t++)
                #pragma unroll
                for (int u = 0; u < 4; u++)
                    mma_tf32(o[t][u], pf[t], vb[u]);
        }
    }

    // ---- epilogue: normalize, q_mask, write tf32 bits to Oh ----
    #pragma unroll
    for (int t = 0; t < 2; t++) {
        #pragma unroll
        for (int hf = 0; hf < 2; hf++) {
            int rl = wm * 32 + t * 16 + grp + 8 * hf;
            int s_ = q0 + rl;
            int qm = q_mask[(size_t)b * SS + s_];
            float inv_l = 1.f / l_r[t][hf];   // NaN rows propagate (matches ref)
            #pragma unroll
            for (int u = 0; u < 4; u++) {
                int dcol = wn * 32 + u * 8 + 2 * tig;
                float2 ov;
                if (qm == 0) {
                    ov = make_float2(0.f, 0.f);
                } else {
                    ov.x = __uint_as_float(f2tf(o[t][u][hf * 2 + 0] * inv_l));
                    ov.y = __uint_as_float(f2tf(o[t][u][hf * 2 + 1] * inv_l));
                }
                *(float2*)(g_Oh + ((size_t)b * SS + s_) * DM + h * DKK + dcol) = ov;
            }
        }
    }
}

// ---------------------------------------------------------------------------
extern "C" void kernel_launch(void* const* d_in, const int* in_sizes, int n_in,
                              void* d_out, int out_size)
{
    const float* q  = (const float*)d_in[0];
    const float* k  = (const float*)d_in[1];
    const int*   qm = (const int*)  d_in[2];
    const int*   km = (const int*)  d_in[3];
    const float* Wq = (const float*)d_in[4];
    const float* bq = (const float*)d_in[5];
    const float* Wk = (const float*)d_in[6];
    const float* bk = (const float*)d_in[7];
    const float* Wv = (const float*)d_in[8];
    const float* bv = (const float*)d_in[9];
    const float* Wo = (const float*)d_in[10];
    const float* bo = (const float*)d_in[11];
    const int* causal = (n_in >= 13) ? (const int*)d_in[12] : nullptr;

    float *Qh, *Kh, *Vh, *Oh, *qtf, *ktf, *Wtf;
    cudaGetSymbolAddress((void**)&Qh,  g_Qh);
    cudaGetSymbolAddress((void**)&Kh,  g_Kh);
    cudaGetSymbolAddress((void**)&Vh,  g_Vh);
    cudaGetSymbolAddress((void**)&Oh,  g_Oh);
    cudaGetSymbolAddress((void**)&qtf, g_qtf);
    cudaGetSymbolAddress((void**)&ktf, g_ktf);
    cudaGetSymbolAddress((void**)&Wtf, g_Wtf);

    cudaFuncSetAttribute(gemm_tf32, cudaFuncAttributeMaxDynamicSharedMemorySize,
                         (int)GEMM_SMEM_BYTES);
    cudaFuncSetAttribute(flash_attn_tc, cudaFuncAttributeMaxDynamicSharedMemorySize,
                         (int)FL_SMEM_BYTES);

    // fused pre-pass: fp32 -> tf32 bits for all GEMM inputs (one launch)
    cvt_all<<<(NCVT4 + 255) / 256, 256>>>(q, k, Wq, Wk, Wv, Wo, qtf, ktf, Wtf);

    dim3 gg(DM / 128, (BB * SS) / 128);   // (8, 32)
    gemm_tf32<<<gg, 128, GEMM_SMEM_BYTES>>>(qtf, Wtf + 0 * DM * DM, bq, Qh, 1);
    gemm_tf32<<<gg, 128, GEMM_SMEM_BYTES>>>(ktf, Wtf + 1 * DM * DM, bk, Kh, 1);
    gemm_tf32<<<gg, 128, GEMM_SMEM_BYTES>>>(ktf, Wtf + 2 * DM * DM, bv, Vh, 1);

    dim3 ga(SS / 128, NH, BB);            // (16, 16, 2)
    flash_attn_tc<<<ga, 256, FL_SMEM_BYTES>>>(qm, km, causal, 1);

    gemm_tf32<<<gg, 128, GEMM_SMEM_BYTES>>>(Oh, Wtf + 3 * DM * DM, bo, (float*)d_out, 0);
}

// round 9
// speedup vs baseline: 1.0842x; 1.0842x over previous
#include <cuda_runtime.h>
#include <math.h>
#include <stdint.h>

#define BB  2
#define SS  2048
#define DM  1024
#define NH  16
#define DKK 64

// Scratch (allocation-free rule: __device__ globals)
__device__ float g_Qh[BB*NH*SS*DKK];   // [b][h][s][dk]  (tf32 bits)
__device__ float g_Kh[BB*NH*SS*DKK];   // (tf32 bits)
__device__ float g_Vh[BB*NH*SS*DKK];   // (tf32 bits)
__device__ float g_Oh[BB*SS*DM];       // [b][s][h*64+dk] (tf32 bits)
__device__ float g_qtf[BB*SS*DM];      // pre-converted q (tf32 bits)
__device__ float g_ktf[BB*SS*DM];      // pre-converted k (tf32 bits)
__device__ float g_Wtf[4*DM*DM];       // pre-converted Wq,Wk,Wv,Wo (tf32 bits)

// ---------------------------------------------------------------------------
// tf32 / cp.async helpers
// ---------------------------------------------------------------------------
__device__ __forceinline__ uint32_t f2tf(float x) {
    uint32_t u;
    asm("cvt.rna.tf32.f32 %0, %1;" : "=r"(u) : "f"(x));
    return u;
}

__device__ __forceinline__ void mma_tf32(float c[4], const uint32_t a[4], const uint32_t b[2]) {
    asm volatile(
        "mma.sync.aligned.m16n8k8.row.col.f32.tf32.tf32.f32 "
        "{%0,%1,%2,%3}, {%4,%5,%6,%7}, {%8,%9}, {%0,%1,%2,%3};\n"
        : "+f"(c[0]), "+f"(c[1]), "+f"(c[2]), "+f"(c[3])
        : "r"(a[0]), "r"(a[1]), "r"(a[2]), "r"(a[3]), "r"(b[0]), "r"(b[1]));
}

__device__ __forceinline__ void cp16(float* dst, const float* src) {
    uint32_t d = (uint32_t)__cvta_generic_to_shared(dst);
    asm volatile("cp.async.cg.shared.global [%0], [%1], 16;" :: "r"(d), "l"(src));
}
__device__ __forceinline__ void cp_commit() {
    asm volatile("cp.async.commit_group;");
}
__device__ __forceinline__ void cp_wait1() {
    asm volatile("cp.async.wait_group 1;");
}

// ---------------------------------------------------------------------------
// Single fused fp32 -> tf32(RNA) pre-pass over q, k, Wq, Wk, Wv, Wo.
// ---------------------------------------------------------------------------
#define NQ4 (BB*SS*DM/4)   // 1048576 float4
#define NW4 (DM*DM/4)      // 262144 float4
#define NCVT4 (2*NQ4 + 4*NW4)

__global__ void cvt_all(const float* __restrict__ q, const float* __restrict__ k,
                        const float* __restrict__ Wq, const float* __restrict__ Wk,
                        const float* __restrict__ Wv, const float* __restrict__ Wo,
                        float* __restrict__ qtf, float* __restrict__ ktf,
                        float* __restrict__ Wtf)
{
    int i = blockIdx.x * blockDim.x + threadIdx.x;
    if (i >= NCVT4) return;
    const float4* src; float4* dst; int off;
    if (i < NQ4)            { src = (const float4*)q;  dst = (float4*)qtf; off = i; }
    else if (i < 2 * NQ4)   { src = (const float4*)k;  dst = (float4*)ktf; off = i - NQ4; }
    else {
        int j = i - 2 * NQ4;
        int w = j / NW4; off = j - w * NW4;
        src = (const float4*)(w == 0 ? Wq : w == 1 ? Wk : w == 2 ? Wv : Wo);
        dst = (float4*)(Wtf) + (size_t)w * NW4;
    }
    float4 d = src[off];
    float4 e;
    e.x = __uint_as_float(f2tf(d.x)); e.y = __uint_as_float(f2tf(d.y));
    e.z = __uint_as_float(f2tf(d.z)); e.w = __uint_as_float(f2tf(d.w));
    dst[off] = e;
}

// ---------------------------------------------------------------------------
// GEMM core: tf32 mma, cp.async double-buffered, cvt-free mainloop.
// 128 threads (4 warps 2x2), warp tile 64x64 (LDS/mma = 1.0).
// Y[m][n] = sum_k X[m][k]*W[n][k] + bias[n]
// head_split=1: write tf32-rounded bits to [b][h][s][dk]; else fp32 row-major.
// ---------------------------------------------------------------------------
#define AS_OFF(buf) ((buf) * 4608)            // 128*36 floats
#define BS_OFF(buf) (9216 + (buf) * 4608)
#define GEMM_SMEM_BYTES (18432 * sizeof(float))   // 73728

__device__ __forceinline__ void gemm_core(
    const float* __restrict__ X, const float* __restrict__ W,
    const float* __restrict__ bias, float* __restrict__ Y,
    int head_split, float* sm)
{
    const int bm = blockIdx.y * 128;
    const int bn = blockIdx.x * 128;
    const int tid = threadIdx.x;
    const int lane = tid & 31, wid = tid >> 5;
    const int wm = wid >> 1;        // 0..1  (m offset wm*64)
    const int wn = wid & 1;         // 0..1  (n offset wn*64)
    const int grp = lane >> 2;      // 0..7
    const int tig = lane & 3;       // 0..3

    const int ldrow = tid >> 3;     // 0..15
    const int ldc4  = tid & 7;      // 0..7

    float c[4][8][4];
    #pragma unroll
    for (int t = 0; t < 4; t++)
        #pragma unroll
        for (int u = 0; u < 8; u++)
            #pragma unroll
            for (int r = 0; r < 4; r++) c[t][u][r] = 0.f;

    // prologue: issue tile 0 (A and B 128x32 each = 1024 float4, 8 per thread)
    #pragma unroll
    for (int i = 0; i < 8; i++) {
        int row = ldrow + i * 16;
        cp16(&sm[AS_OFF(0) + row * 36 + ldc4 * 4], X + (size_t)(bm + row) * DM + ldc4 * 4);
        cp16(&sm[BS_OFF(0) + row * 36 + ldc4 * 4], W + (size_t)(bn + row) * DM + ldc4 * 4);
    }
    cp_commit();

    const int NT = DM / 32;   // 32
    for (int kt = 0; kt < NT; kt++) {
        if (kt + 1 < NT) {
            int k0n = (kt + 1) * 32;
            int bufn = (kt + 1) & 1;
            #pragma unroll
            for (int i = 0; i < 8; i++) {
                int row = ldrow + i * 16;
                cp16(&sm[AS_OFF(bufn) + row * 36 + ldc4 * 4], X + (size_t)(bm + row) * DM + k0n + ldc4 * 4);
                cp16(&sm[BS_OFF(bufn) + row * 36 + ldc4 * 4], W + (size_t)(bn + row) * DM + k0n + ldc4 * 4);
            }
        }
        cp_commit();
        cp_wait1();
        __syncthreads();

        const float* As = &sm[AS_OFF(kt & 1)];
        const float* Bs = &sm[BS_OFF(kt & 1)];

        #pragma unroll
        for (int s = 0; s < 4; s++) {
            uint32_t a[4][4];
            uint32_t b[8][2];
            const int cc = s * 8 + tig;
            #pragma unroll
            for (int t = 0; t < 4; t++) {
                int r = wm * 64 + t * 16 + grp;
                a[t][0] = __float_as_uint(As[r * 36 + cc]);
                a[t][1] = __float_as_uint(As[(r + 8) * 36 + cc]);
                a[t][2] = __float_as_uint(As[r * 36 + cc + 4]);
                a[t][3] = __float_as_uint(As[(r + 8) * 36 + cc + 4]);
            }
            #pragma unroll
            for (int u = 0; u < 8; u++) {
                int n = wn * 64 + u * 8 + grp;
                b[u][0] = __float_as_uint(Bs[n * 36 + cc]);
                b[u][1] = __float_as_uint(Bs[n * 36 + cc + 4]);
            }
            #pragma unroll
            for (int t = 0; t < 4; t++)
                #pragma unroll
                for (int u = 0; u < 8; u++)
                    mma_tf32(c[t][u], a[t], b[u]);
        }
        __syncthreads();   // before next iter's cp.async overwrites the other buffer
    }

    // epilogue
    #pragma unroll
    for (int t = 0; t < 4; t++) {
        #pragma unroll
        for (int u = 0; u < 8; u++) {
            int r0  = bm + wm * 64 + t * 16 + grp;
            int col = bn + wn * 64 + u * 8 + 2 * tig;
            float b0 = bias[col], b1 = bias[col + 1];
            #pragma unroll
            for (int half = 0; half < 2; half++) {
                int m = r0 + half * 8;
                float vx = c[t][u][half * 2 + 0] + b0;
                float vy = c[t][u][half * 2 + 1] + b1;
                if (head_split) {
                    float2 o;
                    o.x = __uint_as_float(f2tf(vx));
                    o.y = __uint_as_float(f2tf(vy));
                    int b_ = m >> 11, s_ = m & 2047;
                    int h_ = col >> 6, dk = col & 63;
                    *(float2*)(Y + (((size_t)b_ * NH + h_) * SS + s_) * DKK + dk) = o;
                } else {
                    float2 o = make_float2(vx, vy);
                    *(float2*)(Y + (size_t)m * DM + col) = o;
                }
            }
        }
    }
}

// Fused Q/K/V projection: blockIdx.z selects which projection.
struct QKVArgs {
    const float *xq, *xk;
    const float *w0, *w1, *w2;
    const float *b0, *b1, *b2;
    float *y0, *y1, *y2;
};

__global__ __launch_bounds__(128, 2)
void gemm_qkv(QKVArgs a)
{
    extern __shared__ float sm[];
    const int z = blockIdx.z;
    const float* X = (z == 0) ? a.xq : a.xk;
    const float* W = (z == 0) ? a.w0 : (z == 1) ? a.w1 : a.w2;
    const float* B = (z == 0) ? a.b0 : (z == 1) ? a.b1 : a.b2;
    float*       Y = (z == 0) ? a.y0 : (z == 1) ? a.y1 : a.y2;
    gemm_core(X, W, B, Y, 1, sm);
}

__global__ __launch_bounds__(128, 2)
void gemm_tf32(const float* __restrict__ X, const float* __restrict__ W,
               const float* __restrict__ bias, float* __restrict__ Y,
               int head_split)
{
    extern __shared__ float sm[];
    gemm_core(X, W, bias, Y, head_split, sm);
}

// ---------------------------------------------------------------------------
// Flash attention, tf32 mma, register-resident online softmax.
// (round-7 proven version: Sq=64, tf32-bit inputs, longest-first)
// Block: 128 threads (4 warps 2x2), tile Sq=64 x Sk=64, d_k=64.
// grid = (S/64, NH, B)
// ---------------------------------------------------------------------------
__global__ __launch_bounds__(128, 3)
void flash_attn_tc(const int* __restrict__ q_mask, const int* __restrict__ k_mask,
                   const int* __restrict__ causal_flag, int causal_default)
{
    __shared__ float Ps[64][68];
    __shared__ float KV[64][68];
    __shared__ float redm[64][2];
    __shared__ float reds[64][2];
    __shared__ int   kmask_s[64];

    const int b  = blockIdx.z, h = blockIdx.y;
    const int q0 = ((int)gridDim.x - 1 - (int)blockIdx.x) * 64;  // longest-first
    const int tid = threadIdx.x;
    const int lane = tid & 31, wid = tid >> 5;
    const int wm = wid >> 1;      // 0..1 : q rows [wm*32, +32)
    const int wn = wid & 1;       // 0..1 : k cols / d cols [wn*32, +32)
    const int grp = lane >> 2;    // 0..7
    const int tig = lane & 3;     // 0..3
    const int causal = causal_flag ? causal_flag[0] : causal_default;

    const float* Qb = g_Qh + (((size_t)b * NH + h) * SS) * DKK;
    const float* Kb = g_Kh + (((size_t)b * NH + h) * SS) * DKK;
    const float* Vb = g_Vh + (((size_t)b * NH + h) * SS) * DKK;

    // ---- stage Q (tf32 bits) into Ps ----
    #pragma unroll
    for (int i = 0; i < 8; i++) {
        int v = tid + i * 128;
        int row = v >> 4, c4 = v & 15;
        float4 d = *(const float4*)(Qb + (size_t)(q0 + row) * DKK + c4 * 4);
        *(float4*)&Ps[row][c4 * 4] = d;
    }
    __syncthreads();

    // ---- extract Q fragments (already tf32) ----
    uint32_t qf[8][2][4];
    #pragma unroll
    for (int s8 = 0; s8 < 8; s8++) {
        #pragma unroll
        for (int t = 0; t < 2; t++) {
            int r = wm * 32 + t * 16 + grp;
            int cc = s8 * 8 + tig;
            qf[s8][t][0] = __float_as_uint(Ps[r    ][cc]);
            qf[s8][t][1] = __float_as_uint(Ps[r + 8][cc]);
            qf[s8][t][2] = __float_as_uint(Ps[r    ][cc + 4]);
            qf[s8][t][3] = __float_as_uint(Ps[r + 8][cc + 4]);
        }
    }

    float o[2][4][4];
    #pragma unroll
    for (int t = 0; t < 2; t++)
        #pragma unroll
        for (int u = 0; u < 4; u++)
            #pragma unroll
            for (int r = 0; r < 4; r++) o[t][u][r] = 0.f;

    float m_r[2][2], l_r[2][2];
    #pragma unroll
    for (int t = 0; t < 2; t++)
        #pragma unroll
        for (int hf = 0; hf < 2; hf++) { m_r[t][hf] = -INFINITY; l_r[t][hf] = 0.f; }

    const int nkt = causal ? (q0 >> 6) + 1 : (SS / 64);

    for (int kt = 0; kt < nkt; kt++) {
        const int k0 = kt * 64;
        __syncthreads();   // S1: KV (prev V) + Ps (prev P / Q frags) free

        // ---- K tile (64x64 = 1024 float4, tf32 bits) -> KV ; kmask ----
        #pragma unroll
        for (int i = 0; i < 8; i++) {
            int v = tid + i * 128;
            int row = v >> 4, c4 = v & 15;
            float4 d = *(const float4*)(Kb + (size_t)(k0 + row) * DKK + c4 * 4);
            *(float4*)&KV[row][c4 * 4] = d;
        }
        if (tid < 64) kmask_s[tid] = k_mask[(size_t)b * SS + k0 + tid];
        __syncthreads();   // S2: K ready

        // ---- S = Q K^T via mma ----
        float sacc[2][4][4];
        #pragma unroll
        for (int t = 0; t < 2; t++)
            #pragma unroll
            for (int u = 0; u < 4; u++)
                #pragma unroll
                for (int r = 0; r < 4; r++) sacc[t][u][r] = 0.f;

        #pragma unroll
        for (int s8 = 0; s8 < 8; s8++) {
            uint32_t kb[4][2];
            const int cc = s8 * 8 + tig;
            #pragma unroll
            for (int u = 0; u < 4; u++) {
                int n = wn * 32 + u * 8 + grp;
                kb[u][0] = __float_as_uint(KV[n][cc]);
                kb[u][1] = __float_as_uint(KV[n][cc + 4]);
            }
            #pragma unroll
            for (int t = 0; t < 2; t++)
                #pragma unroll
                for (int u = 0; u < 4; u++)
                    mma_tf32(sacc[t][u], qf[s8][t], kb[u]);
        }

        // ---- scale + masks (registers) ----
        #pragma unroll
        for (int t = 0; t < 2; t++) {
            int rl0 = wm * 32 + t * 16 + grp;
            int qg0 = q0 + rl0, qg1 = qg0 + 8;
            #pragma unroll
            for (int u = 0; u < 4; u++) {
                int cl = wn * 32 + u * 8 + 2 * tig;
                int kg = k0 + cl;
                int km0 = kmask_s[cl], km1 = kmask_s[cl + 1];
                float x0 = sacc[t][u][0] * 0.125f;
                float x1 = sacc[t][u][1] * 0.125f;
                float x2 = sacc[t][u][2] * 0.125f;
                float x3 = sacc[t][u][3] * 0.125f;
                if ((causal && kg     > qg0) || km0 == 0) x0 = -INFINITY;
                if ((causal && kg + 1 > qg0) || km1 == 0) x1 = -INFINITY;
                if ((causal && kg     > qg1) || km0 == 0) x2 = -INFINITY;
                if ((causal && kg + 1 > qg1) || km1 == 0) x3 = -INFINITY;
                sacc[t][u][0] = x0; sacc[t][u][1] = x1;
                sacc[t][u][2] = x2; sacc[t][u][3] = x3;
            }
        }

        // ---- row max: per-thread partial + quad shuffle + cross-warp via smem ----
        #pragma unroll
        for (int t = 0; t < 2; t++) {
            #pragma unroll
            for (int hf = 0; hf < 2; hf++) {
                float mx = -INFINITY;
                #pragma unroll
                for (int u = 0; u < 4; u++)
                    mx = fmaxf(mx, fmaxf(sacc[t][u][2*hf], sacc[t][u][2*hf + 1]));
                mx = fmaxf(mx, __shfl_xor_sync(0xffffffffu, mx, 1));
                mx = fmaxf(mx, __shfl_xor_sync(0xffffffffu, mx, 2));
                if (tig == 0) redm[wm * 32 + t * 16 + grp + 8 * hf][wn] = mx;
            }
        }
        __syncthreads();   // S3: redm ready, all K reads done

        // ---- V tile (tf32 bits) -> KV (overlaps exp phase) ----
        #pragma unroll
        for (int i = 0; i < 8; i++) {
            int v = tid + i * 128;
            int row = v >> 4, c4 = v & 15;
            float4 d = *(const float4*)(Vb + (size_t)(k0 + row) * DKK + c4 * 4);
            *(float4*)&KV[row][c4 * 4] = d;
        }

        // ---- m_new, exp, row sums ----
        float mnew[2][2];
        #pragma unroll
        for (int t = 0; t < 2; t++) {
            #pragma unroll
            for (int hf = 0; hf < 2; hf++) {
                int rl = wm * 32 + t * 16 + grp + 8 * hf;
                float2 mm = *(float2*)&redm[rl][0];
                mnew[t][hf] = fmaxf(m_r[t][hf], fmaxf(mm.x, mm.y));
            }
        }
        float psum[2][2] = {{0.f, 0.f}, {0.f, 0.f}};
        #pragma unroll
        for (int t = 0; t < 2; t++) {
            #pragma unroll
            for (int u = 0; u < 4; u++) {
                float p0 = __expf(sacc[t][u][0] - mnew[t][0]);
                float p1 = __expf(sacc[t][u][1] - mnew[t][0]);
                float p2 = __expf(sacc[t][u][2] - mnew[t][1]);
                float p3 = __expf(sacc[t][u][3] - mnew[t][1]);
                sacc[t][u][0] = p0; sacc[t][u][1] = p1;
                sacc[t][u][2] = p2; sacc[t][u][3] = p3;
                psum[t][0] += p0 + p1;
                psum[t][1] += p2 + p3;
            }
        }
        #pragma unroll
        for (int t = 0; t < 2; t++) {
            #pragma unroll
            for (int hf = 0; hf < 2; hf++) {
                float s = psum[t][hf];
                s += __shfl_xor_sync(0xffffffffu, s, 1);
                s += __shfl_xor_sync(0xffffffffu, s, 2);
                if (tig == 0) reds[wm * 32 + t * 16 + grp + 8 * hf][wn] = s;
            }
        }

        // ---- write P (tf32) to Ps ----
        #pragma unroll
        for (int t = 0; t < 2; t++) {
            int rl0 = wm * 32 + t * 16 + grp;
            #pragma unroll
            for (int u = 0; u < 4; u++) {
                int cl = wn * 32 + u * 8 + 2 * tig;
                float2 lo, hi;
                lo.x = __uint_as_float(f2tf(sacc[t][u][0]));
                lo.y = __uint_as_float(f2tf(sacc[t][u][1]));
                hi.x = __uint_as_float(f2tf(sacc[t][u][2]));
                hi.y = __uint_as_float(f2tf(sacc[t][u][3]));
                *(float2*)&Ps[rl0    ][cl] = lo;
                *(float2*)&Ps[rl0 + 8][cl] = hi;
            }
        }
        __syncthreads();   // S4: V, reds, Ps all visible

        // ---- l/alpha update + rescale O (registers) ----
        float alpha_v[2][2];
        #pragma unroll
        for (int t = 0; t < 2; t++) {
            #pragma unroll
            for (int hf = 0; hf < 2; hf++) {
                int rl = wm * 32 + t * 16 + grp + 8 * hf;
                float2 ss = *(float2*)&reds[rl][0];
                float al = __expf(m_r[t][hf] - mnew[t][hf]);  // NaN iff both -inf (matches ref)
                l_r[t][hf] = l_r[t][hf] * al + ss.x + ss.y;
                m_r[t][hf] = mnew[t][hf];
                alpha_v[t][hf] = al;
            }
        }
        #pragma unroll
        for (int t = 0; t < 2; t++) {
            #pragma unroll
            for (int u = 0; u < 4; u++) {
                o[t][u][0] *= alpha_v[t][0]; o[t][u][1] *= alpha_v[t][0];
                o[t][u][2] *= alpha_v[t][1]; o[t][u][3] *= alpha_v[t][1];
            }
        }

        // ---- O += P @ V via mma ----
        #pragma unroll
        for (int s8 = 0; s8 < 8; s8++) {
            uint32_t pf[2][4];
            uint32_t vb[4][2];
            const int cc = s8 * 8 + tig;
            #pragma unroll
            for (int t = 0; t < 2; t++) {
                int r = wm * 32 + t * 16 + grp;
                pf[t][0] = __float_as_uint(Ps[r    ][cc]);
                pf[t][1] = __float_as_uint(Ps[r + 8][cc]);
                pf[t][2] = __float_as_uint(Ps[r    ][cc + 4]);
                pf[t][3] = __float_as_uint(Ps[r + 8][cc + 4]);
            }
            #pragma unroll
            for (int u = 0; u < 4; u++) {
                int dcol = wn * 32 + u * 8 + grp;
                int kr = s8 * 8 + tig;
                vb[u][0] = __float_as_uint(KV[kr    ][dcol]);
                vb[u][1] = __float_as_uint(KV[kr + 4][dcol]);
            }
            #pragma unroll
            for (int t = 0; t < 2; t++)
                #pragma unroll
                for (int u = 0; u < 4; u++)
                    mma_tf32(o[t][u], pf[t], vb[u]);
        }
    }

    // ---- epilogue: normalize, q_mask, write tf32 bits to Oh ----
    #pragma unroll
    for (int t = 0; t < 2; t++) {
        #pragma unroll
        for (int hf = 0; hf < 2; hf++) {
            int rl = wm * 32 + t * 16 + grp + 8 * hf;
            int s_ = q0 + rl;
            int qm = q_mask[(size_t)b * SS + s_];
            float inv_l = 1.f / l_r[t][hf];   // NaN rows propagate (matches ref)
            #pragma unroll
            for (int u = 0; u < 4; u++) {
                int dcol = wn * 32 + u * 8 + 2 * tig;
                float2 ov;
                if (qm == 0) {
                    ov = make_float2(0.f, 0.f);
                } else {
                    ov.x = __uint_as_float(f2tf(o[t][u][hf * 2 + 0] * inv_l));
                    ov.y = __uint_as_float(f2tf(o[t][u][hf * 2 + 1] * inv_l));
                }
                *(float2*)(g_Oh + ((size_t)b * SS + s_) * DM + h * DKK + dcol) = ov;
            }
        }
    }
}

// ---------------------------------------------------------------------------
extern "C" void kernel_launch(void* const* d_in, const int* in_sizes, int n_in,
                              void* d_out, int out_size)
{
    const float* q  = (const float*)d_in[0];
    const float* k  = (const float*)d_in[1];
    const int*   qm = (const int*)  d_in[2];
    const int*   km = (const int*)  d_in[3];
    const float* Wq = (const float*)d_in[4];
    const float* bq = (const float*)d_in[5];
    const float* Wk = (const float*)d_in[6];
    const float* bk = (const float*)d_in[7];
    const float* Wv = (const float*)d_in[8];
    const float* bv = (const float*)d_in[9];
    const float* Wo = (const float*)d_in[10];
    const float* bo = (const float*)d_in[11];
    const int* causal = (n_in >= 13) ? (const int*)d_in[12] : nullptr;

    float *Qh, *Kh, *Vh, *Oh, *qtf, *ktf, *Wtf;
    cudaGetSymbolAddress((void**)&Qh,  g_Qh);
    cudaGetSymbolAddress((void**)&Kh,  g_Kh);
    cudaGetSymbolAddress((void**)&Vh,  g_Vh);
    cudaGetSymbolAddress((void**)&Oh,  g_Oh);
    cudaGetSymbolAddress((void**)&qtf, g_qtf);
    cudaGetSymbolAddress((void**)&ktf, g_ktf);
    cudaGetSymbolAddress((void**)&Wtf, g_Wtf);

    cudaFuncSetAttribute(gemm_qkv, cudaFuncAttributeMaxDynamicSharedMemorySize,
                         (int)GEMM_SMEM_BYTES);
    cudaFuncSetAttribute(gemm_tf32, cudaFuncAttributeMaxDynamicSharedMemorySize,
                         (int)GEMM_SMEM_BYTES);

    // fused pre-pass: fp32 -> tf32 bits for all GEMM inputs (one launch)
    cvt_all<<<(NCVT4 + 255) / 256, 256>>>(q, k, Wq, Wk, Wv, Wo, qtf, ktf, Wtf);

    // fused Q/K/V projections: one launch, 768 blocks
    QKVArgs qa;
    qa.xq = qtf; qa.xk = ktf;
    qa.w0 = Wtf + 0 * DM * DM; qa.w1 = Wtf + 1 * DM * DM; qa.w2 = Wtf + 2 * DM * DM;
    qa.b0 = bq;  qa.b1 = bk;  qa.b2 = bv;
    qa.y0 = Qh;  qa.y1 = Kh;  qa.y2 = Vh;
    dim3 gq(DM / 128, (BB * SS) / 128, 3);   // (8, 32, 3)
    gemm_qkv<<<gq, 128, GEMM_SMEM_BYTES>>>(qa);

    dim3 ga(SS / 64, NH, BB);                // (32, 16, 2)
    flash_attn_tc<<<ga, 128>>>(qm, km, causal, 1);

    dim3 gg(DM / 128, (BB * SS) / 128);      // (8, 32)
    gemm_tf32<<<gg, 128, GEMM_SMEM_BYTES>>>(Oh, Wtf + 3 * DM * DM, bo, (float*)d_out, 0);
}

// round 10
// speedup vs baseline: 1.2109x; 1.1169x over previous
#include <cuda_runtime.h>
#include <math.h>
#include <stdint.h>

#define BB  2
#define SS  2048
#define DM  1024
#define NH  16
#define DKK 64

// Scratch (allocation-free rule: __device__ globals)
__device__ float g_Qh[BB*NH*SS*DKK];   // [b][h][s][dk]  (tf32 bits)
__device__ float g_Kh[BB*NH*SS*DKK];   // (tf32 bits)
__device__ float g_Vh[BB*NH*SS*DKK];   // (tf32 bits)
__device__ float g_Oh[BB*SS*DM];       // [b][s][h*64+dk] (tf32 bits)
__device__ float g_qtf[BB*SS*DM];      // pre-converted q (tf32 bits)
__device__ float g_ktf[BB*SS*DM];      // pre-converted k (tf32 bits)
__device__ float g_Wtf[4*DM*DM];       // pre-converted Wq,Wk,Wv,Wo (tf32 bits)

// ---------------------------------------------------------------------------
// tf32 / cp.async helpers
// ---------------------------------------------------------------------------
__device__ __forceinline__ uint32_t f2tf(float x) {
    uint32_t u;
    asm("cvt.rna.tf32.f32 %0, %1;" : "=r"(u) : "f"(x));
    return u;
}

__device__ __forceinline__ void mma_tf32(float c[4], const uint32_t a[4], const uint32_t b[2]) {
    asm volatile(
        "mma.sync.aligned.m16n8k8.row.col.f32.tf32.tf32.f32 "
        "{%0,%1,%2,%3}, {%4,%5,%6,%7}, {%8,%9}, {%0,%1,%2,%3};\n"
        : "+f"(c[0]), "+f"(c[1]), "+f"(c[2]), "+f"(c[3])
        : "r"(a[0]), "r"(a[1]), "r"(a[2]), "r"(a[3]), "r"(b[0]), "r"(b[1]));
}

__device__ __forceinline__ void cp16(float* dst, const float* src) {
    uint32_t d = (uint32_t)__cvta_generic_to_shared(dst);
    asm volatile("cp.async.cg.shared.global [%0], [%1], 16;" :: "r"(d), "l"(src));
}
__device__ __forceinline__ void cp_commit() {
    asm volatile("cp.async.commit_group;");
}
__device__ __forceinline__ void cp_wait0() {
    asm volatile("cp.async.wait_group 0;");
}
__device__ __forceinline__ void cp_wait1() {
    asm volatile("cp.async.wait_group 1;");
}

// ---------------------------------------------------------------------------
// Single fused fp32 -> tf32(RNA) pre-pass over q, k, Wq, Wk, Wv, Wo.
// ---------------------------------------------------------------------------
#define NQ4 (BB*SS*DM/4)   // 1048576 float4
#define NW4 (DM*DM/4)      // 262144 float4
#define NCVT4 (2*NQ4 + 4*NW4)

__global__ void cvt_all(const float* __restrict__ q, const float* __restrict__ k,
                        const float* __restrict__ Wq, const float* __restrict__ Wk,
                        const float* __restrict__ Wv, const float* __restrict__ Wo,
                        float* __restrict__ qtf, float* __restrict__ ktf,
                        float* __restrict__ Wtf)
{
    int i = blockIdx.x * blockDim.x + threadIdx.x;
    if (i >= NCVT4) return;
    const float4* src; float4* dst; int off;
    if (i < NQ4)            { src = (const float4*)q;  dst = (float4*)qtf; off = i; }
    else if (i < 2 * NQ4)   { src = (const float4*)k;  dst = (float4*)ktf; off = i - NQ4; }
    else {
        int j = i - 2 * NQ4;
        int w = j / NW4; off = j - w * NW4;
        src = (const float4*)(w == 0 ? Wq : w == 1 ? Wk : w == 2 ? Wv : Wo);
        dst = (float4*)(Wtf) + (size_t)w * NW4;
    }
    float4 d = src[off];
    float4 e;
    e.x = __uint_as_float(f2tf(d.x)); e.y = __uint_as_float(f2tf(d.y));
    e.z = __uint_as_float(f2tf(d.z)); e.w = __uint_as_float(f2tf(d.w));
    dst[off] = e;
}

// ---------------------------------------------------------------------------
// GEMM core: tf32 mma, cp.async double-buffered, cvt-free mainloop.
// 128 threads (4 warps 2x2), warp tile 64x64 (LDS/mma = 1.0).
// ---------------------------------------------------------------------------
#define AS_OFF(buf) ((buf) * 4608)            // 128*36 floats
#define BS_OFF(buf) (9216 + (buf) * 4608)
#define GEMM_SMEM_BYTES (18432 * sizeof(float))   // 73728

__device__ __forceinline__ void gemm_core(
    const float* __restrict__ X, const float* __restrict__ W,
    const float* __restrict__ bias, float* __restrict__ Y,
    int head_split, float* sm)
{
    const int bm = blockIdx.y * 128;
    const int bn = blockIdx.x * 128;
    const int tid = threadIdx.x;
    const int lane = tid & 31, wid = tid >> 5;
    const int wm = wid >> 1;        // 0..1  (m offset wm*64)
    const int wn = wid & 1;         // 0..1  (n offset wn*64)
    const int grp = lane >> 2;      // 0..7
    const int tig = lane & 3;       // 0..3

    const int ldrow = tid >> 3;     // 0..15
    const int ldc4  = tid & 7;      // 0..7

    float c[4][8][4];
    #pragma unroll
    for (int t = 0; t < 4; t++)
        #pragma unroll
        for (int u = 0; u < 8; u++)
            #pragma unroll
            for (int r = 0; r < 4; r++) c[t][u][r] = 0.f;

    #pragma unroll
    for (int i = 0; i < 8; i++) {
        int row = ldrow + i * 16;
        cp16(&sm[AS_OFF(0) + row * 36 + ldc4 * 4], X + (size_t)(bm + row) * DM + ldc4 * 4);
        cp16(&sm[BS_OFF(0) + row * 36 + ldc4 * 4], W + (size_t)(bn + row) * DM + ldc4 * 4);
    }
    cp_commit();

    const int NT = DM / 32;   // 32
    for (int kt = 0; kt < NT; kt++) {
        if (kt + 1 < NT) {
            int k0n = (kt + 1) * 32;
            int bufn = (kt + 1) & 1;
            #pragma unroll
            for (int i = 0; i < 8; i++) {
                int row = ldrow + i * 16;
                cp16(&sm[AS_OFF(bufn) + row * 36 + ldc4 * 4], X + (size_t)(bm + row) * DM + k0n + ldc4 * 4);
                cp16(&sm[BS_OFF(bufn) + row * 36 + ldc4 * 4], W + (size_t)(bn + row) * DM + k0n + ldc4 * 4);
            }
        }
        cp_commit();
        cp_wait1();
        __syncthreads();

        const float* As = &sm[AS_OFF(kt & 1)];
        const float* Bs = &sm[BS_OFF(kt & 1)];

        #pragma unroll
        for (int s = 0; s < 4; s++) {
            uint32_t a[4][4];
            uint32_t b[8][2];
            const int cc = s * 8 + tig;
            #pragma unroll
            for (int t = 0; t < 4; t++) {
                int r = wm * 64 + t * 16 + grp;
                a[t][0] = __float_as_uint(As[r * 36 + cc]);
                a[t][1] = __float_as_uint(As[(r + 8) * 36 + cc]);
                a[t][2] = __float_as_uint(As[r * 36 + cc + 4]);
                a[t][3] = __float_as_uint(As[(r + 8) * 36 + cc + 4]);
            }
            #pragma unroll
            for (int u = 0; u < 8; u++) {
                int n = wn * 64 + u * 8 + grp;
                b[u][0] = __float_as_uint(Bs[n * 36 + cc]);
                b[u][1] = __float_as_uint(Bs[n * 36 + cc + 4]);
            }
            #pragma unroll
            for (int t = 0; t < 4; t++)
                #pragma unroll
                for (int u = 0; u < 8; u++)
                    mma_tf32(c[t][u], a[t], b[u]);
        }
        __syncthreads();
    }

    #pragma unroll
    for (int t = 0; t < 4; t++) {
        #pragma unroll
        for (int u = 0; u < 8; u++) {
            int r0  = bm + wm * 64 + t * 16 + grp;
            int col = bn + wn * 64 + u * 8 + 2 * tig;
            float b0 = bias[col], b1 = bias[col + 1];
            #pragma unroll
            for (int half = 0; half < 2; half++) {
                int m = r0 + half * 8;
                float vx = c[t][u][half * 2 + 0] + b0;
                float vy = c[t][u][half * 2 + 1] + b1;
                if (head_split) {
                    float2 o;
                    o.x = __uint_as_float(f2tf(vx));
                    o.y = __uint_as_float(f2tf(vy));
                    int b_ = m >> 11, s_ = m & 2047;
                    int h_ = col >> 6, dk = col & 63;
                    *(float2*)(Y + (((size_t)b_ * NH + h_) * SS + s_) * DKK + dk) = o;
                } else {
                    float2 o = make_float2(vx, vy);
                    *(float2*)(Y + (size_t)m * DM + col) = o;
                }
            }
        }
    }
}

// Fused Q/K/V projection: blockIdx.z selects which projection.
struct QKVArgs {
    const float *xq, *xk;
    const float *w0, *w1, *w2;
    const float *b0, *b1, *b2;
    float *y0, *y1, *y2;
};

__global__ __launch_bounds__(128, 2)
void gemm_qkv(QKVArgs a)
{
    extern __shared__ float sm[];
    const int z = blockIdx.z;
    const float* X = (z == 0) ? a.xq : a.xk;
    const float* W = (z == 0) ? a.w0 : (z == 1) ? a.w1 : a.w2;
    const float* B = (z == 0) ? a.b0 : (z == 1) ? a.b1 : a.b2;
    float*       Y = (z == 0) ? a.y0 : (z == 1) ? a.y1 : a.y2;
    gemm_core(X, W, B, Y, 1, sm);
}

__global__ __launch_bounds__(128, 2)
void gemm_tf32(const float* __restrict__ X, const float* __restrict__ W,
               const float* __restrict__ bias, float* __restrict__ Y,
               int head_split)
{
    extern __shared__ float sm[];
    gemm_core(X, W, bias, Y, head_split, sm);
}

// ---------------------------------------------------------------------------
// Flash attention, tf32 mma, register-resident online softmax,
// cp.async PIPELINED K (double-buffered) and V (overlapped) loads.
// Block: 128 threads (4 warps 2x2), tile Sq=64 x Sk=64, d_k=64.
// Dynamic smem (floats): K0@0, K1@4352, V@8704, Ps@13056 (each 64x68),
//   redm@17408 (64x2), reds@17536 (64x2), kmask@17664 (int[2][64]).
// grid = (S/64, NH, B), longest-first.
// cp.async group order per tile t: ... K(t) | V(t), K(t+1) | ...
//   tile start: wait_group 0  -> K(t) landed
//   before PV:  wait_group 1  -> V(t) landed (groups retire in order;
//                                K(t+1) group always committed, possibly empty)
// ---------------------------------------------------------------------------
#define FL_K0   0
#define FL_K1   4352
#define FL_V    8704
#define FL_PS   13056
#define FL_REDM 17408
#define FL_REDS 17536
#define FL_KM   17664
#define FL_SMEM_BYTES ((17664 + 128) * sizeof(float))   // 71168

__global__ __launch_bounds__(128, 3)
void flash_attn_tc(const int* __restrict__ q_mask, const int* __restrict__ k_mask,
                   const int* __restrict__ causal_flag, int causal_default)
{
    extern __shared__ float fsm[];
    float* Ps = fsm + FL_PS;
    float* Vs = fsm + FL_V;
    float (*redm)[2] = (float(*)[2])(fsm + FL_REDM);
    float (*reds)[2] = (float(*)[2])(fsm + FL_REDS);
    int* kmask_s = (int*)(fsm + FL_KM);   // [2][64]

    const int b  = blockIdx.z, h = blockIdx.y;
    const int q0 = ((int)gridDim.x - 1 - (int)blockIdx.x) * 64;  // longest-first
    const int tid = threadIdx.x;
    const int lane = tid & 31, wid = tid >> 5;
    const int wm = wid >> 1;      // 0..1 : q rows [wm*32, +32)
    const int wn = wid & 1;       // 0..1 : k cols / d cols [wn*32, +32)
    const int grp = lane >> 2;    // 0..7
    const int tig = lane & 3;     // 0..3
    const int causal = causal_flag ? causal_flag[0] : causal_default;

    const float* Qb = g_Qh + (((size_t)b * NH + h) * SS) * DKK;
    const float* Kb = g_Kh + (((size_t)b * NH + h) * SS) * DKK;
    const float* Vb = g_Vh + (((size_t)b * NH + h) * SS) * DKK;

    const int ldrow = tid >> 4;   // 0..7  (row stepping by 8 over i)
    const int ldc4  = tid & 15;   // 0..15

    // ---- prologue: prefetch K(0) via cp.async; kmask(0) ----
    #pragma unroll
    for (int i = 0; i < 8; i++) {
        int row = ldrow + i * 8;
        cp16(fsm + FL_K0 + row * 68 + ldc4 * 4, Kb + (size_t)row * DKK + ldc4 * 4);
    }
    cp_commit();   // group: K(0)
    if (tid < 64) kmask_s[tid] = k_mask[(size_t)b * SS + tid];

    // ---- stage Q (tf32 bits) into Ps (overlaps K(0) fetch) ----
    #pragma unroll
    for (int i = 0; i < 8; i++) {
        int row = ldrow + i * 8;
        float4 d = *(const float4*)(Qb + (size_t)(q0 + row) * DKK + ldc4 * 4);
        *(float4*)(Ps + row * 68 + ldc4 * 4) = d;
    }
    __syncthreads();

    // ---- extract Q fragments (already tf32) ----
    uint32_t qf[8][2][4];
    #pragma unroll
    for (int s8 = 0; s8 < 8; s8++) {
        #pragma unroll
        for (int t = 0; t < 2; t++) {
            int r = wm * 32 + t * 16 + grp;
            int cc = s8 * 8 + tig;
            qf[s8][t][0] = __float_as_uint(Ps[r * 68 + cc]);
            qf[s8][t][1] = __float_as_uint(Ps[(r + 8) * 68 + cc]);
            qf[s8][t][2] = __float_as_uint(Ps[r * 68 + cc + 4]);
            qf[s8][t][3] = __float_as_uint(Ps[(r + 8) * 68 + cc + 4]);
        }
    }

    float o[2][4][4];
    #pragma unroll
    for (int t = 0; t < 2; t++)
        #pragma unroll
        for (int u = 0; u < 4; u++)
            #pragma unroll
            for (int r = 0; r < 4; r++) o[t][u][r] = 0.f;

    float m_r[2][2], l_r[2][2];
    #pragma unroll
    for (int t = 0; t < 2; t++)
        #pragma unroll
        for (int hf = 0; hf < 2; hf++) { m_r[t][hf] = -INFINITY; l_r[t][hf] = 0.f; }

    const int nkt = causal ? (q0 >> 6) + 1 : (SS / 64);

    for (int kt = 0; kt < nkt; kt++) {
        const int k0 = kt * 64;
        const float* Kc = fsm + ((kt & 1) ? FL_K1 : FL_K0);
        float*       Kn = fsm + ((kt & 1) ? FL_K0 : FL_K1);
        const int*   kmc = kmask_s + (kt & 1) * 64;

        cp_wait0();        // K(t) landed (V(t-1) drained earlier, in-order retire)
        __syncthreads();   // S1: K(t) visible; Ps (prev P) + Vs (prev V) free

        // ---- issue V(t) -> Vs (overlaps QK + softmax) ----
        #pragma unroll
        for (int i = 0; i < 8; i++) {
            int row = ldrow + i * 8;
            cp16(Vs + row * 68 + ldc4 * 4, Vb + (size_t)(k0 + row) * DKK + ldc4 * 4);
        }
        cp_commit();   // group: V(t)

        // ---- S = Q K^T via mma (from Kc) ----
        float sacc[2][4][4];
        #pragma unroll
        for (int t = 0; t < 2; t++)
            #pragma unroll
            for (int u = 0; u < 4; u++)
                #pragma unroll
                for (int r = 0; r < 4; r++) sacc[t][u][r] = 0.f;

        #pragma unroll
        for (int s8 = 0; s8 < 8; s8++) {
            uint32_t kb[4][2];
            const int cc = s8 * 8 + tig;
            #pragma unroll
            for (int u = 0; u < 4; u++) {
                int n = wn * 32 + u * 8 + grp;
                kb[u][0] = __float_as_uint(Kc[n * 68 + cc]);
                kb[u][1] = __float_as_uint(Kc[n * 68 + cc + 4]);
            }
            #pragma unroll
            for (int t = 0; t < 2; t++)
                #pragma unroll
                for (int u = 0; u < 4; u++)
                    mma_tf32(sacc[t][u], qf[s8][t], kb[u]);
        }

        // ---- scale + masks (registers) ----
        #pragma unroll
        for (int t = 0; t < 2; t++) {
            int rl0 = wm * 32 + t * 16 + grp;
            int qg0 = q0 + rl0, qg1 = qg0 + 8;
            #pragma unroll
            for (int u = 0; u < 4; u++) {
                int cl = wn * 32 + u * 8 + 2 * tig;
                int kg = k0 + cl;
                int km0 = kmc[cl], km1 = kmc[cl + 1];
                float x0 = sacc[t][u][0] * 0.125f;
                float x1 = sacc[t][u][1] * 0.125f;
                float x2 = sacc[t][u][2] * 0.125f;
                float x3 = sacc[t][u][3] * 0.125f;
                if ((causal && kg     > qg0) || km0 == 0) x0 = -INFINITY;
                if ((causal && kg + 1 > qg0) || km1 == 0) x1 = -INFINITY;
                if ((causal && kg     > qg1) || km0 == 0) x2 = -INFINITY;
                if ((causal && kg + 1 > qg1) || km1 == 0) x3 = -INFINITY;
                sacc[t][u][0] = x0; sacc[t][u][1] = x1;
                sacc[t][u][2] = x2; sacc[t][u][3] = x3;
            }
        }

        // ---- row max -> redm ----
        #pragma unroll
        for (int t = 0; t < 2; t++) {
            #pragma unroll
            for (int hf = 0; hf < 2; hf++) {
                float mx = -INFINITY;
                #pragma unroll
                for (int u = 0; u < 4; u++)
                    mx = fmaxf(mx, fmaxf(sacc[t][u][2*hf], sacc[t][u][2*hf + 1]));
                mx = fmaxf(mx, __shfl_xor_sync(0xffffffffu, mx, 1));
                mx = fmaxf(mx, __shfl_xor_sync(0xffffffffu, mx, 2));
                if (tig == 0) redm[wm * 32 + t * 16 + grp + 8 * hf][wn] = mx;
            }
        }

        // ---- prefetch K(t+1) + kmask(t+1) (commit always, maybe empty) ----
        if (kt + 1 < nkt) {
            int k0n = k0 + 64;
            #pragma unroll
            for (int i = 0; i < 8; i++) {
                int row = ldrow + i * 8;
                cp16(Kn + row * 68 + ldc4 * 4, Kb + (size_t)(k0n + row) * DKK + ldc4 * 4);
            }
            if (tid < 64) kmask_s[((kt + 1) & 1) * 64 + tid] = k_mask[(size_t)b * SS + k0n + tid];
        }
        cp_commit();   // group: K(t+1) (empty on last tile)

        __syncthreads();   // S3: redm visible

        // ---- m_new, exp, row sums ----
        float mnew[2][2];
        #pragma unroll
        for (int t = 0; t < 2; t++) {
            #pragma unroll
            for (int hf = 0; hf < 2; hf++) {
                int rl = wm * 32 + t * 16 + grp + 8 * hf;
                float2 mm = *(float2*)&redm[rl][0];
                mnew[t][hf] = fmaxf(m_r[t][hf], fmaxf(mm.x, mm.y));
            }
        }
        float psum[2][2] = {{0.f, 0.f}, {0.f, 0.f}};
        #pragma unroll
        for (int t = 0; t < 2; t++) {
            #pragma unroll
            for (int u = 0; u < 4; u++) {
                float p0 = __expf(sacc[t][u][0] - mnew[t][0]);
                float p1 = __expf(sacc[t][u][1] - mnew[t][0]);
                float p2 = __expf(sacc[t][u][2] - mnew[t][1]);
                float p3 = __expf(sacc[t][u][3] - mnew[t][1]);
                sacc[t][u][0] = p0; sacc[t][u][1] = p1;
                sacc[t][u][2] = p2; sacc[t][u][3] = p3;
                psum[t][0] += p0 + p1;
                psum[t][1] += p2 + p3;
            }
        }
        #pragma unroll
        for (int t = 0; t < 2; t++) {
            #pragma unroll
            for (int hf = 0; hf < 2; hf++) {
                float s = psum[t][hf];
                s += __shfl_xor_sync(0xffffffffu, s, 1);
                s += __shfl_xor_sync(0xffffffffu, s, 2);
                if (tig == 0) reds[wm * 32 + t * 16 + grp + 8 * hf][wn] = s;
            }
        }

        // ---- write P (tf32) to Ps ----
        #pragma unroll
        for (int t = 0; t < 2; t++) {
            int rl0 = wm * 32 + t * 16 + grp;
            #pragma unroll
            for (int u = 0; u < 4; u++) {
                int cl = wn * 32 + u * 8 + 2 * tig;
                float2 lo, hi;
                lo.x = __uint_as_float(f2tf(sacc[t][u][0]));
                lo.y = __uint_as_float(f2tf(sacc[t][u][1]));
                hi.x = __uint_as_float(f2tf(sacc[t][u][2]));
                hi.y = __uint_as_float(f2tf(sacc[t][u][3]));
                *(float2*)(Ps + rl0 * 68 + cl)       = lo;
                *(float2*)(Ps + (rl0 + 8) * 68 + cl) = hi;
            }
        }

        cp_wait1();        // V(t) landed (K(t+1) may still be in flight)
        __syncthreads();   // S4: V, reds, Ps visible

        // ---- l/alpha update + rescale O ----
        float alpha_v[2][2];
        #pragma unroll
        for (int t = 0; t < 2; t++) {
            #pragma unroll
            for (int hf = 0; hf < 2; hf++) {
                int rl = wm * 32 + t * 16 + grp + 8 * hf;
                float2 ss = *(float2*)&reds[rl][0];
                float al = __expf(m_r[t][hf] - mnew[t][hf]);  // NaN iff both -inf (matches ref)
                l_r[t][hf] = l_r[t][hf] * al + ss.x + ss.y;
                m_r[t][hf] = mnew[t][hf];
                alpha_v[t][hf] = al;
            }
        }
        #pragma unroll
        for (int t = 0; t < 2; t++) {
            #pragma unroll
            for (int u = 0; u < 4; u++) {
                o[t][u][0] *= alpha_v[t][0]; o[t][u][1] *= alpha_v[t][0];
                o[t][u][2] *= alpha_v[t][1]; o[t][u][3] *= alpha_v[t][1];
            }
        }

        // ---- O += P @ V via mma ----
        #pragma unroll
        for (int s8 = 0; s8 < 8; s8++) {
            uint32_t pf[2][4];
            uint32_t vb[4][2];
            const int cc = s8 * 8 + tig;
            #pragma unroll
            for (int t = 0; t < 2; t++) {
                int r = wm * 32 + t * 16 + grp;
                pf[t][0] = __float_as_uint(Ps[r * 68 + cc]);
                pf[t][1] = __float_as_uint(Ps[(r + 8) * 68 + cc]);
                pf[t][2] = __float_as_uint(Ps[r * 68 + cc + 4]);
                pf[t][3] = __float_as_uint(Ps[(r + 8) * 68 + cc + 4]);
            }
            #pragma unroll
            for (int u = 0; u < 4; u++) {
                int dcol = wn * 32 + u * 8 + grp;
                int kr = s8 * 8 + tig;
                vb[u][0] = __float_as_uint(Vs[kr * 68 + dcol]);
                vb[u][1] = __float_as_uint(Vs[(kr + 4) * 68 + dcol]);
            }
            #pragma unroll
            for (int t = 0; t < 2; t++)
                #pragma unroll
                for (int u = 0; u < 4; u++)
                    mma_tf32(o[t][u], pf[t], vb[u]);
        }
    }

    // ---- epilogue: normalize, q_mask, write tf32 bits to Oh ----
    #pragma unroll
    for (int t = 0; t < 2; t++) {
        #pragma unroll
        for (int hf = 0; hf < 2; hf++) {
            int rl = wm * 32 + t * 16 + grp + 8 * hf;
            int s_ = q0 + rl;
            int qm = q_mask[(size_t)b * SS + s_];
            float inv_l = 1.f / l_r[t][hf];   // NaN rows propagate (matches ref)
            #pragma unroll
            for (int u = 0; u < 4; u++) {
                int dcol = wn * 32 + u * 8 + 2 * tig;
                float2 ov;
                if (qm == 0) {
                    ov = make_float2(0.f, 0.f);
                } else {
                    ov.x = __uint_as_float(f2tf(o[t][u][hf * 2 + 0] * inv_l));
                    ov.y = __uint_as_float(f2tf(o[t][u][hf * 2 + 1] * inv_l));
                }
                *(float2*)(g_Oh + ((size_t)b * SS + s_) * DM + h * DKK + dcol) = ov;
            }
        }
    }
}

// ---------------------------------------------------------------------------
extern "C" void kernel_launch(void* const* d_in, const int* in_sizes, int n_in,
                              void* d_out, int out_size)
{
    const float* q  = (const float*)d_in[0];
    const float* k  = (const float*)d_in[1];
    const int*   qm = (const int*)  d_in[2];
    const int*   km = (const int*)  d_in[3];
    const float* Wq = (const float*)d_in[4];
    const float* bq = (const float*)d_in[5];
    const float* Wk = (const float*)d_in[6];
    const float* bk = (const float*)d_in[7];
    const float* Wv = (const float*)d_in[8];
    const float* bv = (const float*)d_in[9];
    const float* Wo = (const float*)d_in[10];
    const float* bo = (const float*)d_in[11];
    const int* causal = (n_in >= 13) ? (const int*)d_in[12] : nullptr;

    float *Qh, *Kh, *Vh, *Oh, *qtf, *ktf, *Wtf;
    cudaGetSymbolAddress((void**)&Qh,  g_Qh);
    cudaGetSymbolAddress((void**)&Kh,  g_Kh);
    cudaGetSymbolAddress((void**)&Vh,  g_Vh);
    cudaGetSymbolAddress((void**)&Oh,  g_Oh);
    cudaGetSymbolAddress((void**)&qtf, g_qtf);
    cudaGetSymbolAddress((void**)&ktf, g_ktf);
    cudaGetSymbolAddress((void**)&Wtf, g_Wtf);

    cudaFuncSetAttribute(gemm_qkv, cudaFuncAttributeMaxDynamicSharedMemorySize,
                         (int)GEMM_SMEM_BYTES);
    cudaFuncSetAttribute(gemm_tf32, cudaFuncAttributeMaxDynamicSharedMemorySize,
                         (int)GEMM_SMEM_BYTES);
    cudaFuncSetAttribute(flash_attn_tc, cudaFuncAttributeMaxDynamicSharedMemorySize,
                         (int)FL_SMEM_BYTES);

    // fused pre-pass: fp32 -> tf32 bits for all GEMM inputs (one launch)
    cvt_all<<<(NCVT4 + 255) / 256, 256>>>(q, k, Wq, Wk, Wv, Wo, qtf, ktf, Wtf);

    // fused Q/K/V projections: one launch, 768 blocks
    QKVArgs qa;
    qa.xq = qtf; qa.xk = ktf;
    qa.w0 = Wtf + 0 * DM * DM; qa.w1 = Wtf + 1 * DM * DM; qa.w2 = Wtf + 2 * DM * DM;
    qa.b0 = bq;  qa.b1 = bk;  qa.b2 = bv;
    qa.y0 = Qh;  qa.y1 = Kh;  qa.y2 = Vh;
    dim3 gq(DM / 128, (BB * SS) / 128, 3);   // (8, 32, 3)
    gemm_qkv<<<gq, 128, GEMM_SMEM_BYTES>>>(qa);

    dim3 ga(SS / 64, NH, BB);                // (32, 16, 2)
    flash_attn_tc<<<ga, 128, FL_SMEM_BYTES>>>(qm, km, causal, 1);

    dim3 gg(DM / 128, (BB * SS) / 128);      // (8, 32)
    gemm_tf32<<<gg, 128, GEMM_SMEM_BYTES>>>(Oh, Wtf + 3 * DM * DM, bo, (float*)d_out, 0);
}

// round 11
// speedup vs baseline: 1.5166x; 1.2524x over previous
#include <cuda_runtime.h>
#include <cuda_fp16.h>
#include <math.h>
#include <stdint.h>

#define BB  2
#define SS  2048
#define DM  1024
#define NH  16
#define DKK 64

// Scratch (allocation-free rule: __device__ globals)
__device__ float  g_Qh[BB*NH*SS*DKK];   // [b][h][s][dk] (tf32 bits, for flash)
__device__ float  g_Kh[BB*NH*SS*DKK];
__device__ float  g_Vh[BB*NH*SS*DKK];
__device__ __half g_Ohh[BB*SS*DM];      // [b][s][h*64+dk] (fp16, for out-GEMM)
__device__ __half g_qh[BB*SS*DM];       // pre-converted q (fp16)
__device__ __half g_kh[BB*SS*DM];       // pre-converted k (fp16)
__device__ __half g_Wh[4*DM*DM];        // pre-converted Wq,Wk,Wv,Wo (fp16)

// ---------------------------------------------------------------------------
// helpers
// ---------------------------------------------------------------------------
__device__ __forceinline__ uint32_t f2tf(float x) {
    uint32_t u;
    asm("cvt.rna.tf32.f32 %0, %1;" : "=r"(u) : "f"(x));
    return u;
}

__device__ __forceinline__ void mma_tf32(float c[4], const uint32_t a[4], const uint32_t b[2]) {
    asm volatile(
        "mma.sync.aligned.m16n8k8.row.col.f32.tf32.tf32.f32 "
        "{%0,%1,%2,%3}, {%4,%5,%6,%7}, {%8,%9}, {%0,%1,%2,%3};\n"
        : "+f"(c[0]), "+f"(c[1]), "+f"(c[2]), "+f"(c[3])
        : "r"(a[0]), "r"(a[1]), "r"(a[2]), "r"(a[3]), "r"(b[0]), "r"(b[1]));
}

__device__ __forceinline__ void mma_f16(float c[4], const uint32_t a[4], const uint32_t b[2]) {
    asm volatile(
        "mma.sync.aligned.m16n8k16.row.col.f32.f16.f16.f32 "
        "{%0,%1,%2,%3}, {%4,%5,%6,%7}, {%8,%9}, {%0,%1,%2,%3};\n"
        : "+f"(c[0]), "+f"(c[1]), "+f"(c[2]), "+f"(c[3])
        : "r"(a[0]), "r"(a[1]), "r"(a[2]), "r"(a[3]), "r"(b[0]), "r"(b[1]));
}

__device__ __forceinline__ void cp16(void* dst, const void* src) {
    uint32_t d = (uint32_t)__cvta_generic_to_shared(dst);
    asm volatile("cp.async.cg.shared.global [%0], [%1], 16;" :: "r"(d), "l"(src));
}
__device__ __forceinline__ void cp_commit() { asm volatile("cp.async.commit_group;"); }
__device__ __forceinline__ void cp_wait0()  { asm volatile("cp.async.wait_group 0;"); }
__device__ __forceinline__ void cp_wait1()  { asm volatile("cp.async.wait_group 1;"); }

// ---------------------------------------------------------------------------
// Fused fp32 -> fp16 (RN) pre-pass over q, k, Wq, Wk, Wv, Wo.
// ---------------------------------------------------------------------------
#define NQ4 (BB*SS*DM/4)   // 1048576 float4
#define NW4 (DM*DM/4)      // 262144 float4
#define NCVT4 (2*NQ4 + 4*NW4)

__global__ void cvt_all(const float* __restrict__ q, const float* __restrict__ k,
                        const float* __restrict__ Wq, const float* __restrict__ Wk,
                        const float* __restrict__ Wv, const float* __restrict__ Wo,
                        __half* __restrict__ qh, __half* __restrict__ kh,
                        __half* __restrict__ Wh)
{
    int i = blockIdx.x * blockDim.x + threadIdx.x;
    if (i >= NCVT4) return;
    const float4* src; __half* dsth; int off;
    if (i < NQ4)            { src = (const float4*)q;  dsth = qh; off = i; }
    else if (i < 2 * NQ4)   { src = (const float4*)k;  dsth = kh; off = i - NQ4; }
    else {
        int j = i - 2 * NQ4;
        int w = j / NW4; off = j - w * NW4;
        src = (const float4*)(w == 0 ? Wq : w == 1 ? Wk : w == 2 ? Wv : Wo);
        dsth = Wh + (size_t)w * DM * DM;
    }
    float4 d = src[off];
    __half2 h0 = __floats2half2_rn(d.x, d.y);
    __half2 h1 = __floats2half2_rn(d.z, d.w);
    uint2 e;
    e.x = *(uint32_t*)&h0;
    e.y = *(uint32_t*)&h1;
    ((uint2*)dsth)[off] = e;
}

// ---------------------------------------------------------------------------
// fp16 GEMM core: m16n8k16 mma, cp.async double-buffered.
// Block 128x128, BK=32 halves, 128 threads (4 warps 2x2, warp tile 64x64).
// smem row stride 40 halves (80 B) -> conflict-free fragment loads.
// Y[m][n] = sum_k X[m][k]*W[n][k] + bias[n]
// head_split=1: write tf32 bits (fp32) to [b][h][s][dk]; else fp32 row-major.
// ---------------------------------------------------------------------------
#define HA(buf) ((buf) * 5120)             // halves: 128*40 per tile
#define HB(buf) (10240 + (buf) * 5120)
#define GEMM_SMEM_BYTES (20480 * 2)        // 40960

__device__ __forceinline__ void gemm_core_h(
    const __half* __restrict__ X, const __half* __restrict__ W,
    const float* __restrict__ bias, float* __restrict__ Y,
    int head_split, __half* sm)
{
    const int bm = blockIdx.y * 128;
    const int bn = blockIdx.x * 128;
    const int tid = threadIdx.x;
    const int lane = tid & 31, wid = tid >> 5;
    const int wm = wid >> 1;        // 0..1  (m offset wm*64)
    const int wn = wid & 1;         // 0..1  (n offset wn*64)
    const int grp = lane >> 2;      // 0..7
    const int tig = lane & 3;       // 0..3

    const int ldrow = tid >> 2;     // 0..31
    const int ldc   = tid & 3;      // 0..3  (8 halves each)

    float c[4][8][4];
    #pragma unroll
    for (int t = 0; t < 4; t++)
        #pragma unroll
        for (int u = 0; u < 8; u++)
            #pragma unroll
            for (int r = 0; r < 4; r++) c[t][u][r] = 0.f;

    // prologue: tile 0 (A and B 128x32 halves = 512 cp16 each; 4 per thread)
    #pragma unroll
    for (int i = 0; i < 4; i++) {
        int row = ldrow + i * 32;
        cp16(sm + HA(0) + row * 40 + ldc * 8, X + (size_t)(bm + row) * DM + ldc * 8);
        cp16(sm + HB(0) + row * 40 + ldc * 8, W + (size_t)(bn + row) * DM + ldc * 8);
    }
    cp_commit();

    const int NT = DM / 32;   // 32
    for (int kt = 0; kt < NT; kt++) {
        if (kt + 1 < NT) {
            int k0n = (kt + 1) * 32;
            int bufn = (kt + 1) & 1;
            #pragma unroll
            for (int i = 0; i < 4; i++) {
                int row = ldrow + i * 32;
                cp16(sm + HA(bufn) + row * 40 + ldc * 8, X + (size_t)(bm + row) * DM + k0n + ldc * 8);
                cp16(sm + HB(bufn) + row * 40 + ldc * 8, W + (size_t)(bn + row) * DM + k0n + ldc * 8);
            }
        }
        cp_commit();
        cp_wait1();
        __syncthreads();

        const __half* As = sm + HA(kt & 1);
        const __half* Bs = sm + HB(kt & 1);

        #pragma unroll
        for (int s = 0; s < 2; s++) {        // 2 x k16 per BK=32
            uint32_t a[4][4];
            uint32_t b[8][2];
            const int ck = s * 16 + 2 * tig;
            #pragma unroll
            for (int t = 0; t < 4; t++) {
                int r = wm * 64 + t * 16 + grp;
                a[t][0] = *(const uint32_t*)(As + r * 40 + ck);
                a[t][1] = *(const uint32_t*)(As + (r + 8) * 40 + ck);
                a[t][2] = *(const uint32_t*)(As + r * 40 + ck + 8);
                a[t][3] = *(const uint32_t*)(As + (r + 8) * 40 + ck + 8);
            }
            #pragma unroll
            for (int u = 0; u < 8; u++) {
                int n = wn * 64 + u * 8 + grp;
                b[u][0] = *(const uint32_t*)(Bs + n * 40 + ck);
                b[u][1] = *(const uint32_t*)(Bs + n * 40 + ck + 8);
            }
            #pragma unroll
            for (int t = 0; t < 4; t++)
                #pragma unroll
                for (int u = 0; u < 8; u++)
                    mma_f16(c[t][u], a[t], b[u]);
        }
        __syncthreads();
    }

    // epilogue
    #pragma unroll
    for (int t = 0; t < 4; t++) {
        #pragma unroll
        for (int u = 0; u < 8; u++) {
            int r0  = bm + wm * 64 + t * 16 + grp;
            int col = bn + wn * 64 + u * 8 + 2 * tig;
            float b0 = bias[col], b1 = bias[col + 1];
            #pragma unroll
            for (int half = 0; half < 2; half++) {
                int m = r0 + half * 8;
                float vx = c[t][u][half * 2 + 0] + b0;
                float vy = c[t][u][half * 2 + 1] + b1;
                if (head_split) {
                    float2 o;
                    o.x = __uint_as_float(f2tf(vx));
                    o.y = __uint_as_float(f2tf(vy));
                    int b_ = m >> 11, s_ = m & 2047;
                    int h_ = col >> 6, dk = col & 63;
                    *(float2*)(Y + (((size_t)b_ * NH + h_) * SS + s_) * DKK + dk) = o;
                } else {
                    float2 o = make_float2(vx, vy);
                    *(float2*)(Y + (size_t)m * DM + col) = o;
                }
            }
        }
    }
}

// Fused Q/K/V projection: blockIdx.z selects which projection.
struct QKVArgs {
    const __half *xq, *xk;
    const __half *w0, *w1, *w2;
    const float *b0, *b1, *b2;
    float *y0, *y1, *y2;
};

__global__ __launch_bounds__(128, 2)
void gemm_qkv(QKVArgs a)
{
    extern __shared__ __half smh[];
    const int z = blockIdx.z;
    const __half* X = (z == 0) ? a.xq : a.xk;
    const __half* W = (z == 0) ? a.w0 : (z == 1) ? a.w1 : a.w2;
    const float*  B = (z == 0) ? a.b0 : (z == 1) ? a.b1 : a.b2;
    float*        Y = (z == 0) ? a.y0 : (z == 1) ? a.y1 : a.y2;
    gemm_core_h(X, W, B, Y, 1, smh);
}

__global__ __launch_bounds__(128, 2)
void gemm_h(const __half* __restrict__ X, const __half* __restrict__ W,
            const float* __restrict__ bias, float* __restrict__ Y,
            int head_split)
{
    extern __shared__ __half smh[];
    gemm_core_h(X, W, bias, Y, head_split, smh);
}

// ---------------------------------------------------------------------------
// Flash attention (round-10 proven version: tf32 mma, register softmax,
// cp.async pipelined K double-buffer + V overlap). Epilogue now writes fp16
// into g_Ohh for the fp16 out-GEMM.
// ---------------------------------------------------------------------------
#define FL_K0   0
#define FL_K1   4352
#define FL_V    8704
#define FL_PS   13056
#define FL_REDM 17408
#define FL_REDS 17536
#define FL_KM   17664
#define FL_SMEM_BYTES ((17664 + 128) * sizeof(float))   // 71168

__global__ __launch_bounds__(128, 3)
void flash_attn_tc(const int* __restrict__ q_mask, const int* __restrict__ k_mask,
                   const int* __restrict__ causal_flag, int causal_default)
{
    extern __shared__ float fsm[];
    float* Ps = fsm + FL_PS;
    float* Vs = fsm + FL_V;
    float (*redm)[2] = (float(*)[2])(fsm + FL_REDM);
    float (*reds)[2] = (float(*)[2])(fsm + FL_REDS);
    int* kmask_s = (int*)(fsm + FL_KM);   // [2][64]

    const int b  = blockIdx.z, h = blockIdx.y;
    const int q0 = ((int)gridDim.x - 1 - (int)blockIdx.x) * 64;  // longest-first
    const int tid = threadIdx.x;
    const int lane = tid & 31, wid = tid >> 5;
    const int wm = wid >> 1;
    const int wn = wid & 1;
    const int grp = lane >> 2;
    const int tig = lane & 3;
    const int causal = causal_flag ? causal_flag[0] : causal_default;

    const float* Qb = g_Qh + (((size_t)b * NH + h) * SS) * DKK;
    const float* Kb = g_Kh + (((size_t)b * NH + h) * SS) * DKK;
    const float* Vb = g_Vh + (((size_t)b * NH + h) * SS) * DKK;

    const int ldrow = tid >> 4;   // 0..7
    const int ldc4  = tid & 15;   // 0..15

    // ---- prologue: prefetch K(0); kmask(0) ----
    #pragma unroll
    for (int i = 0; i < 8; i++) {
        int row = ldrow + i * 8;
        cp16(fsm + FL_K0 + row * 68 + ldc4 * 4, Kb + (size_t)row * DKK + ldc4 * 4);
    }
    cp_commit();   // group: K(0)
    if (tid < 64) kmask_s[tid] = k_mask[(size_t)b * SS + tid];

    // ---- stage Q (tf32 bits) into Ps ----
    #pragma unroll
    for (int i = 0; i < 8; i++) {
        int row = ldrow + i * 8;
        float4 d = *(const float4*)(Qb + (size_t)(q0 + row) * DKK + ldc4 * 4);
        *(float4*)(Ps + row * 68 + ldc4 * 4) = d;
    }
    __syncthreads();

    uint32_t qf[8][2][4];
    #pragma unroll
    for (int s8 = 0; s8 < 8; s8++) {
        #pragma unroll
        for (int t = 0; t < 2; t++) {
            int r = wm * 32 + t * 16 + grp;
            int cc = s8 * 8 + tig;
            qf[s8][t][0] = __float_as_uint(Ps[r * 68 + cc]);
            qf[s8][t][1] = __float_as_uint(Ps[(r + 8) * 68 + cc]);
            qf[s8][t][2] = __float_as_uint(Ps[r * 68 + cc + 4]);
            qf[s8][t][3] = __float_as_uint(Ps[(r + 8) * 68 + cc + 4]);
        }
    }

    float o[2][4][4];
    #pragma unroll
    for (int t = 0; t < 2; t++)
        #pragma unroll
        for (int u = 0; u < 4; u++)
            #pragma unroll
            for (int r = 0; r < 4; r++) o[t][u][r] = 0.f;

    float m_r[2][2], l_r[2][2];
    #pragma unroll
    for (int t = 0; t < 2; t++)
        #pragma unroll
        for (int hf = 0; hf < 2; hf++) { m_r[t][hf] = -INFINITY; l_r[t][hf] = 0.f; }

    const int nkt = causal ? (q0 >> 6) + 1 : (SS / 64);

    for (int kt = 0; kt < nkt; kt++) {
        const int k0 = kt * 64;
        const float* Kc = fsm + ((kt & 1) ? FL_K1 : FL_K0);
        float*       Kn = fsm + ((kt & 1) ? FL_K0 : FL_K1);
        const int*   kmc = kmask_s + (kt & 1) * 64;

        cp_wait0();
        __syncthreads();   // S1: K(t) visible; Ps/Vs free

        // ---- issue V(t) ----
        #pragma unroll
        for (int i = 0; i < 8; i++) {
            int row = ldrow + i * 8;
            cp16(Vs + row * 68 + ldc4 * 4, Vb + (size_t)(k0 + row) * DKK + ldc4 * 4);
        }
        cp_commit();   // group: V(t)

        // ---- S = Q K^T ----
        float sacc[2][4][4];
        #pragma unroll
        for (int t = 0; t < 2; t++)
            #pragma unroll
            for (int u = 0; u < 4; u++)
                #pragma unroll
                for (int r = 0; r < 4; r++) sacc[t][u][r] = 0.f;

        #pragma unroll
        for (int s8 = 0; s8 < 8; s8++) {
            uint32_t kb[4][2];
            const int cc = s8 * 8 + tig;
            #pragma unroll
            for (int u = 0; u < 4; u++) {
                int n = wn * 32 + u * 8 + grp;
                kb[u][0] = __float_as_uint(Kc[n * 68 + cc]);
                kb[u][1] = __float_as_uint(Kc[n * 68 + cc + 4]);
            }
            #pragma unroll
            for (int t = 0; t < 2; t++)
                #pragma unroll
                for (int u = 0; u < 4; u++)
                    mma_tf32(sacc[t][u], qf[s8][t], kb[u]);
        }

        // ---- scale + masks ----
        #pragma unroll
        for (int t = 0; t < 2; t++) {
            int rl0 = wm * 32 + t * 16 + grp;
            int qg0 = q0 + rl0, qg1 = qg0 + 8;
            #pragma unroll
            for (int u = 0; u < 4; u++) {
                int cl = wn * 32 + u * 8 + 2 * tig;
                int kg = k0 + cl;
                int km0 = kmc[cl], km1 = kmc[cl + 1];
                float x0 = sacc[t][u][0] * 0.125f;
                float x1 = sacc[t][u][1] * 0.125f;
                float x2 = sacc[t][u][2] * 0.125f;
                float x3 = sacc[t][u][3] * 0.125f;
                if ((causal && kg     > qg0) || km0 == 0) x0 = -INFINITY;
                if ((causal && kg + 1 > qg0) || km1 == 0) x1 = -INFINITY;
                if ((causal && kg     > qg1) || km0 == 0) x2 = -INFINITY;
                if ((causal && kg + 1 > qg1) || km1 == 0) x3 = -INFINITY;
                sacc[t][u][0] = x0; sacc[t][u][1] = x1;
                sacc[t][u][2] = x2; sacc[t][u][3] = x3;
            }
        }

        // ---- row max -> redm ----
        #pragma unroll
        for (int t = 0; t < 2; t++) {
            #pragma unroll
            for (int hf = 0; hf < 2; hf++) {
                float mx = -INFINITY;
                #pragma unroll
                for (int u = 0; u < 4; u++)
                    mx = fmaxf(mx, fmaxf(sacc[t][u][2*hf], sacc[t][u][2*hf + 1]));
                mx = fmaxf(mx, __shfl_xor_sync(0xffffffffu, mx, 1));
                mx = fmaxf(mx, __shfl_xor_sync(0xffffffffu, mx, 2));
                if (tig == 0) redm[wm * 32 + t * 16 + grp + 8 * hf][wn] = mx;
            }
        }

        // ---- prefetch K(t+1) + kmask(t+1) ----
        if (kt + 1 < nkt) {
            int k0n = k0 + 64;
            #pragma unroll
            for (int i = 0; i < 8; i++) {
                int row = ldrow + i * 8;
                cp16(Kn + row * 68 + ldc4 * 4, Kb + (size_t)(k0n + row) * DKK + ldc4 * 4);
            }
            if (tid < 64) kmask_s[((kt + 1) & 1) * 64 + tid] = k_mask[(size_t)b * SS + k0n + tid];
        }
        cp_commit();   // group: K(t+1) (empty on last tile)

        __syncthreads();   // S3: redm visible

        // ---- m_new, exp, row sums ----
        float mnew[2][2];
        #pragma unroll
        for (int t = 0; t < 2; t++) {
            #pragma unroll
            for (int hf = 0; hf < 2; hf++) {
                int rl = wm * 32 + t * 16 + grp + 8 * hf;
                float2 mm = *(float2*)&redm[rl][0];
                mnew[t][hf] = fmaxf(m_r[t][hf], fmaxf(mm.x, mm.y));
            }
        }
        float psum[2][2] = {{0.f, 0.f}, {0.f, 0.f}};
        #pragma unroll
        for (int t = 0; t < 2; t++) {
            #pragma unroll
            for (int u = 0; u < 4; u++) {
                float p0 = __expf(sacc[t][u][0] - mnew[t][0]);
                float p1 = __expf(sacc[t][u][1] - mnew[t][0]);
                float p2 = __expf(sacc[t][u][2] - mnew[t][1]);
                float p3 = __expf(sacc[t][u][3] - mnew[t][1]);
                sacc[t][u][0] = p0; sacc[t][u][1] = p1;
                sacc[t][u][2] = p2; sacc[t][u][3] = p3;
                psum[t][0] += p0 + p1;
                psum[t][1] += p2 + p3;
            }
        }
        #pragma unroll
        for (int t = 0; t < 2; t++) {
            #pragma unroll
            for (int hf = 0; hf < 2; hf++) {
                float s = psum[t][hf];
                s += __shfl_xor_sync(0xffffffffu, s, 1);
                s += __shfl_xor_sync(0xffffffffu, s, 2);
                if (tig == 0) reds[wm * 32 + t * 16 + grp + 8 * hf][wn] = s;
            }
        }

        // ---- write P (tf32) to Ps ----
        #pragma unroll
        for (int t = 0; t < 2; t++) {
            int rl0 = wm * 32 + t * 16 + grp;
            #pragma unroll
            for (int u = 0; u < 4; u++) {
                int cl = wn * 32 + u * 8 + 2 * tig;
                float2 lo, hi;
                lo.x = __uint_as_float(f2tf(sacc[t][u][0]));
                lo.y = __uint_as_float(f2tf(sacc[t][u][1]));
                hi.x = __uint_as_float(f2tf(sacc[t][u][2]));
                hi.y = __uint_as_float(f2tf(sacc[t][u][3]));
                *(float2*)(Ps + rl0 * 68 + cl)       = lo;
                *(float2*)(Ps + (rl0 + 8) * 68 + cl) = hi;
            }
        }

        cp_wait1();        // V(t) landed
        __syncthreads();   // S4: V, reds, Ps visible

        // ---- l/alpha update + rescale O ----
        float alpha_v[2][2];
        #pragma unroll
        for (int t = 0; t < 2; t++) {
            #pragma unroll
            for (int hf = 0; hf < 2; hf++) {
                int rl = wm * 32 + t * 16 + grp + 8 * hf;
                float2 ss = *(float2*)&reds[rl][0];
                float al = __expf(m_r[t][hf] - mnew[t][hf]);  // NaN iff both -inf (matches ref)
                l_r[t][hf] = l_r[t][hf] * al + ss.x + ss.y;
                m_r[t][hf] = mnew[t][hf];
                alpha_v[t][hf] = al;
            }
        }
        #pragma unroll
        for (int t = 0; t < 2; t++) {
            #pragma unroll
            for (int u = 0; u < 4; u++) {
                o[t][u][0] *= alpha_v[t][0]; o[t][u][1] *= alpha_v[t][0];
                o[t][u][2] *= alpha_v[t][1]; o[t][u][3] *= alpha_v[t][1];
            }
        }

        // ---- O += P @ V ----
        #pragma unroll
        for (int s8 = 0; s8 < 8; s8++) {
            uint32_t pf[2][4];
            uint32_t vb[4][2];
            const int cc = s8 * 8 + tig;
            #pragma unroll
            for (int t = 0; t < 2; t++) {
                int r = wm * 32 + t * 16 + grp;
                pf[t][0] = __float_as_uint(Ps[r * 68 + cc]);
                pf[t][1] = __float_as_uint(Ps[(r + 8) * 68 + cc]);
                pf[t][2] = __float_as_uint(Ps[r * 68 + cc + 4]);
                pf[t][3] = __float_as_uint(Ps[(r + 8) * 68 + cc + 4]);
            }
            #pragma unroll
            for (int u = 0; u < 4; u++) {
                int dcol = wn * 32 + u * 8 + grp;
                int kr = s8 * 8 + tig;
                vb[u][0] = __float_as_uint(Vs[kr * 68 + dcol]);
                vb[u][1] = __float_as_uint(Vs[(kr + 4) * 68 + dcol]);
            }
            #pragma unroll
            for (int t = 0; t < 2; t++)
                #pragma unroll
                for (int u = 0; u < 4; u++)
                    mma_tf32(o[t][u], pf[t], vb[u]);
        }
    }

    // ---- epilogue: normalize, q_mask, write fp16 to g_Ohh ----
    #pragma unroll
    for (int t = 0; t < 2; t++) {
        #pragma unroll
        for (int hf = 0; hf < 2; hf++) {
            int rl = wm * 32 + t * 16 + grp + 8 * hf;
            int s_ = q0 + rl;
            int qm = q_mask[(size_t)b * SS + s_];
            float inv_l = 1.f / l_r[t][hf];   // NaN rows propagate (matches ref)
            #pragma unroll
            for (int u = 0; u < 4; u++) {
                int dcol = wn * 32 + u * 8 + 2 * tig;
                __half2 hv;
                if (qm == 0) {
                    hv = __floats2half2_rn(0.f, 0.f);
                } else {
                    hv = __floats2half2_rn(o[t][u][hf * 2 + 0] * inv_l,
                                           o[t][u][hf * 2 + 1] * inv_l);
                }
                *(__half2*)(g_Ohh + ((size_t)b * SS + s_) * DM + h * DKK + dcol) = hv;
            }
        }
    }
}

// ---------------------------------------------------------------------------
extern "C" void kernel_launch(void* const* d_in, const int* in_sizes, int n_in,
                              void* d_out, int out_size)
{
    const float* q  = (const float*)d_in[0];
    const float* k  = (const float*)d_in[1];
    const int*   qm = (const int*)  d_in[2];
    const int*   km = (const int*)  d_in[3];
    const float* Wq = (const float*)d_in[4];
    const float* bq = (const float*)d_in[5];
    const float* Wk = (const float*)d_in[6];
    const float* bk = (const float*)d_in[7];
    const float* Wv = (const float*)d_in[8];
    const float* bv = (const float*)d_in[9];
    const float* Wo = (const float*)d_in[10];
    const float* bo = (const float*)d_in[11];
    const int* causal = (n_in >= 13) ? (const int*)d_in[12] : nullptr;

    float *Qh, *Kh, *Vh;
    __half *Ohh, *qh, *kh, *Wh;
    cudaGetSymbolAddress((void**)&Qh,  g_Qh);
    cudaGetSymbolAddress((void**)&Kh,  g_Kh);
    cudaGetSymbolAddress((void**)&Vh,  g_Vh);
    cudaGetSymbolAddress((void**)&Ohh, g_Ohh);
    cudaGetSymbolAddress((void**)&qh,  g_qh);
    cudaGetSymbolAddress((void**)&kh,  g_kh);
    cudaGetSymbolAddress((void**)&Wh,  g_Wh);

    cudaFuncSetAttribute(gemm_qkv, cudaFuncAttributeMaxDynamicSharedMemorySize,
                         (int)GEMM_SMEM_BYTES);
    cudaFuncSetAttribute(gemm_h, cudaFuncAttributeMaxDynamicSharedMemorySize,
                         (int)GEMM_SMEM_BYTES);
    cudaFuncSetAttribute(flash_attn_tc, cudaFuncAttributeMaxDynamicSharedMemorySize,
                         (int)FL_SMEM_BYTES);

    // fused pre-pass: fp32 -> fp16 for all GEMM inputs (one launch)
    cvt_all<<<(NCVT4 + 255) / 256, 256>>>(q, k, Wq, Wk, Wv, Wo, qh, kh, Wh);

    // fused Q/K/V projections: one launch, 768 blocks
    QKVArgs qa;
    qa.xq = qh; qa.xk = kh;
    qa.w0 = Wh + 0 * (size_t)DM * DM; qa.w1 = Wh + 1 * (size_t)DM * DM; qa.w2 = Wh + 2 * (size_t)DM * DM;
    qa.b0 = bq;  qa.b1 = bk;  qa.b2 = bv;
    qa.y0 = Qh;  qa.y1 = Kh;  qa.y2 = Vh;
    dim3 gq(DM / 128, (BB * SS) / 128, 3);   // (8, 32, 3)
    gemm_qkv<<<gq, 128, GEMM_SMEM_BYTES>>>(qa);

    dim3 ga(SS / 64, NH, BB);                // (32, 16, 2)
    flash_attn_tc<<<ga, 128, FL_SMEM_BYTES>>>(qm, km, causal, 1);

    dim3 gg(DM / 128, (BB * SS) / 128);      // (8, 32)
    gemm_h<<<gg, 128, GEMM_SMEM_BYTES>>>(Ohh, Wh + 3 * (size_t)DM * DM, bo, (float*)d_out, 0);
}

// round 12
// speedup vs baseline: 1.9473x; 1.2840x over previous
#include <cuda_runtime.h>
#include <cuda_fp16.h>
#include <math.h>
#include <stdint.h>

#define BB  2
#define SS  2048
#define DM  1024
#define NH  16
#define DKK 64

// Scratch (allocation-free rule: __device__ globals)
__device__ __half g_Qh[BB*NH*SS*DKK];   // [b][h][s][dk] fp16
__device__ __half g_Kh[BB*NH*SS*DKK];   // [b][h][s][dk] fp16
__device__ __half g_Vt[BB*NH*DKK*SS];   // [b][h][dk][s] fp16 (TRANSPOSED)
__device__ __half g_Ohh[BB*SS*DM];      // [b][s][h*64+dk] fp16
__device__ __half g_qh[BB*SS*DM];       // pre-converted q (fp16)
__device__ __half g_kh[BB*SS*DM];       // pre-converted k (fp16)
__device__ __half g_Wh[4*DM*DM];        // pre-converted Wq,Wk,Wv,Wo (fp16)

// ---------------------------------------------------------------------------
// helpers
// ---------------------------------------------------------------------------
__device__ __forceinline__ void mma_f16(float c[4], const uint32_t a[4], const uint32_t b[2]) {
    asm volatile(
        "mma.sync.aligned.m16n8k16.row.col.f32.f16.f16.f32 "
        "{%0,%1,%2,%3}, {%4,%5,%6,%7}, {%8,%9}, {%0,%1,%2,%3};\n"
        : "+f"(c[0]), "+f"(c[1]), "+f"(c[2]), "+f"(c[3])
        : "r"(a[0]), "r"(a[1]), "r"(a[2]), "r"(a[3]), "r"(b[0]), "r"(b[1]));
}

__device__ __forceinline__ void cp16(void* dst, const void* src) {
    uint32_t d = (uint32_t)__cvta_generic_to_shared(dst);
    asm volatile("cp.async.cg.shared.global [%0], [%1], 16;" :: "r"(d), "l"(src));
}
__device__ __forceinline__ void cp_commit() { asm volatile("cp.async.commit_group;"); }
__device__ __forceinline__ void cp_wait0()  { asm volatile("cp.async.wait_group 0;"); }
__device__ __forceinline__ void cp_wait1()  { asm volatile("cp.async.wait_group 1;"); }

// ---------------------------------------------------------------------------
// Fused fp32 -> fp16 (RN) pre-pass over q, k, Wq, Wk, Wv, Wo.
// ---------------------------------------------------------------------------
#define NQ4 (BB*SS*DM/4)   // 1048576 float4
#define NW4 (DM*DM/4)      // 262144 float4
#define NCVT4 (2*NQ4 + 4*NW4)

__global__ void cvt_all(const float* __restrict__ q, const float* __restrict__ k,
                        const float* __restrict__ Wq, const float* __restrict__ Wk,
                        const float* __restrict__ Wv, const float* __restrict__ Wo,
                        __half* __restrict__ qh, __half* __restrict__ kh,
                        __half* __restrict__ Wh)
{
    int i = blockIdx.x * blockDim.x + threadIdx.x;
    if (i >= NCVT4) return;
    const float4* src; __half* dsth; int off;
    if (i < NQ4)            { src = (const float4*)q;  dsth = qh; off = i; }
    else if (i < 2 * NQ4)   { src = (const float4*)k;  dsth = kh; off = i - NQ4; }
    else {
        int j = i - 2 * NQ4;
        int w = j / NW4; off = j - w * NW4;
        src = (const float4*)(w == 0 ? Wq : w == 1 ? Wk : w == 2 ? Wv : Wo);
        dsth = Wh + (size_t)w * DM * DM;
    }
    float4 d = src[off];
    __half2 h0 = __floats2half2_rn(d.x, d.y);
    __half2 h1 = __floats2half2_rn(d.z, d.w);
    uint2 e;
    e.x = *(uint32_t*)&h0;
    e.y = *(uint32_t*)&h1;
    ((uint2*)dsth)[off] = e;
}

// ---------------------------------------------------------------------------
// fp16 GEMM core: m16n8k16 mma, cp.async double-buffered.
// Block 128x128, BK=32 halves, 128 threads (4 warps 2x2, warp tile 64x64).
// mode 0: fp32 row-major to Yf.
// mode 1: fp16 head-split [b][h][s][dk] to Yh.
// mode 2: fp16 head-split TRANSPOSED [b][h][dk][s] to Yh.
// ---------------------------------------------------------------------------
#define HA(buf) ((buf) * 5120)             // halves: 128*40 per tile
#define HB(buf) (10240 + (buf) * 5120)
#define GEMM_SMEM_BYTES (20480 * 2)        // 40960

__device__ __forceinline__ void gemm_core_h(
    const __half* __restrict__ X, const __half* __restrict__ W,
    const float* __restrict__ bias, float* __restrict__ Yf,
    __half* __restrict__ Yh, int mode, __half* sm)
{
    const int bm = blockIdx.y * 128;
    const int bn = blockIdx.x * 128;
    const int tid = threadIdx.x;
    const int lane = tid & 31, wid = tid >> 5;
    const int wm = wid >> 1;
    const int wn = wid & 1;
    const int grp = lane >> 2;
    const int tig = lane & 3;

    const int ldrow = tid >> 2;     // 0..31
    const int ldc   = tid & 3;      // 0..3

    float c[4][8][4];
    #pragma unroll
    for (int t = 0; t < 4; t++)
        #pragma unroll
        for (int u = 0; u < 8; u++)
            #pragma unroll
            for (int r = 0; r < 4; r++) c[t][u][r] = 0.f;

    #pragma unroll
    for (int i = 0; i < 4; i++) {
        int row = ldrow + i * 32;
        cp16(sm + HA(0) + row * 40 + ldc * 8, X + (size_t)(bm + row) * DM + ldc * 8);
        cp16(sm + HB(0) + row * 40 + ldc * 8, W + (size_t)(bn + row) * DM + ldc * 8);
    }
    cp_commit();

    const int NT = DM / 32;   // 32
    for (int kt = 0; kt < NT; kt++) {
        if (kt + 1 < NT) {
            int k0n = (kt + 1) * 32;
            int bufn = (kt + 1) & 1;
            #pragma unroll
            for (int i = 0; i < 4; i++) {
                int row = ldrow + i * 32;
                cp16(sm + HA(bufn) + row * 40 + ldc * 8, X + (size_t)(bm + row) * DM + k0n + ldc * 8);
                cp16(sm + HB(bufn) + row * 40 + ldc * 8, W + (size_t)(bn + row) * DM + k0n + ldc * 8);
            }
        }
        cp_commit();
        cp_wait1();
        __syncthreads();

        const __half* As = sm + HA(kt & 1);
        const __half* Bs = sm + HB(kt & 1);

        #pragma unroll
        for (int s = 0; s < 2; s++) {
            uint32_t a[4][4];
            uint32_t b[8][2];
            const int ck = s * 16 + 2 * tig;
            #pragma unroll
            for (int t = 0; t < 4; t++) {
                int r = wm * 64 + t * 16 + grp;
                a[t][0] = *(const uint32_t*)(As + r * 40 + ck);
                a[t][1] = *(const uint32_t*)(As + (r + 8) * 40 + ck);
                a[t][2] = *(const uint32_t*)(As + r * 40 + ck + 8);
                a[t][3] = *(const uint32_t*)(As + (r + 8) * 40 + ck + 8);
            }
            #pragma unroll
            for (int u = 0; u < 8; u++) {
                int n = wn * 64 + u * 8 + grp;
                b[u][0] = *(const uint32_t*)(Bs + n * 40 + ck);
                b[u][1] = *(const uint32_t*)(Bs + n * 40 + ck + 8);
            }
            #pragma unroll
            for (int t = 0; t < 4; t++)
                #pragma unroll
                for (int u = 0; u < 8; u++)
                    mma_f16(c[t][u], a[t], b[u]);
        }
        __syncthreads();
    }

    #pragma unroll
    for (int t = 0; t < 4; t++) {
        #pragma unroll
        for (int u = 0; u < 8; u++) {
            int r0  = bm + wm * 64 + t * 16 + grp;
            int col = bn + wn * 64 + u * 8 + 2 * tig;
            float b0 = bias[col], b1 = bias[col + 1];
            #pragma unroll
            for (int half = 0; half < 2; half++) {
                int m = r0 + half * 8;
                float vx = c[t][u][half * 2 + 0] + b0;
                float vy = c[t][u][half * 2 + 1] + b1;
                int b_ = m >> 11, s_ = m & 2047;
                int h_ = col >> 6, dk = col & 63;
                if (mode == 1) {
                    __half2 hv = __floats2half2_rn(vx, vy);
                    *(__half2*)(Yh + (((size_t)b_ * NH + h_) * SS + s_) * DKK + dk) = hv;
                } else if (mode == 2) {
                    size_t base = ((size_t)b_ * NH + h_) * DKK;
                    Yh[(base + dk)     * SS + s_] = __float2half_rn(vx);
                    Yh[(base + dk + 1) * SS + s_] = __float2half_rn(vy);
                } else {
                    *(float2*)(Yf + (size_t)m * DM + col) = make_float2(vx, vy);
                }
            }
        }
    }
}

// Fused Q/K/V projection: blockIdx.z selects which projection.
struct QKVArgs {
    const __half *xq, *xk;
    const __half *w0, *w1, *w2;
    const float *b0, *b1, *b2;
    __half *y0, *y1, *y2;   // y0,y1: head-split; y2: transposed
};

__global__ __launch_bounds__(128, 2)
void gemm_qkv(QKVArgs a)
{
    extern __shared__ __half smh[];
    const int z = blockIdx.z;
    const __half* X = (z == 0) ? a.xq : a.xk;
    const __half* W = (z == 0) ? a.w0 : (z == 1) ? a.w1 : a.w2;
    const float*  B = (z == 0) ? a.b0 : (z == 1) ? a.b1 : a.b2;
    __half*       Y = (z == 0) ? a.y0 : (z == 1) ? a.y1 : a.y2;
    gemm_core_h(X, W, B, nullptr, Y, (z == 2) ? 2 : 1, smh);
}

__global__ __launch_bounds__(128, 2)
void gemm_h(const __half* __restrict__ X, const __half* __restrict__ W,
            const float* __restrict__ bias, float* __restrict__ Y)
{
    extern __shared__ __half smh[];
    gemm_core_h(X, W, bias, Y, nullptr, 0, smh);
}

// ---------------------------------------------------------------------------
// Flash attention, FP16 m16n8k16 mma, register-resident fp32 online softmax,
// cp.async pipelined K double-buffer + V overlap. V pre-transposed in gmem.
// Block: 128 threads (4 warps 2x2), tile Sq=64 x Sk=64, d_k=64.
// smem halves (stride 72): K0@0, K1@4608, Vt@9216, Ps(Q->P)@13824 (64x72 each)
// then floats: redm@9216f, reds@9344f, kmask@9472f. Total 9600 floats = 38400 B.
// grid = (S/64, NH, B), longest-first.
// ---------------------------------------------------------------------------
#define FLH_K0 0
#define FLH_K1 4608
#define FLH_V  9216
#define FLH_PS 13824
#define FL_SMEM_BYTES (9600 * 4)

__global__ __launch_bounds__(128, 3)
void flash_attn_h(const int* __restrict__ q_mask, const int* __restrict__ k_mask,
                  const int* __restrict__ causal_flag, int causal_default)
{
    extern __shared__ float fsm[];
    __half* hsm = (__half*)fsm;
    __half* Vts = hsm + FLH_V;
    __half* Ps  = hsm + FLH_PS;
    float (*redm)[2] = (float(*)[2])(fsm + 9216);
    float (*reds)[2] = (float(*)[2])(fsm + 9344);
    int* kmask_s = (int*)(fsm + 9472);   // [2][64]

    const int b  = blockIdx.z, h = blockIdx.y;
    const int q0 = ((int)gridDim.x - 1 - (int)blockIdx.x) * 64;  // longest-first
    const int tid = threadIdx.x;
    const int lane = tid & 31, wid = tid >> 5;
    const int wm = wid >> 1;      // 0..1 : q rows [wm*32, +32)
    const int wn = wid & 1;       // 0..1 : k cols / d cols [wn*32, +32)
    const int grp = lane >> 2;    // 0..7
    const int tig = lane & 3;     // 0..3
    const int causal = causal_flag ? causal_flag[0] : causal_default;

    const __half* Qb  = g_Qh + (((size_t)b * NH + h) * SS) * DKK;
    const __half* Kb  = g_Kh + (((size_t)b * NH + h) * SS) * DKK;
    const __half* Vtb = g_Vt + (((size_t)b * NH + h) * DKK) * SS;

    const int ldrow = tid >> 3;   // 0..15
    const int ldc   = tid & 7;    // 0..7  (8 halves = 16B each)

    // ---- prologue: cp.async K(0) + Q (one group); kmask(0) ----
    #pragma unroll
    for (int i = 0; i < 4; i++) {
        int row = ldrow + i * 16;
        cp16(hsm + FLH_K0 + row * 72 + ldc * 8, Kb + (size_t)row * DKK + ldc * 8);
        cp16(Ps + row * 72 + ldc * 8, Qb + (size_t)(q0 + row) * DKK + ldc * 8);
    }
    cp_commit();   // group: K(0)+Q
    if (tid < 64) kmask_s[tid] = k_mask[(size_t)b * SS + tid];
    cp_wait0();
    __syncthreads();

    // ---- extract Q fragments (fp16, 4 k16 steps) ----
    uint32_t qf[4][2][4];
    #pragma unroll
    for (int s16 = 0; s16 < 4; s16++) {
        const int ck = s16 * 16 + 2 * tig;
        #pragma unroll
        for (int t = 0; t < 2; t++) {
            int r = wm * 32 + t * 16 + grp;
            qf[s16][t][0] = *(const uint32_t*)(Ps + r * 72 + ck);
            qf[s16][t][1] = *(const uint32_t*)(Ps + (r + 8) * 72 + ck);
            qf[s16][t][2] = *(const uint32_t*)(Ps + r * 72 + ck + 8);
            qf[s16][t][3] = *(const uint32_t*)(Ps + (r + 8) * 72 + ck + 8);
        }
    }

    float o[2][4][4];
    #pragma unroll
    for (int t = 0; t < 2; t++)
        #pragma unroll
        for (int u = 0; u < 4; u++)
            #pragma unroll
            for (int r = 0; r < 4; r++) o[t][u][r] = 0.f;

    float m_r[2][2], l_r[2][2];
    #pragma unroll
    for (int t = 0; t < 2; t++)
        #pragma unroll
        for (int hf = 0; hf < 2; hf++) { m_r[t][hf] = -INFINITY; l_r[t][hf] = 0.f; }

    const int nkt = causal ? (q0 >> 6) + 1 : (SS / 64);

    for (int kt = 0; kt < nkt; kt++) {
        const int k0 = kt * 64;
        const __half* Kc = hsm + ((kt & 1) ? FLH_K1 : FLH_K0);
        __half*       Kn = hsm + ((kt & 1) ? FLH_K0 : FLH_K1);
        const int*   kmc = kmask_s + (kt & 1) * 64;

        cp_wait0();        // K(t) landed
        __syncthreads();   // S1: K(t) visible; Ps (prev P) + Vts (prev V) free

        // ---- issue V(t): rows = dk 0..63, cols = keys k0..k0+63 ----
        #pragma unroll
        for (int i = 0; i < 4; i++) {
            int row = ldrow + i * 16;
            cp16(Vts + row * 72 + ldc * 8, Vtb + (size_t)row * SS + k0 + ldc * 8);
        }
        cp_commit();   // group: V(t)

        // ---- S = Q K^T via fp16 mma ----
        float sacc[2][4][4];
        #pragma unroll
        for (int t = 0; t < 2; t++)
            #pragma unroll
            for (int u = 0; u < 4; u++)
                #pragma unroll
                for (int r = 0; r < 4; r++) sacc[t][u][r] = 0.f;

        #pragma unroll
        for (int s16 = 0; s16 < 4; s16++) {
            uint32_t kb[4][2];
            const int ck = s16 * 16 + 2 * tig;
            #pragma unroll
            for (int u = 0; u < 4; u++) {
                int n = wn * 32 + u * 8 + grp;
                kb[u][0] = *(const uint32_t*)(Kc + n * 72 + ck);
                kb[u][1] = *(const uint32_t*)(Kc + n * 72 + ck + 8);
            }
            #pragma unroll
            for (int t = 0; t < 2; t++)
                #pragma unroll
                for (int u = 0; u < 4; u++)
                    mma_f16(sacc[t][u], qf[s16][t], kb[u]);
        }

        // ---- scale + masks (fp32 registers) ----
        #pragma unroll
        for (int t = 0; t < 2; t++) {
            int rl0 = wm * 32 + t * 16 + grp;
            int qg0 = q0 + rl0, qg1 = qg0 + 8;
            #pragma unroll
            for (int u = 0; u < 4; u++) {
                int cl = wn * 32 + u * 8 + 2 * tig;
                int kg = k0 + cl;
                int km0 = kmc[cl], km1 = kmc[cl + 1];
                float x0 = sacc[t][u][0] * 0.125f;
                float x1 = sacc[t][u][1] * 0.125f;
                float x2 = sacc[t][u][2] * 0.125f;
                float x3 = sacc[t][u][3] * 0.125f;
                if ((causal && kg     > qg0) || km0 == 0) x0 = -INFINITY;
                if ((causal && kg + 1 > qg0) || km1 == 0) x1 = -INFINITY;
                if ((causal && kg     > qg1) || km0 == 0) x2 = -INFINITY;
                if ((causal && kg + 1 > qg1) || km1 == 0) x3 = -INFINITY;
                sacc[t][u][0] = x0; sacc[t][u][1] = x1;
                sacc[t][u][2] = x2; sacc[t][u][3] = x3;
            }
        }

        // ---- row max -> redm ----
        #pragma unroll
        for (int t = 0; t < 2; t++) {
            #pragma unroll
            for (int hf = 0; hf < 2; hf++) {
                float mx = -INFINITY;
                #pragma unroll
                for (int u = 0; u < 4; u++)
                    mx = fmaxf(mx, fmaxf(sacc[t][u][2*hf], sacc[t][u][2*hf + 1]));
                mx = fmaxf(mx, __shfl_xor_sync(0xffffffffu, mx, 1));
                mx = fmaxf(mx, __shfl_xor_sync(0xffffffffu, mx, 2));
                if (tig == 0) redm[wm * 32 + t * 16 + grp + 8 * hf][wn] = mx;
            }
        }

        // ---- prefetch K(t+1) + kmask(t+1) (commit always, maybe empty) ----
        if (kt + 1 < nkt) {
            int k0n = k0 + 64;
            #pragma unroll
            for (int i = 0; i < 4; i++) {
                int row = ldrow + i * 16;
                cp16(Kn + row * 72 + ldc * 8, Kb + (size_t)(k0n + row) * DKK + ldc * 8);
            }
            if (tid < 64) kmask_s[((kt + 1) & 1) * 64 + tid] = k_mask[(size_t)b * SS + k0n + tid];
        }
        cp_commit();   // group: K(t+1)

        __syncthreads();   // S3: redm visible

        // ---- m_new, exp, row sums; write P (fp16) to Ps ----
        float mnew[2][2];
        #pragma unroll
        for (int t = 0; t < 2; t++) {
            #pragma unroll
            for (int hf = 0; hf < 2; hf++) {
                int rl = wm * 32 + t * 16 + grp + 8 * hf;
                float2 mm = *(float2*)&redm[rl][0];
                mnew[t][hf] = fmaxf(m_r[t][hf], fmaxf(mm.x, mm.y));
            }
        }
        float psum[2][2] = {{0.f, 0.f}, {0.f, 0.f}};
        #pragma unroll
        for (int t = 0; t < 2; t++) {
            int rl0 = wm * 32 + t * 16 + grp;
            #pragma unroll
            for (int u = 0; u < 4; u++) {
                int cl = wn * 32 + u * 8 + 2 * tig;
                float p0 = __expf(sacc[t][u][0] - mnew[t][0]);
                float p1 = __expf(sacc[t][u][1] - mnew[t][0]);
                float p2 = __expf(sacc[t][u][2] - mnew[t][1]);
                float p3 = __expf(sacc[t][u][3] - mnew[t][1]);
                psum[t][0] += p0 + p1;
                psum[t][1] += p2 + p3;
                *(__half2*)(Ps + rl0 * 72 + cl)       = __floats2half2_rn(p0, p1);
                *(__half2*)(Ps + (rl0 + 8) * 72 + cl) = __floats2half2_rn(p2, p3);
            }
        }
        #pragma unroll
        for (int t = 0; t < 2; t++) {
            #pragma unroll
            for (int hf = 0; hf < 2; hf++) {
                float s = psum[t][hf];
                s += __shfl_xor_sync(0xffffffffu, s, 1);
                s += __shfl_xor_sync(0xffffffffu, s, 2);
                if (tig == 0) reds[wm * 32 + t * 16 + grp + 8 * hf][wn] = s;
            }
        }

        cp_wait1();        // V(t) landed (K(t+1) may still be in flight)
        __syncthreads();   // S4: V, reds, Ps visible

        // ---- l/alpha update + rescale O ----
        float alpha_v[2][2];
        #pragma unroll
        for (int t = 0; t < 2; t++) {
            #pragma unroll
            for (int hf = 0; hf < 2; hf++) {
                int rl = wm * 32 + t * 16 + grp + 8 * hf;
                float2 ss = *(float2*)&reds[rl][0];
                float al = __expf(m_r[t][hf] - mnew[t][hf]);  // NaN iff both -inf (matches ref)
                l_r[t][hf] = l_r[t][hf] * al + ss.x + ss.y;
                m_r[t][hf] = mnew[t][hf];
                alpha_v[t][hf] = al;
            }
        }
        #pragma unroll
        for (int t = 0; t < 2; t++) {
            #pragma unroll
            for (int u = 0; u < 4; u++) {
                o[t][u][0] *= alpha_v[t][0]; o[t][u][1] *= alpha_v[t][0];
                o[t][u][2] *= alpha_v[t][1]; o[t][u][3] *= alpha_v[t][1];
            }
        }

        // ---- O += P @ V via fp16 mma (V transposed: B K-major, same as K) ----
        #pragma unroll
        for (int s16 = 0; s16 < 4; s16++) {
            uint32_t pf[2][4];
            uint32_t vb[4][2];
            const int ck = s16 * 16 + 2 * tig;
            #pragma unroll
            for (int t = 0; t < 2; t++) {
                int r = wm * 32 + t * 16 + grp;
                pf[t][0] = *(const uint32_t*)(Ps + r * 72 + ck);
                pf[t][1] = *(const uint32_t*)(Ps + (r + 8) * 72 + ck);
                pf[t][2] = *(const uint32_t*)(Ps + r * 72 + ck + 8);
                pf[t][3] = *(const uint32_t*)(Ps + (r + 8) * 72 + ck + 8);
            }
            #pragma unroll
            for (int u = 0; u < 4; u++) {
                int n = wn * 32 + u * 8 + grp;   // dcol
                vb[u][0] = *(const uint32_t*)(Vts + n * 72 + ck);
                vb[u][1] = *(const uint32_t*)(Vts + n * 72 + ck + 8);
            }
            #pragma unroll
            for (int t = 0; t < 2; t++)
                #pragma unroll
                for (int u = 0; u < 4; u++)
                    mma_f16(o[t][u], pf[t], vb[u]);
        }
    }

    // ---- epilogue: normalize, q_mask, write fp16 to g_Ohh ----
    #pragma unroll
    for (int t = 0; t < 2; t++) {
        #pragma unroll
        for (int hf = 0; hf < 2; hf++) {
            int rl = wm * 32 + t * 16 + grp + 8 * hf;
            int s_ = q0 + rl;
            int qm = q_mask[(size_t)b * SS + s_];
            float inv_l = 1.f / l_r[t][hf];   // NaN rows propagate (matches ref)
            #pragma unroll
            for (int u = 0; u < 4; u++) {
                int dcol = wn * 32 + u * 8 + 2 * tig;
                __half2 hv;
                if (qm == 0) {
                    hv = __floats2half2_rn(0.f, 0.f);
                } else {
                    hv = __floats2half2_rn(o[t][u][hf * 2 + 0] * inv_l,
                                           o[t][u][hf * 2 + 1] * inv_l);
                }
                *(__half2*)(g_Ohh + ((size_t)b * SS + s_) * DM + h * DKK + dcol) = hv;
            }
        }
    }
}

// ---------------------------------------------------------------------------
extern "C" void kernel_launch(void* const* d_in, const int* in_sizes, int n_in,
                              void* d_out, int out_size)
{
    const float* q  = (const float*)d_in[0];
    const float* k  = (const float*)d_in[1];
    const int*   qm = (const int*)  d_in[2];
    const int*   km = (const int*)  d_in[3];
    const float* Wq = (const float*)d_in[4];
    const float* bq = (const float*)d_in[5];
    const float* Wk = (const float*)d_in[6];
    const float* bk = (const float*)d_in[7];
    const float* Wv = (const float*)d_in[8];
    const float* bv = (const float*)d_in[9];
    const float* Wo = (const float*)d_in[10];
    const float* bo = (const float*)d_in[11];
    const int* causal = (n_in >= 13) ? (const int*)d_in[12] : nullptr;

    __half *Qh, *Kh, *Vt, *Ohh, *qh, *kh, *Wh;
    cudaGetSymbolAddress((void**)&Qh,  g_Qh);
    cudaGetSymbolAddress((void**)&Kh,  g_Kh);
    cudaGetSymbolAddress((void**)&Vt,  g_Vt);
    cudaGetSymbolAddress((void**)&Ohh, g_Ohh);
    cudaGetSymbolAddress((void**)&qh,  g_qh);
    cudaGetSymbolAddress((void**)&kh,  g_kh);
    cudaGetSymbolAddress((void**)&Wh,  g_Wh);

    cudaFuncSetAttribute(gemm_qkv, cudaFuncAttributeMaxDynamicSharedMemorySize,
                         (int)GEMM_SMEM_BYTES);
    cudaFuncSetAttribute(gemm_h, cudaFuncAttributeMaxDynamicSharedMemorySize,
                         (int)GEMM_SMEM_BYTES);
    cudaFuncSetAttribute(flash_attn_h, cudaFuncAttributeMaxDynamicSharedMemorySize,
                         (int)FL_SMEM_BYTES);

    // fused pre-pass: fp32 -> fp16 for all GEMM inputs (one launch)
    cvt_all<<<(NCVT4 + 255) / 256, 256>>>(q, k, Wq, Wk, Wv, Wo, qh, kh, Wh);

    // fused Q/K/V projections: one launch, 768 blocks (V written transposed)
    QKVArgs qa;
    qa.xq = qh; qa.xk = kh;
    qa.w0 = Wh + 0 * (size_t)DM * DM; qa.w1 = Wh + 1 * (size_t)DM * DM; qa.w2 = Wh + 2 * (size_t)DM * DM;
    qa.b0 = bq;  qa.b1 = bk;  qa.b2 = bv;
    qa.y0 = Qh;  qa.y1 = Kh;  qa.y2 = Vt;
    dim3 gq(DM / 128, (BB * SS) / 128, 3);   // (8, 32, 3)
    gemm_qkv<<<gq, 128, GEMM_SMEM_BYTES>>>(qa);

    dim3 ga(SS / 64, NH, BB);                // (32, 16, 2)
    flash_attn_h<<<ga, 128, FL_SMEM_BYTES>>>(qm, km, causal, 1);

    dim3 gg(DM / 128, (BB * SS) / 128);      // (8, 32)
    gemm_h<<<gg, 128, GEMM_SMEM_BYTES>>>(Ohh, Wh + 3 * (size_t)DM * DM, bo, (float*)d_out);
}

// round 13
// speedup vs baseline: 2.1430x; 1.1005x over previous
#include <cuda_runtime.h>
#include <cuda_fp16.h>
#include <math.h>
#include <stdint.h>

#define BB  2
#define SS  2048
#define DM  1024
#define NH  16
#define DKK 64

// Scratch (allocation-free rule: __device__ globals)
__device__ __half g_Qh[BB*NH*SS*DKK];   // [b][h][s][dk] fp16
__device__ __half g_Kh[BB*NH*SS*DKK];   // [b][h][s][dk] fp16
__device__ __half g_Vt[BB*NH*DKK*SS];   // [b][h][dk][s] fp16 (TRANSPOSED)
__device__ __half g_Ohh[BB*SS*DM];      // [b][s][h*64+dk] fp16
__device__ __half g_qh[BB*SS*DM];       // pre-converted q (fp16)
__device__ __half g_kh[BB*SS*DM];       // pre-converted k (fp16)
__device__ __half g_Wh[4*DM*DM];        // pre-converted Wq,Wk,Wv,Wo (fp16)

// ---------------------------------------------------------------------------
// helpers
// ---------------------------------------------------------------------------
__device__ __forceinline__ void mma_f16(float c[4], const uint32_t a[4], const uint32_t b[2]) {
    asm volatile(
        "mma.sync.aligned.m16n8k16.row.col.f32.f16.f16.f32 "
        "{%0,%1,%2,%3}, {%4,%5,%6,%7}, {%8,%9}, {%0,%1,%2,%3};\n"
        : "+f"(c[0]), "+f"(c[1]), "+f"(c[2]), "+f"(c[3])
        : "r"(a[0]), "r"(a[1]), "r"(a[2]), "r"(a[3]), "r"(b[0]), "r"(b[1]));
}

__device__ __forceinline__ void ldsm_x4(uint32_t r[4], uint32_t saddr) {
    asm volatile("ldmatrix.sync.aligned.m8n8.x4.shared.b16 {%0,%1,%2,%3}, [%4];"
        : "=r"(r[0]), "=r"(r[1]), "=r"(r[2]), "=r"(r[3]) : "r"(saddr));
}

__device__ __forceinline__ float ex2f(float x) {
    float y;
    asm("ex2.approx.f32 %0, %1;" : "=f"(y) : "f"(x));
    return y;
}

__device__ __forceinline__ void cp16(void* dst, const void* src) {
    uint32_t d = (uint32_t)__cvta_generic_to_shared(dst);
    asm volatile("cp.async.cg.shared.global [%0], [%1], 16;" :: "r"(d), "l"(src));
}
__device__ __forceinline__ void cp_commit() { asm volatile("cp.async.commit_group;"); }
__device__ __forceinline__ void cp_wait0()  { asm volatile("cp.async.wait_group 0;"); }
__device__ __forceinline__ void cp_wait1()  { asm volatile("cp.async.wait_group 1;"); }

// 0.125 * log2(e)
#define SC_LOG2E 0.18033688f

// ---------------------------------------------------------------------------
// Fused fp32 -> fp16 (RN) pre-pass over q, k, Wq, Wk, Wv, Wo.
// ---------------------------------------------------------------------------
#define NQ4 (BB*SS*DM/4)   // 1048576 float4
#define NW4 (DM*DM/4)      // 262144 float4
#define NCVT4 (2*NQ4 + 4*NW4)

__global__ void cvt_all(const float* __restrict__ q, const float* __restrict__ k,
                        const float* __restrict__ Wq, const float* __restrict__ Wk,
                        const float* __restrict__ Wv, const float* __restrict__ Wo,
                        __half* __restrict__ qh, __half* __restrict__ kh,
                        __half* __restrict__ Wh)
{
    int i = blockIdx.x * blockDim.x + threadIdx.x;
    if (i >= NCVT4) return;
    const float4* src; __half* dsth; int off;
    if (i < NQ4)            { src = (const float4*)q;  dsth = qh; off = i; }
    else if (i < 2 * NQ4)   { src = (const float4*)k;  dsth = kh; off = i - NQ4; }
    else {
        int j = i - 2 * NQ4;
        int w = j / NW4; off = j - w * NW4;
        src = (const float4*)(w == 0 ? Wq : w == 1 ? Wk : w == 2 ? Wv : Wo);
        dsth = Wh + (size_t)w * DM * DM;
    }
    float4 d = src[off];
    __half2 h0 = __floats2half2_rn(d.x, d.y);
    __half2 h1 = __floats2half2_rn(d.z, d.w);
    uint2 e;
    e.x = *(uint32_t*)&h0;
    e.y = *(uint32_t*)&h1;
    ((uint2*)dsth)[off] = e;
}

// ---------------------------------------------------------------------------
// fp16 GEMM core: m16n8k16 mma, cp.async double-buffered, ldmatrix fragments.
// Block 128x128, BK=32 halves, 128 threads (4 warps 2x2, warp tile 64x64).
// mode 0: fp32 row-major; mode 1: fp16 head-split; mode 2: fp16 transposed.
// ---------------------------------------------------------------------------
#define HA(buf) ((buf) * 5120)             // halves: 128*40 per tile
#define HB(buf) (10240 + (buf) * 5120)
#define GEMM_SMEM_BYTES (20480 * 2)        // 40960

__device__ __forceinline__ void gemm_core_h(
    const __half* __restrict__ X, const __half* __restrict__ W,
    const float* __restrict__ bias, float* __restrict__ Yf,
    __half* __restrict__ Yh, int mode, __half* sm)
{
    const int bm = blockIdx.y * 128;
    const int bn = blockIdx.x * 128;
    const int tid = threadIdx.x;
    const int lane = tid & 31, wid = tid >> 5;
    const int wm = wid >> 1;
    const int wn = wid & 1;
    const int grp = lane >> 2;
    const int tig = lane & 3;

    // ldmatrix per-lane address components
    const int l15 = lane & 15;          // A: row within 16
    const int lh8 = (lane >> 4) * 8;    // A: col tile select / B: row tile select
    const int l7  = lane & 7;           // B: row within 8
    const int l38 = ((lane >> 3) & 1) * 8;  // B: col tile select

    const int ldrow = tid >> 2;     // 0..31
    const int ldc   = tid & 3;      // 0..3

    float c[4][8][4];
    #pragma unroll
    for (int t = 0; t < 4; t++)
        #pragma unroll
        for (int u = 0; u < 8; u++)
            #pragma unroll
            for (int r = 0; r < 4; r++) c[t][u][r] = 0.f;

    #pragma unroll
    for (int i = 0; i < 4; i++) {
        int row = ldrow + i * 32;
        cp16(sm + HA(0) + row * 40 + ldc * 8, X + (size_t)(bm + row) * DM + ldc * 8);
        cp16(sm + HB(0) + row * 40 + ldc * 8, W + (size_t)(bn + row) * DM + ldc * 8);
    }
    cp_commit();

    const int NT = DM / 32;   // 32
    for (int kt = 0; kt < NT; kt++) {
        if (kt + 1 < NT) {
            int k0n = (kt + 1) * 32;
            int bufn = (kt + 1) & 1;
            #pragma unroll
            for (int i = 0; i < 4; i++) {
                int row = ldrow + i * 32;
                cp16(sm + HA(bufn) + row * 40 + ldc * 8, X + (size_t)(bm + row) * DM + k0n + ldc * 8);
                cp16(sm + HB(bufn) + row * 40 + ldc * 8, W + (size_t)(bn + row) * DM + k0n + ldc * 8);
            }
        }
        cp_commit();
        cp_wait1();
        __syncthreads();

        const uint32_t As_b = (uint32_t)__cvta_generic_to_shared(sm + HA(kt & 1));
        const uint32_t Bs_b = (uint32_t)__cvta_generic_to_shared(sm + HB(kt & 1));

        #pragma unroll
        for (int s = 0; s < 2; s++) {
            const int ck = s * 16;
            uint32_t a[4][4];
            uint32_t b[8][2];
            #pragma unroll
            for (int t = 0; t < 4; t++)
                ldsm_x4(a[t], As_b + 2u * ((wm * 64 + t * 16 + l15) * 40 + ck + lh8));
            #pragma unroll
            for (int up = 0; up < 4; up++) {
                uint32_t tmp[4];
                ldsm_x4(tmp, Bs_b + 2u * ((wn * 64 + up * 16 + lh8 + l7) * 40 + ck + l38));
                b[2*up][0] = tmp[0]; b[2*up][1] = tmp[1];
                b[2*up+1][0] = tmp[2]; b[2*up+1][1] = tmp[3];
            }
            #pragma unroll
            for (int t = 0; t < 4; t++)
                #pragma unroll
                for (int u = 0; u < 8; u++)
                    mma_f16(c[t][u], a[t], b[u]);
        }
        __syncthreads();
    }

    #pragma unroll
    for (int t = 0; t < 4; t++) {
        #pragma unroll
        for (int u = 0; u < 8; u++) {
            int r0  = bm + wm * 64 + t * 16 + grp;
            int col = bn + wn * 64 + u * 8 + 2 * tig;
            float b0 = bias[col], b1 = bias[col + 1];
            #pragma unroll
            for (int half = 0; half < 2; half++) {
                int m = r0 + half * 8;
                float vx = c[t][u][half * 2 + 0] + b0;
                float vy = c[t][u][half * 2 + 1] + b1;
                int b_ = m >> 11, s_ = m & 2047;
                int h_ = col >> 6, dk = col & 63;
                if (mode == 1) {
                    __half2 hv = __floats2half2_rn(vx, vy);
                    *(__half2*)(Yh + (((size_t)b_ * NH + h_) * SS + s_) * DKK + dk) = hv;
                } else if (mode == 2) {
                    size_t base = ((size_t)b_ * NH + h_) * DKK;
                    Yh[(base + dk)     * SS + s_] = __float2half_rn(vx);
                    Yh[(base + dk + 1) * SS + s_] = __float2half_rn(vy);
                } else {
                    *(float2*)(Yf + (size_t)m * DM + col) = make_float2(vx, vy);
                }
            }
        }
    }
}

// Fused Q/K/V projection: blockIdx.z selects which projection.
struct QKVArgs {
    const __half *xq, *xk;
    const __half *w0, *w1, *w2;
    const float *b0, *b1, *b2;
    __half *y0, *y1, *y2;   // y0,y1: head-split; y2: transposed
};

__global__ __launch_bounds__(128, 2)
void gemm_qkv(QKVArgs a)
{
    extern __shared__ __half smh[];
    const int z = blockIdx.z;
    const __half* X = (z == 0) ? a.xq : a.xk;
    const __half* W = (z == 0) ? a.w0 : (z == 1) ? a.w1 : a.w2;
    const float*  B = (z == 0) ? a.b0 : (z == 1) ? a.b1 : a.b2;
    __half*       Y = (z == 0) ? a.y0 : (z == 1) ? a.y1 : a.y2;
    gemm_core_h(X, W, B, nullptr, Y, (z == 2) ? 2 : 1, smh);
}

__global__ __launch_bounds__(128, 2)
void gemm_h(const __half* __restrict__ X, const __half* __restrict__ W,
            const float* __restrict__ bias, float* __restrict__ Y)
{
    extern __shared__ __half smh[];
    gemm_core_h(X, W, bias, Y, nullptr, 0, smh);
}

// ---------------------------------------------------------------------------
// Flash attention, FP16 mma, ldmatrix fragments, additive kmask bias,
// diagonal-only causal, pre-scaled ex2 softmax (fp32 register stats),
// cp.async pipelined K double-buffer + V overlap. V pre-transposed.
// Block: 128 threads (4 warps 2x2), tile Sq=64 x Sk=64, d_k=64.
// smem halves (stride 72): K0@0, K1@4608, Vt@9216, Ps(Q->P)@13824;
// floats: redm@9216f, reds@9344f, kbias@9472f ([2][64]). 9600 floats.
// ---------------------------------------------------------------------------
#define FLH_K0 0
#define FLH_K1 4608
#define FLH_V  9216
#define FLH_PS 13824
#define FL_SMEM_BYTES (9600 * 4)

__global__ __launch_bounds__(128, 3)
void flash_attn_h(const int* __restrict__ q_mask, const int* __restrict__ k_mask,
                  const int* __restrict__ causal_flag, int causal_default)
{
    extern __shared__ float fsm[];
    __half* hsm = (__half*)fsm;
    __half* Vts = hsm + FLH_V;
    __half* Ps  = hsm + FLH_PS;
    float (*redm)[2] = (float(*)[2])(fsm + 9216);
    float (*reds)[2] = (float(*)[2])(fsm + 9344);
    float* kbias = fsm + 9472;   // [2][64]

    const int b  = blockIdx.z, h = blockIdx.y;
    const int q0 = ((int)gridDim.x - 1 - (int)blockIdx.x) * 64;  // longest-first
    const int tid = threadIdx.x;
    const int lane = tid & 31, wid = tid >> 5;
    const int wm = wid >> 1;
    const int wn = wid & 1;
    const int grp = lane >> 2;
    const int tig = lane & 3;
    const int causal = causal_flag ? causal_flag[0] : causal_default;

    const int l15 = lane & 15;
    const int lh8 = (lane >> 4) * 8;
    const int l7  = lane & 7;
    const int l38 = ((lane >> 3) & 1) * 8;

    const __half* Qb  = g_Qh + (((size_t)b * NH + h) * SS) * DKK;
    const __half* Kb  = g_Kh + (((size_t)b * NH + h) * SS) * DKK;
    const __half* Vtb = g_Vt + (((size_t)b * NH + h) * DKK) * SS;

    const int ldrow = tid >> 3;   // 0..15
    const int ldc   = tid & 7;    // 0..7

    // ---- prologue: cp.async K(0) + Q (one group); kbias(0) ----
    #pragma unroll
    for (int i = 0; i < 4; i++) {
        int row = ldrow + i * 16;
        cp16(hsm + FLH_K0 + row * 72 + ldc * 8, Kb + (size_t)row * DKK + ldc * 8);
        cp16(Ps + row * 72 + ldc * 8, Qb + (size_t)(q0 + row) * DKK + ldc * 8);
    }
    cp_commit();   // group: K(0)+Q
    if (tid < 64) kbias[tid] = k_mask[(size_t)b * SS + tid] ? 0.f : -INFINITY;
    cp_wait0();
    __syncthreads();

    // ---- extract Q fragments via ldmatrix ----
    const uint32_t Ps_b = (uint32_t)__cvta_generic_to_shared(Ps);
    uint32_t qf[4][2][4];
    #pragma unroll
    for (int s16 = 0; s16 < 4; s16++) {
        const int ck = s16 * 16;
        #pragma unroll
        for (int t = 0; t < 2; t++)
            ldsm_x4(qf[s16][t], Ps_b + 2u * ((wm * 32 + t * 16 + l15) * 72 + ck + lh8));
    }

    float o[2][4][4];
    #pragma unroll
    for (int t = 0; t < 2; t++)
        #pragma unroll
        for (int u = 0; u < 4; u++)
            #pragma unroll
            for (int r = 0; r < 4; r++) o[t][u][r] = 0.f;

    float m_r[2][2], l_r[2][2];
    #pragma unroll
    for (int t = 0; t < 2; t++)
        #pragma unroll
        for (int hf = 0; hf < 2; hf++) { m_r[t][hf] = -INFINITY; l_r[t][hf] = 0.f; }

    const int nkt = causal ? (q0 >> 6) + 1 : (SS / 64);
    const uint32_t Vts_b = (uint32_t)__cvta_generic_to_shared(Vts);

    for (int kt = 0; kt < nkt; kt++) {
        const int k0 = kt * 64;
        const __half* KcP = hsm + ((kt & 1) ? FLH_K1 : FLH_K0);
        __half*       Kn  = hsm + ((kt & 1) ? FLH_K0 : FLH_K1);
        const float*  kbc = kbias + (kt & 1) * 64;
        const bool diag = causal && (kt == nkt - 1);

        cp_wait0();        // K(t) landed
        __syncthreads();   // S1: K(t) visible; Ps (prev P) + Vts (prev V) free

        // ---- issue V(t) ----
        #pragma unroll
        for (int i = 0; i < 4; i++) {
            int row = ldrow + i * 16;
            cp16(Vts + row * 72 + ldc * 8, Vtb + (size_t)row * SS + k0 + ldc * 8);
        }
        cp_commit();   // group: V(t)

        // ---- S = Q K^T via fp16 mma (ldmatrix B) ----
        const uint32_t Kc_b = (uint32_t)__cvta_generic_to_shared(KcP);
        float sacc[2][4][4];
        #pragma unroll
        for (int t = 0; t < 2; t++)
            #pragma unroll
            for (int u = 0; u < 4; u++)
                #pragma unroll
                for (int r = 0; r < 4; r++) sacc[t][u][r] = 0.f;

        #pragma unroll
        for (int s16 = 0; s16 < 4; s16++) {
            const int ck = s16 * 16;
            uint32_t kb[4][2];
            #pragma unroll
            for (int up = 0; up < 2; up++) {
                uint32_t tmp[4];
                ldsm_x4(tmp, Kc_b + 2u * ((wn * 32 + up * 16 + lh8 + l7) * 72 + ck + l38));
                kb[2*up][0] = tmp[0]; kb[2*up][1] = tmp[1];
                kb[2*up+1][0] = tmp[2]; kb[2*up+1][1] = tmp[3];
            }
            #pragma unroll
            for (int t = 0; t < 2; t++)
                #pragma unroll
                for (int u = 0; u < 4; u++)
                    mma_f16(sacc[t][u], qf[s16][t], kb[u]);
        }

        // ---- scale(log2-domain) + additive kmask; causal only on diagonal ----
        #pragma unroll
        for (int t = 0; t < 2; t++) {
            int rl0 = wm * 32 + t * 16 + grp;
            #pragma unroll
            for (int u = 0; u < 4; u++) {
                int cl = wn * 32 + u * 8 + 2 * tig;
                float kb0 = kbc[cl], kb1 = kbc[cl + 1];
                float x0 = fmaf(sacc[t][u][0], SC_LOG2E, kb0);
                float x1 = fmaf(sacc[t][u][1], SC_LOG2E, kb1);
                float x2 = fmaf(sacc[t][u][2], SC_LOG2E, kb0);
                float x3 = fmaf(sacc[t][u][3], SC_LOG2E, kb1);
                if (diag) {
                    int qg0 = q0 + rl0, qg1 = qg0 + 8;
                    int kg = k0 + cl;
                    if (kg     > qg0) x0 = -INFINITY;
                    if (kg + 1 > qg0) x1 = -INFINITY;
                    if (kg     > qg1) x2 = -INFINITY;
                    if (kg + 1 > qg1) x3 = -INFINITY;
                }
                sacc[t][u][0] = x0; sacc[t][u][1] = x1;
                sacc[t][u][2] = x2; sacc[t][u][3] = x3;
            }
        }

        // ---- row max -> redm ----
        #pragma unroll
        for (int t = 0; t < 2; t++) {
            #pragma unroll
            for (int hf = 0; hf < 2; hf++) {
                float mx = -INFINITY;
                #pragma unroll
                for (int u = 0; u < 4; u++)
                    mx = fmaxf(mx, fmaxf(sacc[t][u][2*hf], sacc[t][u][2*hf + 1]));
                mx = fmaxf(mx, __shfl_xor_sync(0xffffffffu, mx, 1));
                mx = fmaxf(mx, __shfl_xor_sync(0xffffffffu, mx, 2));
                if (tig == 0) redm[wm * 32 + t * 16 + grp + 8 * hf][wn] = mx;
            }
        }

        // ---- prefetch K(t+1) + kbias(t+1) (commit always, maybe empty) ----
        if (kt + 1 < nkt) {
            int k0n = k0 + 64;
            #pragma unroll
            for (int i = 0; i < 4; i++) {
                int row = ldrow + i * 16;
                cp16(Kn + row * 72 + ldc * 8, Kb + (size_t)(k0n + row) * DKK + ldc * 8);
            }
            if (tid < 64)
                kbias[((kt + 1) & 1) * 64 + tid] = k_mask[(size_t)b * SS + k0n + tid] ? 0.f : -INFINITY;
        }
        cp_commit();   // group: K(t+1)

        __syncthreads();   // S3: redm visible

        // ---- m_new, ex2, row sums; write P (fp16) to Ps ----
        float mnew[2][2];
        #pragma unroll
        for (int t = 0; t < 2; t++) {
            #pragma unroll
            for (int hf = 0; hf < 2; hf++) {
                int rl = wm * 32 + t * 16 + grp + 8 * hf;
                float2 mm = *(float2*)&redm[rl][0];
                mnew[t][hf] = fmaxf(m_r[t][hf], fmaxf(mm.x, mm.y));
            }
        }
        float psum[2][2] = {{0.f, 0.f}, {0.f, 0.f}};
        #pragma unroll
        for (int t = 0; t < 2; t++) {
            int rl0 = wm * 32 + t * 16 + grp;
            #pragma unroll
            for (int u = 0; u < 4; u++) {
                int cl = wn * 32 + u * 8 + 2 * tig;
                float p0 = ex2f(sacc[t][u][0] - mnew[t][0]);
                float p1 = ex2f(sacc[t][u][1] - mnew[t][0]);
                float p2 = ex2f(sacc[t][u][2] - mnew[t][1]);
                float p3 = ex2f(sacc[t][u][3] - mnew[t][1]);
                psum[t][0] += p0 + p1;
                psum[t][1] += p2 + p3;
                *(__half2*)(Ps + rl0 * 72 + cl)       = __floats2half2_rn(p0, p1);
                *(__half2*)(Ps + (rl0 + 8) * 72 + cl) = __floats2half2_rn(p2, p3);
            }
        }
        #pragma unroll
        for (int t = 0; t < 2; t++) {
            #pragma unroll
            for (int hf = 0; hf < 2; hf++) {
                float s = psum[t][hf];
                s += __shfl_xor_sync(0xffffffffu, s, 1);
                s += __shfl_xor_sync(0xffffffffu, s, 2);
                if (tig == 0) reds[wm * 32 + t * 16 + grp + 8 * hf][wn] = s;
            }
        }

        cp_wait1();        // V(t) landed (K(t+1) may still be in flight)
        __syncthreads();   // S4: V, reds, Ps visible

        // ---- l/alpha update + rescale O ----
        float alpha_v[2][2];
        #pragma unroll
        for (int t = 0; t < 2; t++) {
            #pragma unroll
            for (int hf = 0; hf < 2; hf++) {
                int rl = wm * 32 + t * 16 + grp + 8 * hf;
                float2 ss = *(float2*)&reds[rl][0];
                float al = ex2f(m_r[t][hf] - mnew[t][hf]);  // NaN iff both -inf (matches ref)
                l_r[t][hf] = l_r[t][hf] * al + ss.x + ss.y;
                m_r[t][hf] = mnew[t][hf];
                alpha_v[t][hf] = al;
            }
        }
        #pragma unroll
        for (int t = 0; t < 2; t++) {
            #pragma unroll
            for (int u = 0; u < 4; u++) {
                o[t][u][0] *= alpha_v[t][0]; o[t][u][1] *= alpha_v[t][0];
                o[t][u][2] *= alpha_v[t][1]; o[t][u][3] *= alpha_v[t][1];
            }
        }

        // ---- O += P @ V via fp16 mma (ldmatrix P and V) ----
        #pragma unroll
        for (int s16 = 0; s16 < 4; s16++) {
            const int ck = s16 * 16;
            uint32_t pf[2][4];
            uint32_t vb[4][2];
            #pragma unroll
            for (int t = 0; t < 2; t++)
                ldsm_x4(pf[t], Ps_b + 2u * ((wm * 32 + t * 16 + l15) * 72 + ck + lh8));
            #pragma unroll
            for (int up = 0; up < 2; up++) {
                uint32_t tmp[4];
                ldsm_x4(tmp, Vts_b + 2u * ((wn * 32 + up * 16 + lh8 + l7) * 72 + ck + l38));
                vb[2*up][0] = tmp[0]; vb[2*up][1] = tmp[1];
                vb[2*up+1][0] = tmp[2]; vb[2*up+1][1] = tmp[3];
            }
            #pragma unroll
            for (int t = 0; t < 2; t++)
                #pragma unroll
                for (int u = 0; u < 4; u++)
                    mma_f16(o[t][u], pf[t], vb[u]);
        }
    }

    // ---- epilogue: normalize, q_mask, write fp16 to g_Ohh ----
    #pragma unroll
    for (int t = 0; t < 2; t++) {
        #pragma unroll
        for (int hf = 0; hf < 2; hf++) {
            int rl = wm * 32 + t * 16 + grp + 8 * hf;
            int s_ = q0 + rl;
            int qm = q_mask[(size_t)b * SS + s_];
            float inv_l = 1.f / l_r[t][hf];   // NaN rows propagate (matches ref)
            #pragma unroll
            for (int u = 0; u < 4; u++) {
                int dcol = wn * 32 + u * 8 + 2 * tig;
                __half2 hv;
                if (qm == 0) {
                    hv = __floats2half2_rn(0.f, 0.f);
                } else {
                    hv = __floats2half2_rn(o[t][u][hf * 2 + 0] * inv_l,
                                           o[t][u][hf * 2 + 1] * inv_l);
                }
                *(__half2*)(g_Ohh + ((size_t)b * SS + s_) * DM + h * DKK + dcol) = hv;
            }
        }
    }
}

// ---------------------------------------------------------------------------
extern "C" void kernel_launch(void* const* d_in, const int* in_sizes, int n_in,
                              void* d_out, int out_size)
{
    const float* q  = (const float*)d_in[0];
    const float* k  = (const float*)d_in[1];
    const int*   qm = (const int*)  d_in[2];
    const int*   km = (const int*)  d_in[3];
    const float* Wq = (const float*)d_in[4];
    const float* bq = (const float*)d_in[5];
    const float* Wk = (const float*)d_in[6];
    const float* bk = (const float*)d_in[7];
    const float* Wv = (const float*)d_in[8];
    const float* bv = (const float*)d_in[9];
    const float* Wo = (const float*)d_in[10];
    const float* bo = (const float*)d_in[11];
    const int* causal = (n_in >= 13) ? (const int*)d_in[12] : nullptr;

    __half *Qh, *Kh, *Vt, *Ohh, *qh, *kh, *Wh;
    cudaGetSymbolAddress((void**)&Qh,  g_Qh);
    cudaGetSymbolAddress((void**)&Kh,  g_Kh);
    cudaGetSymbolAddress((void**)&Vt,  g_Vt);
    cudaGetSymbolAddress((void**)&Ohh, g_Ohh);
    cudaGetSymbolAddress((void**)&qh,  g_qh);
    cudaGetSymbolAddress((void**)&kh,  g_kh);
    cudaGetSymbolAddress((void**)&Wh,  g_Wh);

    cudaFuncSetAttribute(gemm_qkv, cudaFuncAttributeMaxDynamicSharedMemorySize,
                         (int)GEMM_SMEM_BYTES);
    cudaFuncSetAttribute(gemm_h, cudaFuncAttributeMaxDynamicSharedMemorySize,
                         (int)GEMM_SMEM_BYTES);
    cudaFuncSetAttribute(flash_attn_h, cudaFuncAttributeMaxDynamicSharedMemorySize,
                         (int)FL_SMEM_BYTES);

    // fused pre-pass: fp32 -> fp16 for all GEMM inputs (one launch)
    cvt_all<<<(NCVT4 + 255) / 256, 256>>>(q, k, Wq, Wk, Wv, Wo, qh, kh, Wh);

    // fused Q/K/V projections: one launch, 768 blocks (V written transposed)
    QKVArgs qa;
    qa.xq = qh; qa.xk = kh;
    qa.w0 = Wh + 0 * (size_t)DM * DM; qa.w1 = Wh + 1 * (size_t)DM * DM; qa.w2 = Wh + 2 * (size_t)DM * DM;
    qa.b0 = bq;  qa.b1 = bk;  qa.b2 = bv;
    qa.y0 = Qh;  qa.y1 = Kh;  qa.y2 = Vt;
    dim3 gq(DM / 128, (BB * SS) / 128, 3);   // (8, 32, 3)
    gemm_qkv<<<gq, 128, GEMM_SMEM_BYTES>>>(qa);

    dim3 ga(SS / 64, NH, BB);                // (32, 16, 2)
    flash_attn_h<<<ga, 128, FL_SMEM_BYTES>>>(qm, km, causal, 1);

    dim3 gg(DM / 128, (BB * SS) / 128);      // (8, 32)
    gemm_h<<<gg, 128, GEMM_SMEM_BYTES>>>(Ohh, Wh + 3 * (size_t)DM * DM, bo, (float*)d_out);
}

// round 14
// speedup vs baseline: 2.2772x; 1.0627x over previous
#include <cuda_runtime.h>
#include <cuda_fp16.h>
#include <math.h>
#include <stdint.h>

#define BB  2
#define SS  2048
#define DM  1024
#define NH  16
#define DKK 64

// Scratch (allocation-free rule: __device__ globals)
__device__ __half g_Qh[BB*NH*SS*DKK];   // [b][h][s][dk] fp16
__device__ __half g_Kh[BB*NH*SS*DKK];   // [b][h][s][dk] fp16
__device__ __half g_Vt[BB*NH*DKK*SS];   // [b][h][dk][s] fp16 (TRANSPOSED)
__device__ __half g_Ohh[BB*SS*DM];      // [b][s][h*64+dk] fp16
__device__ __half g_qh[BB*SS*DM];       // pre-converted q (fp16)
__device__ __half g_kh[BB*SS*DM];       // pre-converted k (fp16)
__device__ __half g_Wh[4*DM*DM];        // pre-converted Wq,Wk,Wv,Wo (fp16)

// ---------------------------------------------------------------------------
// helpers
// ---------------------------------------------------------------------------
__device__ __forceinline__ void mma_f16(float c[4], const uint32_t a[4], const uint32_t b[2]) {
    asm volatile(
        "mma.sync.aligned.m16n8k16.row.col.f32.f16.f16.f32 "
        "{%0,%1,%2,%3}, {%4,%5,%6,%7}, {%8,%9}, {%0,%1,%2,%3};\n"
        : "+f"(c[0]), "+f"(c[1]), "+f"(c[2]), "+f"(c[3])
        : "r"(a[0]), "r"(a[1]), "r"(a[2]), "r"(a[3]), "r"(b[0]), "r"(b[1]));
}

__device__ __forceinline__ void ldsm_x4(uint32_t r[4], uint32_t saddr) {
    asm volatile("ldmatrix.sync.aligned.m8n8.x4.shared.b16 {%0,%1,%2,%3}, [%4];"
        : "=r"(r[0]), "=r"(r[1]), "=r"(r[2]), "=r"(r[3]) : "r"(saddr));
}

__device__ __forceinline__ float ex2f(float x) {
    float y;
    asm("ex2.approx.f32 %0, %1;" : "=f"(y) : "f"(x));
    return y;
}

__device__ __forceinline__ void cp16(void* dst, const void* src) {
    uint32_t d = (uint32_t)__cvta_generic_to_shared(dst);
    asm volatile("cp.async.cg.shared.global [%0], [%1], 16;" :: "r"(d), "l"(src));
}
__device__ __forceinline__ void cp_commit() { asm volatile("cp.async.commit_group;"); }
__device__ __forceinline__ void cp_wait0()  { asm volatile("cp.async.wait_group 0;"); }
__device__ __forceinline__ void cp_wait1()  { asm volatile("cp.async.wait_group 1;"); }

// 0.125 * log2(e)
#define SC_LOG2E 0.18033688f

// ---------------------------------------------------------------------------
// Fused fp32 -> fp16 (RN) pre-pass over q, k, Wq, Wk, Wv, Wo.
// ---------------------------------------------------------------------------
#define NQ4 (BB*SS*DM/4)   // 1048576 float4
#define NW4 (DM*DM/4)      // 262144 float4
#define NCVT4 (2*NQ4 + 4*NW4)

__global__ void cvt_all(const float* __restrict__ q, const float* __restrict__ k,
                        const float* __restrict__ Wq, const float* __restrict__ Wk,
                        const float* __restrict__ Wv, const float* __restrict__ Wo,
                        __half* __restrict__ qh, __half* __restrict__ kh,
                        __half* __restrict__ Wh)
{
    int i = blockIdx.x * blockDim.x + threadIdx.x;
    if (i >= NCVT4) return;
    const float4* src; __half* dsth; int off;
    if (i < NQ4)            { src = (const float4*)q;  dsth = qh; off = i; }
    else if (i < 2 * NQ4)   { src = (const float4*)k;  dsth = kh; off = i - NQ4; }
    else {
        int j = i - 2 * NQ4;
        int w = j / NW4; off = j - w * NW4;
        src = (const float4*)(w == 0 ? Wq : w == 1 ? Wk : w == 2 ? Wv : Wo);
        dsth = Wh + (size_t)w * DM * DM;
    }
    float4 d = src[off];
    __half2 h0 = __floats2half2_rn(d.x, d.y);
    __half2 h1 = __floats2half2_rn(d.z, d.w);
    uint2 e;
    e.x = *(uint32_t*)&h0;
    e.y = *(uint32_t*)&h1;
    ((uint2*)dsth)[off] = e;
}

// ---------------------------------------------------------------------------
// fp16 GEMM core: m16n8k16 mma, cp.async double-buffered, BK=64,
// SINGLE sync per k-tile (wait -> sync -> prefetch other buf -> compute).
// Block 128x128, 128 threads (4 warps 2x2, warp tile 64x64), ldmatrix frags.
// smem stride 72 halves (proven conflict-free in flash kernel).
// mode 0: fp32 row-major; mode 1: fp16 head-split; mode 2: fp16 transposed.
// ---------------------------------------------------------------------------
#define HA(buf) ((buf) * 9216)              // halves: 128*72 per tile
#define HB(buf) (18432 + (buf) * 9216)
#define GEMM_SMEM_BYTES (36864 * 2)         // 73728

__device__ __forceinline__ void gemm_core_h(
    const __half* __restrict__ X, const __half* __restrict__ W,
    const float* __restrict__ bias, float* __restrict__ Yf,
    __half* __restrict__ Yh, int mode, __half* sm)
{
    const int bm = blockIdx.y * 128;
    const int bn = blockIdx.x * 128;
    const int tid = threadIdx.x;
    const int lane = tid & 31, wid = tid >> 5;
    const int wm = wid >> 1;
    const int wn = wid & 1;
    const int grp = lane >> 2;
    const int tig = lane & 3;

    // ldmatrix per-lane address components
    const int l15 = lane & 15;
    const int lh8 = (lane >> 4) * 8;
    const int l7  = lane & 7;
    const int l38 = ((lane >> 3) & 1) * 8;

    const int ldrow = tid >> 3;     // 0..15
    const int ldc   = tid & 7;      // 0..7 (8 halves = 16B each; 64 halves/row)

    float c[4][8][4];
    #pragma unroll
    for (int t = 0; t < 4; t++)
        #pragma unroll
        for (int u = 0; u < 8; u++)
            #pragma unroll
            for (int r = 0; r < 4; r++) c[t][u][r] = 0.f;

    // prologue: tile 0 (A and B 128x64 halves each; 8 cp16 per thread per mat)
    #pragma unroll
    for (int i = 0; i < 8; i++) {
        int row = ldrow + i * 16;
        cp16(sm + HA(0) + row * 72 + ldc * 8, X + (size_t)(bm + row) * DM + ldc * 8);
        cp16(sm + HB(0) + row * 72 + ldc * 8, W + (size_t)(bn + row) * DM + ldc * 8);
    }
    cp_commit();

    const int NT = DM / 64;   // 16
    for (int kt = 0; kt < NT; kt++) {
        cp_wait0();          // tile kt landed (only group possibly in flight)
        __syncthreads();     // all warps done reading buf[(kt+1)&1] (iter kt-1)

        if (kt + 1 < NT) {   // prefetch kt+1 into the other buffer
            int k0n = (kt + 1) * 64;
            int bufn = (kt + 1) & 1;
            #pragma unroll
            for (int i = 0; i < 8; i++) {
                int row = ldrow + i * 16;
                cp16(sm + HA(bufn) + row * 72 + ldc * 8, X + (size_t)(bm + row) * DM + k0n + ldc * 8);
                cp16(sm + HB(bufn) + row * 72 + ldc * 8, W + (size_t)(bn + row) * DM + k0n + ldc * 8);
            }
            cp_commit();
        }

        const uint32_t As_b = (uint32_t)__cvta_generic_to_shared(sm + HA(kt & 1));
        const uint32_t Bs_b = (uint32_t)__cvta_generic_to_shared(sm + HB(kt & 1));

        #pragma unroll
        for (int s = 0; s < 4; s++) {        // 4 x k16 per BK=64
            const int ck = s * 16;
            uint32_t a[4][4];
            uint32_t b[8][2];
            #pragma unroll
            for (int t = 0; t < 4; t++)
                ldsm_x4(a[t], As_b + 2u * ((wm * 64 + t * 16 + l15) * 72 + ck + lh8));
            #pragma unroll
            for (int up = 0; up < 4; up++) {
                uint32_t tmp[4];
                ldsm_x4(tmp, Bs_b + 2u * ((wn * 64 + up * 16 + lh8 + l7) * 72 + ck + l38));
                b[2*up][0] = tmp[0]; b[2*up][1] = tmp[1];
                b[2*up+1][0] = tmp[2]; b[2*up+1][1] = tmp[3];
            }
            #pragma unroll
            for (int t = 0; t < 4; t++)
                #pragma unroll
                for (int u = 0; u < 8; u++)
                    mma_f16(c[t][u], a[t], b[u]);
        }
    }

    #pragma unroll
    for (int t = 0; t < 4; t++) {
        #pragma unroll
        for (int u = 0; u < 8; u++) {
            int r0  = bm + wm * 64 + t * 16 + grp;
            int col = bn + wn * 64 + u * 8 + 2 * tig;
            float b0 = bias[col], b1 = bias[col + 1];
            #pragma unroll
            for (int half = 0; half < 2; half++) {
                int m = r0 + half * 8;
                float vx = c[t][u][half * 2 + 0] + b0;
                float vy = c[t][u][half * 2 + 1] + b1;
                int b_ = m >> 11, s_ = m & 2047;
                int h_ = col >> 6, dk = col & 63;
                if (mode == 1) {
                    __half2 hv = __floats2half2_rn(vx, vy);
                    *(__half2*)(Yh + (((size_t)b_ * NH + h_) * SS + s_) * DKK + dk) = hv;
                } else if (mode == 2) {
                    size_t base = ((size_t)b_ * NH + h_) * DKK;
                    Yh[(base + dk)     * SS + s_] = __float2half_rn(vx);
                    Yh[(base + dk + 1) * SS + s_] = __float2half_rn(vy);
                } else {
                    *(float2*)(Yf + (size_t)m * DM + col) = make_float2(vx, vy);
                }
            }
        }
    }
}

// Fused Q/K/V projection: blockIdx.z selects which projection.
struct QKVArgs {
    const __half *xq, *xk;
    const __half *w0, *w1, *w2;
    const float *b0, *b1, *b2;
    __half *y0, *y1, *y2;   // y0,y1: head-split; y2: transposed
};

__global__ __launch_bounds__(128, 2)
void gemm_qkv(QKVArgs a)
{
    extern __shared__ __half smh[];
    const int z = blockIdx.z;
    const __half* X = (z == 0) ? a.xq : a.xk;
    const __half* W = (z == 0) ? a.w0 : (z == 1) ? a.w1 : a.w2;
    const float*  B = (z == 0) ? a.b0 : (z == 1) ? a.b1 : a.b2;
    __half*       Y = (z == 0) ? a.y0 : (z == 1) ? a.y1 : a.y2;
    gemm_core_h(X, W, B, nullptr, Y, (z == 2) ? 2 : 1, smh);
}

__global__ __launch_bounds__(128, 2)
void gemm_h(const __half* __restrict__ X, const __half* __restrict__ W,
            const float* __restrict__ bias, float* __restrict__ Y)
{
    extern __shared__ __half smh[];
    gemm_core_h(X, W, bias, Y, nullptr, 0, smh);
}

// ---------------------------------------------------------------------------
// Flash attention (round-13 proven version, unchanged): fp16 mma, ldmatrix,
// additive kmask bias, diagonal-only causal, pre-scaled ex2 softmax,
// cp.async pipelined K double-buffer + V overlap. V pre-transposed.
// ---------------------------------------------------------------------------
#define FLH_K0 0
#define FLH_K1 4608
#define FLH_V  9216
#define FLH_PS 13824
#define FL_SMEM_BYTES (9600 * 4)

__global__ __launch_bounds__(128, 3)
void flash_attn_h(const int* __restrict__ q_mask, const int* __restrict__ k_mask,
                  const int* __restrict__ causal_flag, int causal_default)
{
    extern __shared__ float fsm[];
    __half* hsm = (__half*)fsm;
    __half* Vts = hsm + FLH_V;
    __half* Ps  = hsm + FLH_PS;
    float (*redm)[2] = (float(*)[2])(fsm + 9216);
    float (*reds)[2] = (float(*)[2])(fsm + 9344);
    float* kbias = fsm + 9472;   // [2][64]

    const int b  = blockIdx.z, h = blockIdx.y;
    const int q0 = ((int)gridDim.x - 1 - (int)blockIdx.x) * 64;  // longest-first
    const int tid = threadIdx.x;
    const int lane = tid & 31, wid = tid >> 5;
    const int wm = wid >> 1;
    const int wn = wid & 1;
    const int grp = lane >> 2;
    const int tig = lane & 3;
    const int causal = causal_flag ? causal_flag[0] : causal_default;

    const int l15 = lane & 15;
    const int lh8 = (lane >> 4) * 8;
    const int l7  = lane & 7;
    const int l38 = ((lane >> 3) & 1) * 8;

    const __half* Qb  = g_Qh + (((size_t)b * NH + h) * SS) * DKK;
    const __half* Kb  = g_Kh + (((size_t)b * NH + h) * SS) * DKK;
    const __half* Vtb = g_Vt + (((size_t)b * NH + h) * DKK) * SS;

    const int ldrow = tid >> 3;   // 0..15
    const int ldc   = tid & 7;    // 0..7

    // ---- prologue: cp.async K(0) + Q (one group); kbias(0) ----
    #pragma unroll
    for (int i = 0; i < 4; i++) {
        int row = ldrow + i * 16;
        cp16(hsm + FLH_K0 + row * 72 + ldc * 8, Kb + (size_t)row * DKK + ldc * 8);
        cp16(Ps + row * 72 + ldc * 8, Qb + (size_t)(q0 + row) * DKK + ldc * 8);
    }
    cp_commit();   // group: K(0)+Q
    if (tid < 64) kbias[tid] = k_mask[(size_t)b * SS + tid] ? 0.f : -INFINITY;
    cp_wait0();
    __syncthreads();

    // ---- extract Q fragments via ldmatrix ----
    const uint32_t Ps_b = (uint32_t)__cvta_generic_to_shared(Ps);
    uint32_t qf[4][2][4];
    #pragma unroll
    for (int s16 = 0; s16 < 4; s16++) {
        const int ck = s16 * 16;
        #pragma unroll
        for (int t = 0; t < 2; t++)
            ldsm_x4(qf[s16][t], Ps_b + 2u * ((wm * 32 + t * 16 + l15) * 72 + ck + lh8));
    }

    float o[2][4][4];
    #pragma unroll
    for (int t = 0; t < 2; t++)
        #pragma unroll
        for (int u = 0; u < 4; u++)
            #pragma unroll
            for (int r = 0; r < 4; r++) o[t][u][r] = 0.f;

    float m_r[2][2], l_r[2][2];
    #pragma unroll
    for (int t = 0; t < 2; t++)
        #pragma unroll
        for (int hf = 0; hf < 2; hf++) { m_r[t][hf] = -INFINITY; l_r[t][hf] = 0.f; }

    const int nkt = causal ? (q0 >> 6) + 1 : (SS / 64);
    const uint32_t Vts_b = (uint32_t)__cvta_generic_to_shared(Vts);

    for (int kt = 0; kt < nkt; kt++) {
        const int k0 = kt * 64;
        const __half* KcP = hsm + ((kt & 1) ? FLH_K1 : FLH_K0);
        __half*       Kn  = hsm + ((kt & 1) ? FLH_K0 : FLH_K1);
        const float*  kbc = kbias + (kt & 1) * 64;
        const bool diag = causal && (kt == nkt - 1);

        cp_wait0();        // K(t) landed
        __syncthreads();   // S1: K(t) visible; Ps (prev P) + Vts (prev V) free

        // ---- issue V(t) ----
        #pragma unroll
        for (int i = 0; i < 4; i++) {
            int row = ldrow + i * 16;
            cp16(Vts + row * 72 + ldc * 8, Vtb + (size_t)row * SS + k0 + ldc * 8);
        }
        cp_commit();   // group: V(t)

        // ---- S = Q K^T via fp16 mma (ldmatrix B) ----
        const uint32_t Kc_b = (uint32_t)__cvta_generic_to_shared(KcP);
        float sacc[2][4][4];
        #pragma unroll
        for (int t = 0; t < 2; t++)
            #pragma unroll
            for (int u = 0; u < 4; u++)
                #pragma unroll
                for (int r = 0; r < 4; r++) sacc[t][u][r] = 0.f;

        #pragma unroll
        for (int s16 = 0; s16 < 4; s16++) {
            const int ck = s16 * 16;
            uint32_t kb[4][2];
            #pragma unroll
            for (int up = 0; up < 2; up++) {
                uint32_t tmp[4];
                ldsm_x4(tmp, Kc_b + 2u * ((wn * 32 + up * 16 + lh8 + l7) * 72 + ck + l38));
                kb[2*up][0] = tmp[0]; kb[2*up][1] = tmp[1];
                kb[2*up+1][0] = tmp[2]; kb[2*up+1][1] = tmp[3];
            }
            #pragma unroll
            for (int t = 0; t < 2; t++)
                #pragma unroll
                for (int u = 0; u < 4; u++)
                    mma_f16(sacc[t][u], qf[s16][t], kb[u]);
        }

        // ---- scale(log2-domain) + additive kmask; causal only on diagonal ----
        #pragma unroll
        for (int t = 0; t < 2; t++) {
            int rl0 = wm * 32 + t * 16 + grp;
            #pragma unroll
            for (int u = 0; u < 4; u++) {
                int cl = wn * 32 + u * 8 + 2 * tig;
                float kb0 = kbc[cl], kb1 = kbc[cl + 1];
                float x0 = fmaf(sacc[t][u][0], SC_LOG2E, kb0);
                float x1 = fmaf(sacc[t][u][1], SC_LOG2E, kb1);
                float x2 = fmaf(sacc[t][u][2], SC_LOG2E, kb0);
                float x3 = fmaf(sacc[t][u][3], SC_LOG2E, kb1);
                if (diag) {
                    int qg0 = q0 + rl0, qg1 = qg0 + 8;
                    int kg = k0 + cl;
                    if (kg     > qg0) x0 = -INFINITY;
                    if (kg + 1 > qg0) x1 = -INFINITY;
                    if (kg     > qg1) x2 = -INFINITY;
                    if (kg + 1 > qg1) x3 = -INFINITY;
                }
                sacc[t][u][0] = x0; sacc[t][u][1] = x1;
                sacc[t][u][2] = x2; sacc[t][u][3] = x3;
            }
        }

        // ---- row max -> redm ----
        #pragma unroll
        for (int t = 0; t < 2; t++) {
            #pragma unroll
            for (int hf = 0; hf < 2; hf++) {
                float mx = -INFINITY;
                #pragma unroll
                for (int u = 0; u < 4; u++)
                    mx = fmaxf(mx, fmaxf(sacc[t][u][2*hf], sacc[t][u][2*hf + 1]));
                mx = fmaxf(mx, __shfl_xor_sync(0xffffffffu, mx, 1));
                mx = fmaxf(mx, __shfl_xor_sync(0xffffffffu, mx, 2));
                if (tig == 0) redm[wm * 32 + t * 16 + grp + 8 * hf][wn] = mx;
            }
        }

        // ---- prefetch K(t+1) + kbias(t+1) (commit always, maybe empty) ----
        if (kt + 1 < nkt) {
            int k0n = k0 + 64;
            #pragma unroll
            for (int i = 0; i < 4; i++) {
                int row = ldrow + i * 16;
                cp16(Kn + row * 72 + ldc * 8, Kb + (size_t)(k0n + row) * DKK + ldc * 8);
            }
            if (tid < 64)
                kbias[((kt + 1) & 1) * 64 + tid] = k_mask[(size_t)b * SS + k0n + tid] ? 0.f : -INFINITY;
        }
        cp_commit();   // group: K(t+1)

        __syncthreads();   // S3: redm visible

        // ---- m_new, ex2, row sums; write P (fp16) to Ps ----
        float mnew[2][2];
        #pragma unroll
        for (int t = 0; t < 2; t++) {
            #pragma unroll
            for (int hf = 0; hf < 2; hf++) {
                int rl = wm * 32 + t * 16 + grp + 8 * hf;
                float2 mm = *(float2*)&redm[rl][0];
                mnew[t][hf] = fmaxf(m_r[t][hf], fmaxf(mm.x, mm.y));
            }
        }
        float psum[2][2] = {{0.f, 0.f}, {0.f, 0.f}};
        #pragma unroll
        for (int t = 0; t < 2; t++) {
            int rl0 = wm * 32 + t * 16 + grp;
            #pragma unroll
            for (int u = 0; u < 4; u++) {
                int cl = wn * 32 + u * 8 + 2 * tig;
                float p0 = ex2f(sacc[t][u][0] - mnew[t][0]);
                float p1 = ex2f(sacc[t][u][1] - mnew[t][0]);
                float p2 = ex2f(sacc[t][u][2] - mnew[t][1]);
                float p3 = ex2f(sacc[t][u][3] - mnew[t][1]);
                psum[t][0] += p0 + p1;
                psum[t][1] += p2 + p3;
                *(__half2*)(Ps + rl0 * 72 + cl)       = __floats2half2_rn(p0, p1);
                *(__half2*)(Ps + (rl0 + 8) * 72 + cl) = __floats2half2_rn(p2, p3);
            }
        }
        #pragma unroll
        for (int t = 0; t < 2; t++) {
            #pragma unroll
            for (int hf = 0; hf < 2; hf++) {
                float s = psum[t][hf];
                s += __shfl_xor_sync(0xffffffffu, s, 1);
                s += __shfl_xor_sync(0xffffffffu, s, 2);
                if (tig == 0) reds[wm * 32 + t * 16 + grp + 8 * hf][wn] = s;
            }
        }

        cp_wait1();        // V(t) landed (K(t+1) may still be in flight)
        __syncthreads();   // S4: V, reds, Ps visible

        // ---- l/alpha update + rescale O ----
        float alpha_v[2][2];
        #pragma unroll
        for (int t = 0; t < 2; t++) {
            #pragma unroll
            for (int hf = 0; hf < 2; hf++) {
                int rl = wm * 32 + t * 16 + grp + 8 * hf;
                float2 ss = *(float2*)&reds[rl][0];
                float al = ex2f(m_r[t][hf] - mnew[t][hf]);  // NaN iff both -inf (matches ref)
                l_r[t][hf] = l_r[t][hf] * al + ss.x + ss.y;
                m_r[t][hf] = mnew[t][hf];
                alpha_v[t][hf] = al;
            }
        }
        #pragma unroll
        for (int t = 0; t < 2; t++) {
            #pragma unroll
            for (int u = 0; u < 4; u++) {
                o[t][u][0] *= alpha_v[t][0]; o[t][u][1] *= alpha_v[t][0];
                o[t][u][2] *= alpha_v[t][1]; o[t][u][3] *= alpha_v[t][1];
            }
        }

        // ---- O += P @ V via fp16 mma (ldmatrix P and V) ----
        #pragma unroll
        for (int s16 = 0; s16 < 4; s16++) {
            const int ck = s16 * 16;
            uint32_t pf[2][4];
            uint32_t vb[4][2];
            #pragma unroll
            for (int t = 0; t < 2; t++)
                ldsm_x4(pf[t], Ps_b + 2u * ((wm * 32 + t * 16 + l15) * 72 + ck + lh8));
            #pragma unroll
            for (int up = 0; up < 2; up++) {
                uint32_t tmp[4];
                ldsm_x4(tmp, Vts_b + 2u * ((wn * 32 + up * 16 + lh8 + l7) * 72 + ck + l38));
                vb[2*up][0] = tmp[0]; vb[2*up][1] = tmp[1];
                vb[2*up+1][0] = tmp[2]; vb[2*up+1][1] = tmp[3];
            }
            #pragma unroll
            for (int t = 0; t < 2; t++)
                #pragma unroll
                for (int u = 0; u < 4; u++)
                    mma_f16(o[t][u], pf[t], vb[u]);
        }
    }

    // ---- epilogue: normalize, q_mask, write fp16 to g_Ohh ----
    #pragma unroll
    for (int t = 0; t < 2; t++) {
        #pragma unroll
        for (int hf = 0; hf < 2; hf++) {
            int rl = wm * 32 + t * 16 + grp + 8 * hf;
            int s_ = q0 + rl;
            int qm = q_mask[(size_t)b * SS + s_];
            float inv_l = 1.f / l_r[t][hf];   // NaN rows propagate (matches ref)
            #pragma unroll
            for (int u = 0; u < 4; u++) {
                int dcol = wn * 32 + u * 8 + 2 * tig;
                __half2 hv;
                if (qm == 0) {
                    hv = __floats2half2_rn(0.f, 0.f);
                } else {
                    hv = __floats2half2_rn(o[t][u][hf * 2 + 0] * inv_l,
                                           o[t][u][hf * 2 + 1] * inv_l);
                }
                *(__half2*)(g_Ohh + ((size_t)b * SS + s_) * DM + h * DKK + dcol) = hv;
            }
        }
    }
}

// ---------------------------------------------------------------------------
extern "C" void kernel_launch(void* const* d_in, const int* in_sizes, int n_in,
                              void* d_out, int out_size)
{
    const float* q  = (const float*)d_in[0];
    const float* k  = (const float*)d_in[1];
    const int*   qm = (const int*)  d_in[2];
    const int*   km = (const int*)  d_in[3];
    const float* Wq = (const float*)d_in[4];
    const float* bq = (const float*)d_in[5];
    const float* Wk = (const float*)d_in[6];
    const float* bk = (const float*)d_in[7];
    const float* Wv = (const float*)d_in[8];
    const float* bv = (const float*)d_in[9];
    const float* Wo = (const float*)d_in[10];
    const float* bo = (const float*)d_in[11];
    const int* causal = (n_in >= 13) ? (const int*)d_in[12] : nullptr;

    __half *Qh, *Kh, *Vt, *Ohh, *qh, *kh, *Wh;
    cudaGetSymbolAddress((void**)&Qh,  g_Qh);
    cudaGetSymbolAddress((void**)&Kh,  g_Kh);
    cudaGetSymbolAddress((void**)&Vt,  g_Vt);
    cudaGetSymbolAddress((void**)&Ohh, g_Ohh);
    cudaGetSymbolAddress((void**)&qh,  g_qh);
    cudaGetSymbolAddress((void**)&kh,  g_kh);
    cudaGetSymbolAddress((void**)&Wh,  g_Wh);

    cudaFuncSetAttribute(gemm_qkv, cudaFuncAttributeMaxDynamicSharedMemorySize,
                         (int)GEMM_SMEM_BYTES);
    cudaFuncSetAttribute(gemm_h, cudaFuncAttributeMaxDynamicSharedMemorySize,
                         (int)GEMM_SMEM_BYTES);
    cudaFuncSetAttribute(flash_attn_h, cudaFuncAttributeMaxDynamicSharedMemorySize,
                         (int)FL_SMEM_BYTES);

    // fused pre-pass: fp32 -> fp16 for all GEMM inputs (one launch)
    cvt_all<<<(NCVT4 + 255) / 256, 256>>>(q, k, Wq, Wk, Wv, Wo, qh, kh, Wh);

    // fused Q/K/V projections: one launch, 768 blocks (V written transposed)
    QKVArgs qa;
    qa.xq = qh; qa.xk = kh;
    qa.w0 = Wh + 0 * (size_t)DM * DM; qa.w1 = Wh + 1 * (size_t)DM * DM; qa.w2 = Wh + 2 * (size_t)DM * DM;
    qa.b0 = bq;  qa.b1 = bk;  qa.b2 = bv;
    qa.y0 = Qh;  qa.y1 = Kh;  qa.y2 = Vt;
    dim3 gq(DM / 128, (BB * SS) / 128, 3);   // (8, 32, 3)
    gemm_qkv<<<gq, 128, GEMM_SMEM_BYTES>>>(qa);

    dim3 ga(SS / 64, NH, BB);                // (32, 16, 2)
    flash_attn_h<<<ga, 128, FL_SMEM_BYTES>>>(qm, km, causal, 1);

    dim3 gg(DM / 128, (BB * SS) / 128);      // (8, 32)
    gemm_h<<<gg, 128, GEMM_SMEM_BYTES>>>(Ohh, Wh + 3 * (size_t)DM * DM, bo, (float*)d_out);
}

// round 15
// speedup vs baseline: 2.3485x; 1.0313x over previous
#include <cuda_runtime.h>
#include <cuda_fp16.h>
#include <math.h>
#include <stdint.h>

#define BB  2
#define SS  2048
#define DM  1024
#define NH  16
#define DKK 64

// Scratch (allocation-free rule: __device__ globals)
__device__ __half g_Qh[BB*NH*SS*DKK];   // [b][h][s][dk] fp16
__device__ __half g_Kh[BB*NH*SS*DKK];   // [b][h][s][dk] fp16
__device__ __half g_Vt[BB*NH*DKK*SS];   // [b][h][dk][s] fp16 (TRANSPOSED)
__device__ __half g_Ohh[BB*SS*DM];      // [b][s][h*64+dk] fp16
__device__ __half g_qh[BB*SS*DM];       // pre-converted q (fp16)
__device__ __half g_kh[BB*SS*DM];       // pre-converted k (fp16)
__device__ __half g_Wh[4*DM*DM];        // pre-converted Wq,Wk,Wv,Wo (fp16)

// ---------------------------------------------------------------------------
// helpers
// ---------------------------------------------------------------------------
__device__ __forceinline__ void mma_f16(float c[4], const uint32_t a[4], const uint32_t b[2]) {
    asm volatile(
        "mma.sync.aligned.m16n8k16.row.col.f32.f16.f16.f32 "
        "{%0,%1,%2,%3}, {%4,%5,%6,%7}, {%8,%9}, {%0,%1,%2,%3};\n"
        : "+f"(c[0]), "+f"(c[1]), "+f"(c[2]), "+f"(c[3])
        : "r"(a[0]), "r"(a[1]), "r"(a[2]), "r"(a[3]), "r"(b[0]), "r"(b[1]));
}

__device__ __forceinline__ void ldsm_x4(uint32_t r[4], uint32_t saddr) {
    asm volatile("ldmatrix.sync.aligned.m8n8.x4.shared.b16 {%0,%1,%2,%3}, [%4];"
        : "=r"(r[0]), "=r"(r[1]), "=r"(r[2]), "=r"(r[3]) : "r"(saddr));
}

__device__ __forceinline__ float ex2f(float x) {
    float y;
    asm("ex2.approx.f32 %0, %1;" : "=f"(y) : "f"(x));
    return y;
}

__device__ __forceinline__ uint32_t packh2(float x, float y) {
    __half2 h = __floats2half2_rn(x, y);
    return *(uint32_t*)&h;
}

__device__ __forceinline__ void cp16(void* dst, const void* src) {
    uint32_t d = (uint32_t)__cvta_generic_to_shared(dst);
    asm volatile("cp.async.cg.shared.global [%0], [%1], 16;" :: "r"(d), "l"(src));
}
__device__ __forceinline__ void cp_commit() { asm volatile("cp.async.commit_group;"); }
__device__ __forceinline__ void cp_wait0()  { asm volatile("cp.async.wait_group 0;"); }
__device__ __forceinline__ void cp_wait1()  { asm volatile("cp.async.wait_group 1;"); }

// 0.125 * log2(e)
#define SC_LOG2E 0.18033688f

// ---------------------------------------------------------------------------
// Fused fp32 -> fp16 (RN) pre-pass over q, k, Wq, Wk, Wv, Wo.
// ---------------------------------------------------------------------------
#define NQ4 (BB*SS*DM/4)   // 1048576 float4
#define NW4 (DM*DM/4)      // 262144 float4
#define NCVT4 (2*NQ4 + 4*NW4)

__global__ void cvt_all(const float* __restrict__ q, const float* __restrict__ k,
                        const float* __restrict__ Wq, const float* __restrict__ Wk,
                        const float* __restrict__ Wv, const float* __restrict__ Wo,
                        __half* __restrict__ qh, __half* __restrict__ kh,
                        __half* __restrict__ Wh)
{
    int i = blockIdx.x * blockDim.x + threadIdx.x;
    if (i >= NCVT4) return;
    const float4* src; __half* dsth; int off;
    if (i < NQ4)            { src = (const float4*)q;  dsth = qh; off = i; }
    else if (i < 2 * NQ4)   { src = (const float4*)k;  dsth = kh; off = i - NQ4; }
    else {
        int j = i - 2 * NQ4;
        int w = j / NW4; off = j - w * NW4;
        src = (const float4*)(w == 0 ? Wq : w == 1 ? Wk : w == 2 ? Wv : Wo);
        dsth = Wh + (size_t)w * DM * DM;
    }
    float4 d = src[off];
    __half2 h0 = __floats2half2_rn(d.x, d.y);
    __half2 h1 = __floats2half2_rn(d.z, d.w);
    uint2 e;
    e.x = *(uint32_t*)&h0;
    e.y = *(uint32_t*)&h1;
    ((uint2*)dsth)[off] = e;
}

// ---------------------------------------------------------------------------
// fp16 GEMM core (round-14 proven): m16n8k16 mma, cp.async double-buffered,
// BK=64, single sync per k-tile, ldmatrix fragments, stride 72.
// mode 0: fp32 row-major; mode 1: fp16 head-split; mode 2: fp16 transposed.
// ---------------------------------------------------------------------------
#define HA(buf) ((buf) * 9216)              // halves: 128*72 per tile
#define HB(buf) (18432 + (buf) * 9216)
#define GEMM_SMEM_BYTES (36864 * 2)         // 73728

__device__ __forceinline__ void gemm_core_h(
    const __half* __restrict__ X, const __half* __restrict__ W,
    const float* __restrict__ bias, float* __restrict__ Yf,
    __half* __restrict__ Yh, int mode, __half* sm)
{
    const int bm = blockIdx.y * 128;
    const int bn = blockIdx.x * 128;
    const int tid = threadIdx.x;
    const int lane = tid & 31, wid = tid >> 5;
    const int wm = wid >> 1;
    const int wn = wid & 1;
    const int grp = lane >> 2;
    const int tig = lane & 3;

    const int l15 = lane & 15;
    const int lh8 = (lane >> 4) * 8;
    const int l7  = lane & 7;
    const int l38 = ((lane >> 3) & 1) * 8;

    const int ldrow = tid >> 3;     // 0..15
    const int ldc   = tid & 7;      // 0..7

    float c[4][8][4];
    #pragma unroll
    for (int t = 0; t < 4; t++)
        #pragma unroll
        for (int u = 0; u < 8; u++)
            #pragma unroll
            for (int r = 0; r < 4; r++) c[t][u][r] = 0.f;

    #pragma unroll
    for (int i = 0; i < 8; i++) {
        int row = ldrow + i * 16;
        cp16(sm + HA(0) + row * 72 + ldc * 8, X + (size_t)(bm + row) * DM + ldc * 8);
        cp16(sm + HB(0) + row * 72 + ldc * 8, W + (size_t)(bn + row) * DM + ldc * 8);
    }
    cp_commit();

    const int NT = DM / 64;   // 16
    for (int kt = 0; kt < NT; kt++) {
        cp_wait0();
        __syncthreads();

        if (kt + 1 < NT) {
            int k0n = (kt + 1) * 64;
            int bufn = (kt + 1) & 1;
            #pragma unroll
            for (int i = 0; i < 8; i++) {
                int row = ldrow + i * 16;
                cp16(sm + HA(bufn) + row * 72 + ldc * 8, X + (size_t)(bm + row) * DM + k0n + ldc * 8);
                cp16(sm + HB(bufn) + row * 72 + ldc * 8, W + (size_t)(bn + row) * DM + k0n + ldc * 8);
            }
            cp_commit();
        }

        const uint32_t As_b = (uint32_t)__cvta_generic_to_shared(sm + HA(kt & 1));
        const uint32_t Bs_b = (uint32_t)__cvta_generic_to_shared(sm + HB(kt & 1));

        #pragma unroll
        for (int s = 0; s < 4; s++) {
            const int ck = s * 16;
            uint32_t a[4][4];
            uint32_t b[8][2];
            #pragma unroll
            for (int t = 0; t < 4; t++)
                ldsm_x4(a[t], As_b + 2u * ((wm * 64 + t * 16 + l15) * 72 + ck + lh8));
            #pragma unroll
            for (int up = 0; up < 4; up++) {
                uint32_t tmp[4];
                ldsm_x4(tmp, Bs_b + 2u * ((wn * 64 + up * 16 + lh8 + l7) * 72 + ck + l38));
                b[2*up][0] = tmp[0]; b[2*up][1] = tmp[1];
                b[2*up+1][0] = tmp[2]; b[2*up+1][1] = tmp[3];
            }
            #pragma unroll
            for (int t = 0; t < 4; t++)
                #pragma unroll
                for (int u = 0; u < 8; u++)
                    mma_f16(c[t][u], a[t], b[u]);
        }
    }

    #pragma unroll
    for (int t = 0; t < 4; t++) {
        #pragma unroll
        for (int u = 0; u < 8; u++) {
            int r0  = bm + wm * 64 + t * 16 + grp;
            int col = bn + wn * 64 + u * 8 + 2 * tig;
            float b0 = bias[col], b1 = bias[col + 1];
            #pragma unroll
            for (int half = 0; half < 2; half++) {
                int m = r0 + half * 8;
                float vx = c[t][u][half * 2 + 0] + b0;
                float vy = c[t][u][half * 2 + 1] + b1;
                int b_ = m >> 11, s_ = m & 2047;
                int h_ = col >> 6, dk = col & 63;
                if (mode == 1) {
                    __half2 hv = __floats2half2_rn(vx, vy);
                    *(__half2*)(Yh + (((size_t)b_ * NH + h_) * SS + s_) * DKK + dk) = hv;
                } else if (mode == 2) {
                    size_t base = ((size_t)b_ * NH + h_) * DKK;
                    Yh[(base + dk)     * SS + s_] = __float2half_rn(vx);
                    Yh[(base + dk + 1) * SS + s_] = __float2half_rn(vy);
                } else {
                    *(float2*)(Yf + (size_t)m * DM + col) = make_float2(vx, vy);
                }
            }
        }
    }
}

// Fused Q/K/V projection: blockIdx.z selects which projection.
struct QKVArgs {
    const __half *xq, *xk;
    const __half *w0, *w1, *w2;
    const float *b0, *b1, *b2;
    __half *y0, *y1, *y2;   // y0,y1: head-split; y2: transposed
};

__global__ __launch_bounds__(128, 2)
void gemm_qkv(QKVArgs a)
{
    extern __shared__ __half smh[];
    const int z = blockIdx.z;
    const __half* X = (z == 0) ? a.xq : a.xk;
    const __half* W = (z == 0) ? a.w0 : (z == 1) ? a.w1 : a.w2;
    const float*  B = (z == 0) ? a.b0 : (z == 1) ? a.b1 : a.b2;
    __half*       Y = (z == 0) ? a.y0 : (z == 1) ? a.y1 : a.y2;
    gemm_core_h(X, W, B, nullptr, Y, (z == 2) ? 2 : 1, smh);
}

__global__ __launch_bounds__(128, 2)
void gemm_h(const __half* __restrict__ X, const __half* __restrict__ W,
            const float* __restrict__ bias, float* __restrict__ Y)
{
    extern __shared__ __half smh[];
    gemm_core_h(X, W, bias, Y, nullptr, 0, smh);
}

// ---------------------------------------------------------------------------
// Flash attention, WARP-ROW tiling: 4 warps x (16 rows x 64 keys).
// P stays in registers (C-layout == A-operand layout); softmax reductions are
// pure quad shuffles; 2 block syncs per tile. fp16 mma, ldmatrix K/V,
// additive kmask bias, diag-only causal, ex2 softmax, cp.async pipeline
// (K double-buffered, V overlapped; Q staged through the V buffer).
// smem halves (stride 72): K0@0, K1@4608, V@9216; kbias floats @6912f.
// ---------------------------------------------------------------------------
#define FLH_K0 0
#define FLH_K1 4608
#define FLH_V  9216
#define FL_SMEM_BYTES (13824 * 2 + 512 + 128)   // 28288

__global__ __launch_bounds__(128, 3)
void flash_attn_h(const int* __restrict__ q_mask, const int* __restrict__ k_mask,
                  const int* __restrict__ causal_flag, int causal_default)
{
    extern __shared__ float fsm[];
    __half* hsm = (__half*)fsm;
    __half* Vts = hsm + FLH_V;
    float* kbias = fsm + 6912;   // [2][64]

    const int b  = blockIdx.z, h = blockIdx.y;
    const int q0 = ((int)gridDim.x - 1 - (int)blockIdx.x) * 64;  // longest-first
    const int tid = threadIdx.x;
    const int lane = tid & 31, wid = tid >> 5;
    const int grp = lane >> 2;
    const int tig = lane & 3;
    const int causal = causal_flag ? causal_flag[0] : causal_default;

    const int l15 = lane & 15;
    const int lh8 = (lane >> 4) * 8;
    const int l7  = lane & 7;
    const int l38 = ((lane >> 3) & 1) * 8;

    const __half* Qb  = g_Qh + (((size_t)b * NH + h) * SS) * DKK;
    const __half* Kb  = g_Kh + (((size_t)b * NH + h) * SS) * DKK;
    const __half* Vtb = g_Vt + (((size_t)b * NH + h) * DKK) * SS;

    const int ldrow = tid >> 3;   // 0..15
    const int ldc   = tid & 7;    // 0..7

    // ---- prologue: cp.async K(0) -> K0, Q -> V buffer (one group); kbias(0) ----
    #pragma unroll
    for (int i = 0; i < 4; i++) {
        int row = ldrow + i * 16;
        cp16(hsm + FLH_K0 + row * 72 + ldc * 8, Kb + (size_t)row * DKK + ldc * 8);
        cp16(Vts + row * 72 + ldc * 8, Qb + (size_t)(q0 + row) * DKK + ldc * 8);
    }
    cp_commit();
    if (tid < 64) kbias[tid] = k_mask[(size_t)b * SS + tid] ? 0.f : -INFINITY;
    cp_wait0();
    __syncthreads();

    // ---- extract Q fragments (rows wid*16..+15) from V buffer ----
    const uint32_t Vts_b = (uint32_t)__cvta_generic_to_shared(Vts);
    uint32_t qf[4][4];
    #pragma unroll
    for (int s16 = 0; s16 < 4; s16++)
        ldsm_x4(qf[s16], Vts_b + 2u * ((wid * 16 + l15) * 72 + s16 * 16 + lh8));

    float o[8][4];
    #pragma unroll
    for (int u = 0; u < 8; u++)
        #pragma unroll
        for (int r = 0; r < 4; r++) o[u][r] = 0.f;

    float m_r[2] = {-INFINITY, -INFINITY};
    float l_r[2] = {0.f, 0.f};

    const int nkt = causal ? (q0 >> 6) + 1 : (SS / 64);

    for (int kt = 0; kt < nkt; kt++) {
        const int k0 = kt * 64;
        const uint32_t Kc_b = (uint32_t)__cvta_generic_to_shared(
            hsm + ((kt & 1) ? FLH_K1 : FLH_K0));
        __half* Kn = hsm + ((kt & 1) ? FLH_K0 : FLH_K1);
        const float* kbc = kbias + (kt & 1) * 64;
        const bool diag = causal && (kt == nkt - 1);

        cp_wait0();        // K(t) landed (V(t-1)/Q already consumed)
        __syncthreads();   // S1: K(t) visible; V buffer free (PV/qf done)

        // ---- issue V(t) ----
        #pragma unroll
        for (int i = 0; i < 4; i++) {
            int row = ldrow + i * 16;
            cp16(Vts + row * 72 + ldc * 8, Vtb + (size_t)row * SS + k0 + ldc * 8);
        }
        cp_commit();   // group: V(t)

        // ---- S = Q K^T (warp covers all 64 keys) ----
        float sacc[8][4];
        #pragma unroll
        for (int u = 0; u < 8; u++)
            #pragma unroll
            for (int r = 0; r < 4; r++) sacc[u][r] = 0.f;

        #pragma unroll
        for (int s16 = 0; s16 < 4; s16++) {
            const int ck = s16 * 16;
            uint32_t kb2[8][2];
            #pragma unroll
            for (int up = 0; up < 4; up++) {
                uint32_t tmp[4];
                ldsm_x4(tmp, Kc_b + 2u * ((up * 16 + lh8 + l7) * 72 + ck + l38));
                kb2[2*up][0] = tmp[0]; kb2[2*up][1] = tmp[1];
                kb2[2*up+1][0] = tmp[2]; kb2[2*up+1][1] = tmp[3];
            }
            #pragma unroll
            for (int u = 0; u < 8; u++)
                mma_f16(sacc[u], qf[s16], kb2[u]);
        }

        // ---- scale(log2) + kmask bias; causal only on diagonal tile ----
        const int r0 = q0 + wid * 16 + grp;
        const int r1 = r0 + 8;
        #pragma unroll
        for (int u = 0; u < 8; u++) {
            int cl = u * 8 + 2 * tig;
            float kb0 = kbc[cl], kb1 = kbc[cl + 1];
            float x0 = fmaf(sacc[u][0], SC_LOG2E, kb0);
            float x1 = fmaf(sacc[u][1], SC_LOG2E, kb1);
            float x2 = fmaf(sacc[u][2], SC_LOG2E, kb0);
            float x3 = fmaf(sacc[u][3], SC_LOG2E, kb1);
            if (diag) {
                int kg = k0 + cl;
                if (kg     > r0) x0 = -INFINITY;
                if (kg + 1 > r0) x1 = -INFINITY;
                if (kg     > r1) x2 = -INFINITY;
                if (kg + 1 > r1) x3 = -INFINITY;
            }
            sacc[u][0] = x0; sacc[u][1] = x1;
            sacc[u][2] = x2; sacc[u][3] = x3;
        }

        // ---- row max: pure quad shuffles (rows never cross warps) ----
        float mx0 = -INFINITY, mx1 = -INFINITY;
        #pragma unroll
        for (int u = 0; u < 8; u++) {
            mx0 = fmaxf(mx0, fmaxf(sacc[u][0], sacc[u][1]));
            mx1 = fmaxf(mx1, fmaxf(sacc[u][2], sacc[u][3]));
        }
        mx0 = fmaxf(mx0, __shfl_xor_sync(0xffffffffu, mx0, 1));
        mx0 = fmaxf(mx0, __shfl_xor_sync(0xffffffffu, mx0, 2));
        mx1 = fmaxf(mx1, __shfl_xor_sync(0xffffffffu, mx1, 1));
        mx1 = fmaxf(mx1, __shfl_xor_sync(0xffffffffu, mx1, 2));
        const float mnew0 = fmaxf(m_r[0], mx0);
        const float mnew1 = fmaxf(m_r[1], mx1);

        // ---- prefetch K(t+1) + kbias(t+1) (commit always, maybe empty) ----
        if (kt + 1 < nkt) {
            int k0n = k0 + 64;
            #pragma unroll
            for (int i = 0; i < 4; i++) {
                int row = ldrow + i * 16;
                cp16(Kn + row * 72 + ldc * 8, Kb + (size_t)(k0n + row) * DKK + ldc * 8);
            }
            if (tid < 64)
                kbias[((kt + 1) & 1) * 64 + tid] = k_mask[(size_t)b * SS + k0n + tid] ? 0.f : -INFINITY;
        }
        cp_commit();   // group: K(t+1)

        // ---- ex2, row sums, P packed directly into A-operand registers ----
        float ps0 = 0.f, ps1 = 0.f;
        uint32_t pf[4][4];
        #pragma unroll
        for (int u = 0; u < 8; u++) {
            float p0 = ex2f(sacc[u][0] - mnew0);
            float p1 = ex2f(sacc[u][1] - mnew0);
            float p2 = ex2f(sacc[u][2] - mnew1);
            float p3 = ex2f(sacc[u][3] - mnew1);
            ps0 += p0 + p1;
            ps1 += p2 + p3;
            const int s = u >> 1;
            if ((u & 1) == 0) { pf[s][0] = packh2(p0, p1); pf[s][1] = packh2(p2, p3); }
            else              { pf[s][2] = packh2(p0, p1); pf[s][3] = packh2(p2, p3); }
        }
        ps0 += __shfl_xor_sync(0xffffffffu, ps0, 1);
        ps0 += __shfl_xor_sync(0xffffffffu, ps0, 2);
        ps1 += __shfl_xor_sync(0xffffffffu, ps1, 1);
        ps1 += __shfl_xor_sync(0xffffffffu, ps1, 2);

        // ---- l/alpha update + rescale O ----
        const float al0 = ex2f(m_r[0] - mnew0);   // NaN iff both -inf (matches ref)
        const float al1 = ex2f(m_r[1] - mnew1);
        l_r[0] = l_r[0] * al0 + ps0; m_r[0] = mnew0;
        l_r[1] = l_r[1] * al1 + ps1; m_r[1] = mnew1;
        #pragma unroll
        for (int u = 0; u < 8; u++) {
            o[u][0] *= al0; o[u][1] *= al0;
            o[u][2] *= al1; o[u][3] *= al1;
        }

        cp_wait1();        // V(t) landed (K(t+1) may still be in flight)
        __syncthreads();   // S4: V visible to all warps

        // ---- O += P @ V (P from registers, V via ldmatrix) ----
        #pragma unroll
        for (int s16 = 0; s16 < 4; s16++) {
            const int ck = s16 * 16;
            uint32_t vb2[8][2];
            #pragma unroll
            for (int up = 0; up < 4; up++) {
                uint32_t tmp[4];
                ldsm_x4(tmp, Vts_b + 2u * ((up * 16 + lh8 + l7) * 72 + ck + l38));
                vb2[2*up][0] = tmp[0]; vb2[2*up][1] = tmp[1];
                vb2[2*up+1][0] = tmp[2]; vb2[2*up+1][1] = tmp[3];
            }
            #pragma unroll
            for (int u = 0; u < 8; u++)
                mma_f16(o[u], pf[s16], vb2[u]);
        }
    }

    // ---- epilogue: normalize, q_mask, write fp16 to g_Ohh ----
    #pragma unroll
    for (int hf = 0; hf < 2; hf++) {
        int row = wid * 16 + grp + 8 * hf;
        int s_ = q0 + row;
        int qm = q_mask[(size_t)b * SS + s_];
        float inv_l = 1.f / l_r[hf];   // NaN rows propagate (matches ref)
        #pragma unroll
        for (int u = 0; u < 8; u++) {
            int dcol = u * 8 + 2 * tig;
            __half2 hv;
            if (qm == 0) {
                hv = __floats2half2_rn(0.f, 0.f);
            } else {
                hv = __floats2half2_rn(o[u][2*hf + 0] * inv_l,
                                       o[u][2*hf + 1] * inv_l);
            }
            *(__half2*)(g_Ohh + ((size_t)b * SS + s_) * DM + h * DKK + dcol) = hv;
        }
    }
}

// ---------------------------------------------------------------------------
extern "C" void kernel_launch(void* const* d_in, const int* in_sizes, int n_in,
                              void* d_out, int out_size)
{
    const float* q  = (const float*)d_in[0];
    const float* k  = (const float*)d_in[1];
    const int*   qm = (const int*)  d_in[2];
    const int*   km = (const int*)  d_in[3];
    const float* Wq = (const float*)d_in[4];
    const float* bq = (const float*)d_in[5];
    const float* Wk = (const float*)d_in[6];
    const float* bk = (const float*)d_in[7];
    const float* Wv = (const float*)d_in[8];
    const float* bv = (const float*)d_in[9];
    const float* Wo = (const float*)d_in[10];
    const float* bo = (const float*)d_in[11];
    const int* causal = (n_in >= 13) ? (const int*)d_in[12] : nullptr;

    __half *Qh, *Kh, *Vt, *Ohh, *qh, *kh, *Wh;
    cudaGetSymbolAddress((void**)&Qh,  g_Qh);
    cudaGetSymbolAddress((void**)&Kh,  g_Kh);
    cudaGetSymbolAddress((void**)&Vt,  g_Vt);
    cudaGetSymbolAddress((void**)&Ohh, g_Ohh);
    cudaGetSymbolAddress((void**)&qh,  g_qh);
    cudaGetSymbolAddress((void**)&kh,  g_kh);
    cudaGetSymbolAddress((void**)&Wh,  g_Wh);

    cudaFuncSetAttribute(gemm_qkv, cudaFuncAttributeMaxDynamicSharedMemorySize,
                         (int)GEMM_SMEM_BYTES);
    cudaFuncSetAttribute(gemm_h, cudaFuncAttributeMaxDynamicSharedMemorySize,
                         (int)GEMM_SMEM_BYTES);
    cudaFuncSetAttribute(flash_attn_h, cudaFuncAttributeMaxDynamicSharedMemorySize,
                         (int)FL_SMEM_BYTES);

    // fused pre-pass: fp32 -> fp16 for all GEMM inputs (one launch)
    cvt_all<<<(NCVT4 + 255) / 256, 256>>>(q, k, Wq, Wk, Wv, Wo, qh, kh, Wh);

    // fused Q/K/V projections: one launch, 768 blocks (V written transposed)
    QKVArgs qa;
    qa.xq = qh; qa.xk = kh;
    qa.w0 = Wh + 0 * (size_t)DM * DM; qa.w1 = Wh + 1 * (size_t)DM * DM; qa.w2 = Wh + 2 * (size_t)DM * DM;
    qa.b0 = bq;  qa.b1 = bk;  qa.b2 = bv;
    qa.y0 = Qh;  qa.y1 = Kh;  qa.y2 = Vt;
    dim3 gq(DM / 128, (BB * SS) / 128, 3);   // (8, 32, 3)
    gemm_qkv<<<gq, 128, GEMM_SMEM_BYTES>>>(qa);

    dim3 ga(SS / 64, NH, BB);                // (32, 16, 2)
    flash_attn_h<<<ga, 128, FL_SMEM_BYTES>>>(qm, km, causal, 1);

    dim3 gg(DM / 128, (BB * SS) / 128);      // (8, 32)
    gemm_h<<<gg, 128, GEMM_SMEM_BYTES>>>(Ohh, Wh + 3 * (size_t)DM * DM, bo, (float*)d_out);
}